// round 1
// baseline (speedup 1.0000x reference)
#include <cuda_runtime.h>
#include <math.h>

// Problem constants
#define TT 1024
#define DD 192
#define NHH 4
#define NN 3072
#define VV 256
#define NLAYER 4
#define KSPLIT 16
#define KCH ((NHH*NN)/KSPLIT)   // 768

// Scratch (static device globals -- no allocation allowed)
__device__ float g_x[TT*DD];
__device__ float g_xs[NHH*TT*NN];
__device__ float g_qr[NHH*TT*NN];     // qr, reused as xy
__device__ float g_sc[NHH*TT*TT];
__device__ float g_ykv[NHH*TT*DD];
__device__ float g_part[KSPLIT*TT*DD];
__device__ float g_cos[TT*NN];
__device__ float g_sin[TT*NN];

// ---------------------------------------------------------------------------
// Generic tiled SGEMM: C[M,N] = op(A[M,K] @ B)   (row-major)
// EPI: 0 plain, 1 relu, 2 relu*E, 3 strict-lower-tri mask (c<r)
// AHS: A is xy laid out [h][t][n]; k = h*NN+n; blockIdx.z selects k-chunk (split-K)
// BT : B is [N,K] row-major (i.e. compute A @ B^T)
// ---------------------------------------------------------------------------
#define BM 128
#define BN 128
#define BK 16
#define TM 8
#define TN 8

template<int EPI, bool AHS, bool BT>
__global__ __launch_bounds__(256)
void gemm_k(const float* __restrict__ A, const float* __restrict__ B,
            float* __restrict__ C, const float* __restrict__ E,
            int M, int N, int K, int sA, int sB, int sC, int sE)
{
    __shared__ float As[BK][BM];
    __shared__ float Bs[BK][BN];

    const int bx = blockIdx.x, by = blockIdx.y, bz = blockIdx.z;
    int koff = 0;
    if (AHS) koff = bz * sA;               // sA = k-chunk size per z
    else     A += (size_t)bz * sA;
    B += (size_t)bz * sB;
    C += (size_t)bz * sC;
    if (EPI == 2) E += (size_t)bz * sE;

    const int row0 = by * BM, col0 = bx * BN;
    const int tid = threadIdx.x;
    const int tx = tid & 15, ty = tid >> 4;

    float acc[TM][TN];
    #pragma unroll
    for (int i = 0; i < TM; i++)
        #pragma unroll
        for (int j = 0; j < TN; j++) acc[i][j] = 0.f;

    const bool skip = (EPI == 3) && (bx > by);   // tile entirely above diagonal
    if (!skip) {
        for (int k0 = 0; k0 < K; k0 += BK) {
            // ---- load A tile (transposed into smem) ----
            #pragma unroll
            for (int it = 0; it < 2; ++it) {
                int idx4 = tid + it * 256;       // 0..511 float4 slots
                int r  = idx4 >> 2;              // 0..127
                int kc = (idx4 & 3) << 2;        // 0,4,8,12
                float4 v;
                if (AHS) {
                    int gk = koff + k0 + kc;     // stays within one head per float4
                    int hh = gk / NN;
                    int nn = gk - hh * NN;
                    v = *(const float4*)(A + (size_t)hh * TT * NN
                                           + (size_t)(row0 + r) * NN + nn);
                } else {
                    v = *(const float4*)(A + (size_t)(row0 + r) * K + k0 + kc);
                }
                As[kc + 0][r] = v.x; As[kc + 1][r] = v.y;
                As[kc + 2][r] = v.z; As[kc + 3][r] = v.w;
            }
            // ---- load B tile ----
            #pragma unroll
            for (int it = 0; it < 2; ++it) {
                int idx4 = tid + it * 256;
                if (BT) {
                    int nr = idx4 >> 2;
                    int kc = (idx4 & 3) << 2;
                    float4 v = *(const float4*)(B + (size_t)(col0 + nr) * K + k0 + kc);
                    Bs[kc + 0][nr] = v.x; Bs[kc + 1][nr] = v.y;
                    Bs[kc + 2][nr] = v.z; Bs[kc + 3][nr] = v.w;
                } else {
                    int kr = idx4 >> 5;            // 0..15
                    int nc = (idx4 & 31) << 2;     // 0..124
                    int gn = col0 + nc;
                    float4 v = make_float4(0.f, 0.f, 0.f, 0.f);
                    if (gn < N)
                        v = *(const float4*)(B + (size_t)(k0 + kr) * N + gn);
                    *(float4*)(&Bs[kr][nc]) = v;
                }
            }
            __syncthreads();
            // ---- compute ----
            #pragma unroll
            for (int kk = 0; kk < BK; ++kk) {
                float ra[TM], rb[TN];
                #pragma unroll
                for (int i = 0; i < TM; i++) ra[i] = As[kk][ty * TM + i];
                #pragma unroll
                for (int j = 0; j < TN; j++) rb[j] = Bs[kk][tx * TN + j];
                #pragma unroll
                for (int i = 0; i < TM; i++)
                    #pragma unroll
                    for (int j = 0; j < TN; j++)
                        acc[i][j] = fmaf(ra[i], rb[j], acc[i][j]);
            }
            __syncthreads();
        }
    }
    // ---- epilogue ----
    #pragma unroll
    for (int i = 0; i < TM; i++) {
        int r = row0 + ty * TM + i;
        #pragma unroll
        for (int j = 0; j < TN; j++) {
            int c = col0 + tx * TN + j;
            if (c < N) {
                float v = acc[i][j];
                if (EPI == 1)      v = fmaxf(v, 0.f);
                else if (EPI == 2) v = fmaxf(v, 0.f) * E[(size_t)r * N + c];
                else if (EPI == 3) v = (c < r) ? v : 0.f;
                C[(size_t)r * N + c] = v;
            }
        }
    }
}

// ---------------------------------------------------------------------------
// LayerNorm helper: mean/var over 192-thread row (6 warps)
// ---------------------------------------------------------------------------
__device__ __forceinline__ float2 meanvar192(float v, float* s1, float* s2)
{
    __syncthreads();   // safe reuse of s1/s2 across calls
    float a = v, b = v * v;
    #pragma unroll
    for (int o = 16; o > 0; o >>= 1) {
        a += __shfl_down_sync(0xffffffffu, a, o);
        b += __shfl_down_sync(0xffffffffu, b, o);
    }
    int lane = threadIdx.x & 31, w = threadIdx.x >> 5;
    if (lane == 0) { s1[w] = a; s2[w] = b; }
    __syncthreads();
    if (threadIdx.x == 0) {
        float sa = 0.f, sb = 0.f;
        #pragma unroll
        for (int i = 0; i < 6; i++) { sa += s1[i]; sb += s2[i]; }
        s1[0] = sa; s2[0] = sb;
    }
    __syncthreads();
    float m   = s1[0] * (1.0f / 192.0f);
    float var = s2[0] * (1.0f / 192.0f) - m * m;
    return make_float2(m, fmaxf(var, 0.f));
}

// x = ln(embed[idx] + pos_emb)
__global__ void embed_ln_k(const int* __restrict__ idx,
                           const float* __restrict__ emb,
                           const float* __restrict__ pos)
{
    int t = blockIdx.x, d = threadIdx.x;
    __shared__ float s1[8], s2[8];
    float v = emb[(size_t)idx[t] * DD + d] + pos[(size_t)t * DD + d];
    float2 mv = meanvar192(v, s1, s2);
    g_x[(size_t)t * DD + d] = (v - mv.x) * rsqrtf(mv.y + 1e-5f);
}

// rope cos/sin table (matches numpy get_freqs + phase computation in fp32)
__global__ void sincos_k()
{
    int i = blockIdx.x * blockDim.x + threadIdx.x;
    if (i >= TT * NN) return;
    int t = i / NN;
    int n = i - t * NN;
    float q = (float)(n & ~1);
    float e = q / 3072.0f;
    float f = exp2f(-16.0f * e) * 0.15915494309189535f;  // /(2*pi)
    float ph = fmodf((float)t * f, 1.0f) * 6.283185307179586f;
    float s, c;
    sincosf(ph, &s, &c);
    g_cos[i] = c;
    g_sin[i] = s;
}

// qr = rope(x_sparse)
__global__ void rope_k()
{
    int i = blockIdx.x * blockDim.x + threadIdx.x;   // pair index
    if (i >= NHH * TT * (NN / 2)) return;
    int p  = i % (NN / 2);
    int ht = i / (NN / 2);
    int t  = ht & (TT - 1);
    size_t off = (size_t)ht * NN + 2 * p;
    float2 xv = *(const float2*)(g_xs + off);
    float c = g_cos[(size_t)t * NN + 2 * p];
    float s = g_sin[(size_t)t * NN + 2 * p];
    float2 o;
    o.x = xv.x * c - xv.y * s;
    o.y = xv.y * c + xv.x * s;
    *(float2*)(g_qr + off) = o;
}

// ykv = ln(ykv) row-wise over D
__global__ void ln_ykv_k()
{
    int r = blockIdx.x, d = threadIdx.x;
    __shared__ float s1[8], s2[8];
    float v = g_ykv[(size_t)r * DD + d];
    float2 mv = meanvar192(v, s1, s2);
    g_ykv[(size_t)r * DD + d] = (v - mv.x) * rsqrtf(mv.y + 1e-5f);
}

// ymlp = sum(partials); x = ln(x + ln(ymlp))
__global__ void finalize_k()
{
    int t = blockIdx.x, d = threadIdx.x;
    __shared__ float s1[8], s2[8];
    float ym = 0.f;
    #pragma unroll
    for (int c = 0; c < KSPLIT; c++)
        ym += g_part[(size_t)c * TT * DD + (size_t)t * DD + d];
    float2 mv = meanvar192(ym, s1, s2);
    float l1 = (ym - mv.x) * rsqrtf(mv.y + 1e-5f);
    float xv = g_x[(size_t)t * DD + d] + l1;
    float2 mv2 = meanvar192(xv, s1, s2);
    g_x[(size_t)t * DD + d] = (xv - mv2.x) * rsqrtf(mv2.y + 1e-5f);
}

// ---------------------------------------------------------------------------
extern "C" void kernel_launch(void* const* d_in, const int* in_sizes, int n_in,
                              void* d_out, int out_size)
{
    const int*   idx  = (const int*)  d_in[0];
    const float* decx = (const float*)d_in[1];   // (NH, D, N)
    const float* decy = (const float*)d_in[2];   // (NH, D, N)
    const float* enc  = (const float*)d_in[3];   // (NH*N, D)
    const float* emb  = (const float*)d_in[4];   // (VOCAB, D)
    const float* pos  = (const float*)d_in[5];   // (BLOCK, D)
    const float* lmh  = (const float*)d_in[6];   // (D, VOCAB)
    float* out = (float*)d_out;

    float *px, *pxs, *pqr, *psc, *pykv, *ppart;
    cudaGetSymbolAddress((void**)&px,    g_x);
    cudaGetSymbolAddress((void**)&pxs,   g_xs);
    cudaGetSymbolAddress((void**)&pqr,   g_qr);
    cudaGetSymbolAddress((void**)&psc,   g_sc);
    cudaGetSymbolAddress((void**)&pykv,  g_ykv);
    cudaGetSymbolAddress((void**)&ppart, g_part);

    sincos_k<<<(TT * NN + 255) / 256, 256>>>();
    embed_ln_k<<<TT, 192>>>(idx, emb, pos);

    for (int l = 0; l < NLAYER; l++) {
        // x_sparse = relu(x @ decoder_x[h])     [1024,192]x[192,3072] per head
        gemm_k<1, false, false><<<dim3(NN / BN, TT / BM, NHH), 256>>>(
            px, decx, pxs, nullptr, TT, NN, DD, 0, DD * NN, TT * NN, 0);

        // qr = rope(x_sparse)
        rope_k<<<(NHH * TT * (NN / 2) + 255) / 256, 256>>>();

        // scores = (qr @ qr^T) * tril(-1)       [1024,3072]x[3072,1024] per head
        gemm_k<3, false, true><<<dim3(TT / BN, TT / BM, NHH), 256>>>(
            pqr, pqr, psc, nullptr, TT, TT, NN, TT * NN, TT * NN, TT * TT, 0);

        // ykv_raw = scores @ x                  [1024,1024]x[1024,192] per head
        gemm_k<0, false, false><<<dim3((DD + BN - 1) / BN, TT / BM, NHH), 256>>>(
            psc, px, pykv, nullptr, TT, DD, TT, TT * TT, 0, TT * DD, 0);

        // ykv = ln(ykv_raw)
        ln_ykv_k<<<NHH * TT, 192>>>();

        // xy = relu(ykv @ decoder_y[h]) * x_sparse   -> g_qr (reuse)
        gemm_k<2, false, false><<<dim3(NN / BN, TT / BM, NHH), 256>>>(
            pykv, decy, pqr, pxs, TT, NN, DD, TT * DD, DD * NN, TT * NN, TT * NN);

        // ymlp partials: xy[1024,12288] @ enc[12288,192], split-K into 16 chunks
        gemm_k<0, true, false><<<dim3((DD + BN - 1) / BN, TT / BM, KSPLIT), 256>>>(
            pqr, enc, ppart, nullptr, TT, DD, KCH, KCH, KCH * DD, TT * DD, 0);

        // x = ln(x + ln(sum partials))
        finalize_k<<<TT, 192>>>();
    }

    // logits = x @ lm_head                      [1024,192]x[192,256]
    gemm_k<0, false, false><<<dim3(VV / BN, TT / BM, 1), 256>>>(
        px, lmh, out, nullptr, TT, VV, DD, 0, 0, 0, 0);
}

// round 3
// speedup vs baseline: 2.2102x; 2.2102x over previous
#include <cuda_runtime.h>
#include <math.h>
#include <stdint.h>

// Problem constants
#define TT 1024
#define DD 192
#define NHH 4
#define NN 3072
#define VV 256
#define NLAYER 4
#define KSPLIT 16
#define KCH ((NHH*NN)/KSPLIT)   // 768

// ---------------------------------------------------------------------------
// Static device scratch (no allocation allowed)
// ---------------------------------------------------------------------------
__device__ float  g_x[TT*DD];
__device__ float  g_xs[NHH*TT*NN];
__device__ float  g_qr[NHH*TT*NN];          // qr, later reused as xy
__device__ float  g_sc[NHH*TT*TT];
__device__ float  g_ykv[NHH*TT*DD];
__device__ float  g_part[KSPLIT*TT*DD];
__device__ float2 g_rt[TT*(NN/2)];          // rope (cos,sin) per (t, pair)

__device__ __forceinline__ uint32_t tf32r(float x) {
    uint32_t y;
    asm("cvt.rna.tf32.f32 %0, %1;" : "=r"(y) : "f"(x));
    return y;
}

__device__ __forceinline__ void mma8(float c[4], const uint32_t a[4], const uint32_t b[2]) {
    asm volatile(
        "mma.sync.aligned.m16n8k8.row.col.f32.tf32.tf32.f32 "
        "{%0,%1,%2,%3}, {%4,%5,%6,%7}, {%8,%9}, {%0,%1,%2,%3};"
        : "+f"(c[0]), "+f"(c[1]), "+f"(c[2]), "+f"(c[3])
        : "r"(a[0]), "r"(a[1]), "r"(a[2]), "r"(a[3]), "r"(b[0]), "r"(b[1]));
}

// ---------------------------------------------------------------------------
// tf32 warp-MMA GEMM: C[M,Nc] = epi(A[M,K] @ B)
// Tile 128x128, BK=16, 256 thr (8 warps, 4x2), warp tile 32x64, m16n8k8.
// EPI: 0 plain | 1 relu (+fused rope -> aux as output) | 2 relu * aux | 3 strict tril
// BT : B given as [Nc,K] row-major (compute A @ B^T); else B is [K,Nc]
// AZM: 1 -> A is xy [h][t][n], split-K chunk of KCH selected by blockIdx.z
// ---------------------------------------------------------------------------
template<int EPI, int BT, int AZM>
__global__ __launch_bounds__(256, 2)
void gemm_mma(const float* __restrict__ A, const float* __restrict__ B,
              float* __restrict__ C, const float* __restrict__ aux,
              const float2* __restrict__ rtab,
              int Nc, int K, int lda, int ldb, int ldc,
              long long sA, long long sB, long long sC, long long sAux)
{
    __shared__ uint32_t As[2][16][132];
    __shared__ uint32_t Bs[2][16][132];

    const int bx = blockIdx.x, by = blockIdx.y, bz = blockIdx.z;
    const int tid = threadIdx.x;
    const int wid = tid >> 5, lane = tid & 31;
    const int grp = lane >> 2, qid = lane & 3;
    const int wm0 = (wid & 3) * 32, wn0 = (wid >> 2) * 64;
    const int row0 = by * 128, col0 = bx * 128;

    int koff = 0;
    if (AZM == 1) koff = bz * KCH;
    else          A += (long long)bz * sA;
    B += (long long)bz * sB;
    C += (long long)bz * sC;
    const float* auxr = aux ? aux + (long long)bz * sAux : aux;
    float*       qout = (float*)auxr;

    // fully-masked tile above diagonal: zero-fill, exit
    if (EPI == 3 && bx > by) {
        #pragma unroll 4
        for (int i = tid; i < 128 * 32; i += 256) {
            int r = i >> 5, c4 = (i & 31) << 2;
            *(float4*)(C + (size_t)(row0 + r) * ldc + col0 + c4) = make_float4(0, 0, 0, 0);
        }
        return;
    }

    float acc[2][8][4];
    #pragma unroll
    for (int mi = 0; mi < 2; mi++)
        #pragma unroll
        for (int ni = 0; ni < 8; ni++)
            #pragma unroll
            for (int j = 0; j < 4; j++) acc[mi][ni][j] = 0.f;

    const int nch = K / 16;
    uint4 ra[2], rb[2];

    // ---- helpers ----
    auto ldA = [&](int k0) {
        #pragma unroll
        for (int it = 0; it < 2; it++) {
            int idx4 = tid + it * 256;
            int r = idx4 >> 2, kc = (idx4 & 3) << 2;
            const float* p;
            if (AZM == 1) {
                int gk = koff + k0 + kc;
                int hh = gk / NN, nn = gk - hh * NN;
                p = A + (size_t)hh * TT * NN + (size_t)(row0 + r) * lda + nn;
            } else {
                p = A + (size_t)(row0 + r) * lda + k0 + kc;
            }
            float4 v = *(const float4*)p;
            ra[it] = make_uint4(tf32r(v.x), tf32r(v.y), tf32r(v.z), tf32r(v.w));
        }
    };
    auto ldB = [&](int k0) {
        #pragma unroll
        for (int it = 0; it < 2; it++) {
            int idx4 = tid + it * 256;
            float4 v;
            if (BT) {
                int nr = idx4 >> 2, kc = (idx4 & 3) << 2;
                v = *(const float4*)(B + (size_t)(col0 + nr) * ldb + k0 + kc);
            } else {
                int kr = idx4 >> 5, nc = (idx4 & 31) << 2;
                int gn = col0 + nc;
                v = make_float4(0, 0, 0, 0);
                if (gn < Nc) v = *(const float4*)(B + (size_t)(k0 + kr) * ldb + gn);
            }
            rb[it] = make_uint4(tf32r(v.x), tf32r(v.y), tf32r(v.z), tf32r(v.w));
        }
    };
    auto stAB = [&](int buf) {
        #pragma unroll
        for (int it = 0; it < 2; it++) {
            int idx4 = tid + it * 256;
            { int r = idx4 >> 2, kc = (idx4 & 3) << 2;
              As[buf][kc + 0][r] = ra[it].x; As[buf][kc + 1][r] = ra[it].y;
              As[buf][kc + 2][r] = ra[it].z; As[buf][kc + 3][r] = ra[it].w; }
            if (BT) {
                int nr = idx4 >> 2, kc = (idx4 & 3) << 2;
                Bs[buf][kc + 0][nr] = rb[it].x; Bs[buf][kc + 1][nr] = rb[it].y;
                Bs[buf][kc + 2][nr] = rb[it].z; Bs[buf][kc + 3][nr] = rb[it].w;
            } else {
                int kr = idx4 >> 5, nc = (idx4 & 31) << 2;
                Bs[buf][kr][nc + 0] = rb[it].x; Bs[buf][kr][nc + 1] = rb[it].y;
                Bs[buf][kr][nc + 2] = rb[it].z; Bs[buf][kr][nc + 3] = rb[it].w;
            }
        }
    };

    // prologue
    ldA(0); ldB(0); stAB(0);
    __syncthreads();

    for (int c = 0; c < nch; c++) {
        const int buf = c & 1;
        const bool more = (c + 1 < nch);
        if (more) { ldA((c + 1) * 16); ldB((c + 1) * 16); }
        // compute on smem[buf]
        #pragma unroll
        for (int ks = 0; ks < 16; ks += 8) {
            uint32_t af[2][4], bf8[8][2];
            #pragma unroll
            for (int mi = 0; mi < 2; mi++) {
                int r0 = wm0 + mi * 16;
                af[mi][0] = As[buf][ks + qid    ][r0 + grp];
                af[mi][1] = As[buf][ks + qid    ][r0 + grp + 8];
                af[mi][2] = As[buf][ks + qid + 4][r0 + grp];
                af[mi][3] = As[buf][ks + qid + 4][r0 + grp + 8];
            }
            #pragma unroll
            for (int ni = 0; ni < 8; ni++) {
                int n0 = wn0 + ni * 8;
                bf8[ni][0] = Bs[buf][ks + qid    ][n0 + grp];
                bf8[ni][1] = Bs[buf][ks + qid + 4][n0 + grp];
            }
            #pragma unroll
            for (int mi = 0; mi < 2; mi++)
                #pragma unroll
                for (int ni = 0; ni < 8; ni++)
                    mma8(acc[mi][ni], af[mi], bf8[ni]);
        }
        if (more) stAB(buf ^ 1);
        __syncthreads();
    }

    // ---- epilogue ----
    #pragma unroll
    for (int mi = 0; mi < 2; mi++) {
        const int rA = row0 + wm0 + mi * 16 + grp;
        const int rB = rA + 8;
        #pragma unroll
        for (int ni = 0; ni < 8; ni++) {
            const int c = col0 + wn0 + ni * 8 + (qid << 1);
            if (c >= Nc) continue;
            float2 lo = make_float2(acc[mi][ni][0], acc[mi][ni][1]);
            float2 hi = make_float2(acc[mi][ni][2], acc[mi][ni][3]);
            if (EPI == 0) {
                *(float2*)(C + (size_t)rA * ldc + c) = lo;
                *(float2*)(C + (size_t)rB * ldc + c) = hi;
            } else if (EPI == 1) {
                lo.x = fmaxf(lo.x, 0.f); lo.y = fmaxf(lo.y, 0.f);
                hi.x = fmaxf(hi.x, 0.f); hi.y = fmaxf(hi.y, 0.f);
                *(float2*)(C + (size_t)rA * ldc + c) = lo;
                *(float2*)(C + (size_t)rB * ldc + c) = hi;
                // fused rope (even/odd pair is exactly this fragment's columns)
                float2 ca = rtab[(size_t)rA * (NN / 2) + (c >> 1)];
                float2 cb = rtab[(size_t)rB * (NN / 2) + (c >> 1)];
                float2 qa, qb;
                qa.x = lo.x * ca.x - lo.y * ca.y;
                qa.y = lo.y * ca.x + lo.x * ca.y;
                qb.x = hi.x * cb.x - hi.y * cb.y;
                qb.y = hi.y * cb.x + hi.x * cb.y;
                *(float2*)(qout + (size_t)rA * ldc + c) = qa;
                *(float2*)(qout + (size_t)rB * ldc + c) = qb;
            } else if (EPI == 2) {
                float2 ea = *(const float2*)(auxr + (size_t)rA * ldc + c);
                float2 eb = *(const float2*)(auxr + (size_t)rB * ldc + c);
                lo.x = fmaxf(lo.x, 0.f) * ea.x; lo.y = fmaxf(lo.y, 0.f) * ea.y;
                hi.x = fmaxf(hi.x, 0.f) * eb.x; hi.y = fmaxf(hi.y, 0.f) * eb.y;
                *(float2*)(C + (size_t)rA * ldc + c) = lo;
                *(float2*)(C + (size_t)rB * ldc + c) = hi;
            } else { // EPI == 3: strict lower-triangular mask
                float2 oa, ob;
                oa.x = (c     < rA) ? lo.x : 0.f;
                oa.y = (c + 1 < rA) ? lo.y : 0.f;
                ob.x = (c     < rB) ? hi.x : 0.f;
                ob.y = (c + 1 < rB) ? hi.y : 0.f;
                *(float2*)(C + (size_t)rA * ldc + c) = oa;
                *(float2*)(C + (size_t)rB * ldc + c) = ob;
            }
        }
    }
}

// ---------------------------------------------------------------------------
// LayerNorm helpers (192-wide rows, 6 warps)
// ---------------------------------------------------------------------------
__device__ __forceinline__ float2 meanvar192(float v, float* s1, float* s2)
{
    __syncthreads();
    float a = v, b = v * v;
    #pragma unroll
    for (int o = 16; o > 0; o >>= 1) {
        a += __shfl_down_sync(0xffffffffu, a, o);
        b += __shfl_down_sync(0xffffffffu, b, o);
    }
    int lane = threadIdx.x & 31, w = threadIdx.x >> 5;
    if (lane == 0) { s1[w] = a; s2[w] = b; }
    __syncthreads();
    if (threadIdx.x == 0) {
        float sa = 0.f, sb = 0.f;
        #pragma unroll
        for (int i = 0; i < 6; i++) { sa += s1[i]; sb += s2[i]; }
        s1[0] = sa; s2[0] = sb;
    }
    __syncthreads();
    float m   = s1[0] * (1.0f / 192.0f);
    float var = s2[0] * (1.0f / 192.0f) - m * m;
    return make_float2(m, fmaxf(var, 0.f));
}

__global__ void embed_ln_k(const int* __restrict__ idx,
                           const float* __restrict__ emb,
                           const float* __restrict__ pos)
{
    int t = blockIdx.x, d = threadIdx.x;
    __shared__ float s1[8], s2[8];
    float v = emb[(size_t)idx[t] * DD + d] + pos[(size_t)t * DD + d];
    float2 mv = meanvar192(v, s1, s2);
    g_x[(size_t)t * DD + d] = (v - mv.x) * rsqrtf(mv.y + 1e-5f);
}

// rope table: g_rt[t][p] = (cos, sin) of phase(t, col=2p)
__global__ void sincos_k()
{
    int i = blockIdx.x * blockDim.x + threadIdx.x;
    if (i >= TT * (NN / 2)) return;
    int t = i / (NN / 2);
    int p = i - t * (NN / 2);
    float f = exp2f(-(float)p * (1.0f / 96.0f)) * 0.15915494309189535f;
    float ph = fmodf((float)t * f, 1.0f) * 6.283185307179586f;
    float s, c;
    sincosf(ph, &s, &c);
    g_rt[i] = make_float2(c, s);
}

__global__ void ln_ykv_k()
{
    int r = blockIdx.x, d = threadIdx.x;
    __shared__ float s1[8], s2[8];
    float v = g_ykv[(size_t)r * DD + d];
    float2 mv = meanvar192(v, s1, s2);
    g_ykv[(size_t)r * DD + d] = (v - mv.x) * rsqrtf(mv.y + 1e-5f);
}

__global__ void finalize_k()
{
    int t = blockIdx.x, d = threadIdx.x;
    __shared__ float s1[8], s2[8];
    float ym = 0.f;
    #pragma unroll
    for (int c = 0; c < KSPLIT; c++)
        ym += g_part[(size_t)c * TT * DD + (size_t)t * DD + d];
    float2 mv = meanvar192(ym, s1, s2);
    float l1 = (ym - mv.x) * rsqrtf(mv.y + 1e-5f);
    float xv = g_x[(size_t)t * DD + d] + l1;
    float2 mv2 = meanvar192(xv, s1, s2);
    g_x[(size_t)t * DD + d] = (xv - mv2.x) * rsqrtf(mv2.y + 1e-5f);
}

// ---------------------------------------------------------------------------
extern "C" void kernel_launch(void* const* d_in, const int* in_sizes, int n_in,
                              void* d_out, int out_size)
{
    const int*   idx  = (const int*)  d_in[0];
    const float* decx = (const float*)d_in[1];   // (NH, D, N)
    const float* decy = (const float*)d_in[2];   // (NH, D, N)
    const float* enc  = (const float*)d_in[3];   // (NH*N, D)
    const float* emb  = (const float*)d_in[4];   // (VOCAB, D)
    const float* pos  = (const float*)d_in[5];   // (BLOCK, D)
    const float* lmh  = (const float*)d_in[6];   // (D, VOCAB)
    float* out = (float*)d_out;

    float *px, *pxs, *pqr, *psc, *pykv, *ppart;
    float2* prt;
    cudaGetSymbolAddress((void**)&px,    g_x);
    cudaGetSymbolAddress((void**)&pxs,   g_xs);
    cudaGetSymbolAddress((void**)&pqr,   g_qr);
    cudaGetSymbolAddress((void**)&psc,   g_sc);
    cudaGetSymbolAddress((void**)&pykv,  g_ykv);
    cudaGetSymbolAddress((void**)&ppart, g_part);
    cudaGetSymbolAddress((void**)&prt,   g_rt);

    sincos_k<<<(TT * (NN / 2) + 255) / 256, 256>>>();
    embed_ln_k<<<TT, 192>>>(idx, emb, pos);

    for (int l = 0; l < NLAYER; l++) {
        // x_sparse = relu(x @ decx[h]);  qr = rope(x_sparse)  [fused epilogue]
        gemm_mma<1, 0, 0><<<dim3(NN / 128, TT / 128, NHH), 256>>>(
            px, decx, pxs, pqr, prt, NN, DD, DD, NN, NN,
            0LL, (long long)DD * NN, (long long)TT * NN, (long long)TT * NN);

        // scores = (qr @ qr^T) * tril(-1)
        gemm_mma<3, 1, 0><<<dim3(TT / 128, TT / 128, NHH), 256>>>(
            pqr, pqr, psc, nullptr, nullptr, TT, NN, NN, NN, TT,
            (long long)TT * NN, (long long)TT * NN, (long long)TT * TT, 0LL);

        // ykv_raw = scores @ x
        gemm_mma<0, 0, 0><<<dim3((DD + 127) / 128, TT / 128, NHH), 256>>>(
            psc, px, pykv, nullptr, nullptr, DD, TT, TT, DD, DD,
            (long long)TT * TT, 0LL, (long long)TT * DD, 0LL);

        // ykv = ln(ykv_raw)
        ln_ykv_k<<<NHH * TT, 192>>>();

        // xy = relu(ykv @ decy[h]) * x_sparse   -> g_qr (reuse)
        gemm_mma<2, 0, 0><<<dim3(NN / 128, TT / 128, NHH), 256>>>(
            pykv, decy, pqr, pxs, nullptr, NN, DD, DD, NN, NN,
            (long long)TT * DD, (long long)DD * NN, (long long)TT * NN,
            (long long)TT * NN);

        // ymlp partials: xy[1024,12288] @ enc[12288,192], split-K = 16
        gemm_mma<0, 0, 1><<<dim3((DD + 127) / 128, TT / 128, KSPLIT), 256>>>(
            pqr, enc, ppart, nullptr, nullptr, DD, KCH, NN, DD, DD,
            0LL, (long long)KCH * DD, (long long)TT * DD, 0LL);

        // x = ln(x + ln(sum partials))
        finalize_k<<<TT, 192>>>();
    }

    // logits = x @ lm_head
    gemm_mma<0, 0, 0><<<dim3(VV / 128, TT / 128, 1), 256>>>(
        px, lmh, out, nullptr, nullptr, VV, DD, DD, VV, VV,
        0LL, 0LL, 0LL, 0LL);
}

// round 4
// speedup vs baseline: 2.9039x; 1.3139x over previous
#include <cuda_runtime.h>
#include <math.h>
#include <stdint.h>

// Problem constants
#define TT 1024
#define DD 192
#define NHH 4
#define NN 3072
#define VV 256
#define NLAYER 4
#define KSPLIT 16
#define KCH ((NHH*NN)/KSPLIT)   // 768
#define NSTAGE 4

// ---------------------------------------------------------------------------
// Static device scratch (no allocation allowed) -- 16B aligned for cp.async
// ---------------------------------------------------------------------------
__device__ __align__(16) float  g_x[TT*DD];
__device__ __align__(16) float  g_xs[NHH*TT*NN];
__device__ __align__(16) float  g_qr[NHH*TT*NN];     // qr, later reused as xy
__device__ __align__(16) float  g_sc[NHH*TT*TT];
__device__ __align__(16) float  g_ykv[NHH*TT*DD];
__device__ __align__(16) float  g_part[KSPLIT*TT*DD];
__device__ __align__(16) float2 g_rt[TT*(NN/2)];     // rope (cos,sin) per (t, pair)

__device__ __forceinline__ uint32_t tf32r(float x) {
    uint32_t y;
    asm("cvt.rna.tf32.f32 %0, %1;" : "=r"(y) : "f"(x));
    return y;
}
__device__ __forceinline__ uint32_t su32(const void* p) {
    uint32_t a;
    asm("{ .reg .u64 t; cvta.to.shared.u64 t, %1; cvt.u32.u64 %0, t; }"
        : "=r"(a) : "l"(p));
    return a;
}
__device__ __forceinline__ void cp16(uint32_t dst, const void* src, bool full) {
    int sz = full ? 16 : 0;
    asm volatile("cp.async.cg.shared.global [%0], [%1], 16, %2;"
                 :: "r"(dst), "l"(src), "r"(sz) : "memory");
}
__device__ __forceinline__ void mma8(float c[4], const uint32_t a[4], const uint32_t b[2]) {
    asm volatile(
        "mma.sync.aligned.m16n8k8.row.col.f32.tf32.tf32.f32 "
        "{%0,%1,%2,%3}, {%4,%5,%6,%7}, {%8,%9}, {%0,%1,%2,%3};"
        : "+f"(c[0]), "+f"(c[1]), "+f"(c[2]), "+f"(c[3])
        : "r"(a[0]), "r"(a[1]), "r"(a[2]), "r"(a[3]), "r"(b[0]), "r"(b[1]));
}

// ---------------------------------------------------------------------------
// tf32 warp-MMA GEMM, cp.async 4-stage pipeline.
// C[M,Nc] = epi(A[M,K] @ B); tile 128x128, BK=16, 8 warps (4x2), warp 32x64.
// EPI: 0 plain | 1 relu (+fused rope -> aux out) | 2 relu * aux | 3 strict tril
// BT : B given as [Nc,K] row-major (A @ B^T); else B is [K,Nc]
// AZM: 1 -> A is xy [h][t][n], split-K chunk KCH selected by blockIdx.z
// smem: A [S][128][20]f ; B(BT) [S][128][20]f ; B(nonBT) [S][16][136]f
// ---------------------------------------------------------------------------
#define A_ROW 20
#define A_STG (128*A_ROW)        // floats per A stage
#define BT_STG (128*A_ROW)
#define BN_ROW 136
#define BN_STG (16*BN_ROW)

template<int EPI, int BT, int AZM>
__global__ __launch_bounds__(256, 2)
void gemm_mma(const float* __restrict__ A, const float* __restrict__ B,
              float* __restrict__ C, const float* __restrict__ aux,
              const float2* __restrict__ rtab,
              int Nc, int K, int lda, int ldb, int ldc,
              long long sA, long long sB, long long sC, long long sAux)
{
    extern __shared__ float smf[];
    float* sA_f = smf;                         // [NSTAGE][128][20]
    float* sB_f = smf + NSTAGE * A_STG;        // BT or nonBT layout

    const int bx = blockIdx.x, by = blockIdx.y, bz = blockIdx.z;
    const int tid = threadIdx.x;
    const int wid = tid >> 5, lane = tid & 31;
    const int grp = lane >> 2, qid = lane & 3;
    const int wm0 = (wid & 3) * 32, wn0 = (wid >> 2) * 64;
    const int row0 = by * 128, col0 = bx * 128;

    int koff = 0;
    if (AZM == 1) koff = bz * KCH;
    else          A += (long long)bz * sA;
    B += (long long)bz * sB;
    C += (long long)bz * sC;
    const float* auxr = aux ? aux + (long long)bz * sAux : aux;
    float*       qout = (float*)auxr;

    // fully-masked tile above diagonal: zero-fill, exit
    if (EPI == 3 && bx > by) {
        #pragma unroll 4
        for (int i = tid; i < 128 * 32; i += 256) {
            int r = i >> 5, c4 = (i & 31) << 2;
            *(float4*)(C + (size_t)(row0 + r) * ldc + col0 + c4) = make_float4(0, 0, 0, 0);
        }
        return;
    }

    const uint32_t sA_u = su32(sA_f);
    const uint32_t sB_u = su32(sB_f);

    float acc[2][8][4];
    #pragma unroll
    for (int mi = 0; mi < 2; mi++)
        #pragma unroll
        for (int ni = 0; ni < 8; ni++)
            #pragma unroll
            for (int j = 0; j < 4; j++) acc[mi][ni][j] = 0.f;

    const int nch = K / 16;

    auto issue = [&](int s) {
        const int k0 = s * 16;
        const int buf = s & (NSTAGE - 1);
        // A: 512 x 16B chunks
        #pragma unroll
        for (int it = 0; it < 2; it++) {
            int idx4 = tid + it * 256;
            int r = idx4 >> 2, kc = (idx4 & 3) << 2;
            const float* src;
            if (AZM == 1) {
                int gk = koff + k0 + kc;
                int hh = gk / NN, nn = gk - hh * NN;
                src = A + (size_t)hh * TT * NN + (size_t)(row0 + r) * lda + nn;
            } else {
                src = A + (size_t)(row0 + r) * lda + k0 + kc;
            }
            cp16(sA_u + (buf * A_STG + r * A_ROW + kc) * 4, src, true);
        }
        // B
        #pragma unroll
        for (int it = 0; it < 2; it++) {
            int idx4 = tid + it * 256;
            if (BT) {
                int nr = idx4 >> 2, kc = (idx4 & 3) << 2;
                const float* src = B + (size_t)(col0 + nr) * ldb + k0 + kc;
                cp16(sB_u + (buf * BT_STG + nr * A_ROW + kc) * 4, src, true);
            } else {
                int kr = idx4 >> 5, nc = (idx4 & 31) << 2;
                int gn = col0 + nc;
                const float* src = B + (size_t)(k0 + kr) * ldb + gn;
                cp16(sB_u + (buf * BN_STG + kr * BN_ROW + nc) * 4, src, gn < Nc);
            }
        }
        asm volatile("cp.async.commit_group;" ::: "memory");
    };

    // prologue: NSTAGE-1 stages (nch >= 12 always)
    #pragma unroll
    for (int s = 0; s < NSTAGE - 1; s++) issue(s);

    for (int c = 0; c < nch; c++) {
        asm volatile("cp.async.wait_group %0;" :: "n"(NSTAGE - 2) : "memory");
        __syncthreads();
        if (c + NSTAGE - 1 < nch) issue(c + NSTAGE - 1);   // fills buffer freed last iter

        const int buf = c & (NSTAGE - 1);
        const float* Ab = sA_f + buf * A_STG;
        const float* Bb = sB_f + buf * (BT ? BT_STG : BN_STG);
        #pragma unroll
        for (int ks = 0; ks < 16; ks += 8) {
            uint32_t af[2][4], bf8[8][2];
            #pragma unroll
            for (int mi = 0; mi < 2; mi++) {
                int r0 = wm0 + mi * 16;
                af[mi][0] = tf32r(Ab[(r0 + grp    ) * A_ROW + ks + qid    ]);
                af[mi][1] = tf32r(Ab[(r0 + grp + 8) * A_ROW + ks + qid    ]);
                af[mi][2] = tf32r(Ab[(r0 + grp    ) * A_ROW + ks + qid + 4]);
                af[mi][3] = tf32r(Ab[(r0 + grp + 8) * A_ROW + ks + qid + 4]);
            }
            #pragma unroll
            for (int ni = 0; ni < 8; ni++) {
                int n0 = wn0 + ni * 8;
                if (BT) {
                    bf8[ni][0] = tf32r(Bb[(n0 + grp) * A_ROW + ks + qid    ]);
                    bf8[ni][1] = tf32r(Bb[(n0 + grp) * A_ROW + ks + qid + 4]);
                } else {
                    bf8[ni][0] = tf32r(Bb[(ks + qid    ) * BN_ROW + n0 + grp]);
                    bf8[ni][1] = tf32r(Bb[(ks + qid + 4) * BN_ROW + n0 + grp]);
                }
            }
            #pragma unroll
            for (int mi = 0; mi < 2; mi++)
                #pragma unroll
                for (int ni = 0; ni < 8; ni++)
                    mma8(acc[mi][ni], af[mi], bf8[ni]);
        }
    }

    // ---- epilogue ----
    #pragma unroll
    for (int mi = 0; mi < 2; mi++) {
        const int rA = row0 + wm0 + mi * 16 + grp;
        const int rB = rA + 8;
        #pragma unroll
        for (int ni = 0; ni < 8; ni++) {
            const int c = col0 + wn0 + ni * 8 + (qid << 1);
            if (c >= Nc) continue;
            float2 lo = make_float2(acc[mi][ni][0], acc[mi][ni][1]);
            float2 hi = make_float2(acc[mi][ni][2], acc[mi][ni][3]);
            if (EPI == 0) {
                *(float2*)(C + (size_t)rA * ldc + c) = lo;
                *(float2*)(C + (size_t)rB * ldc + c) = hi;
            } else if (EPI == 1) {
                lo.x = fmaxf(lo.x, 0.f); lo.y = fmaxf(lo.y, 0.f);
                hi.x = fmaxf(hi.x, 0.f); hi.y = fmaxf(hi.y, 0.f);
                *(float2*)(C + (size_t)rA * ldc + c) = lo;
                *(float2*)(C + (size_t)rB * ldc + c) = hi;
                float2 ca = rtab[(size_t)rA * (NN / 2) + (c >> 1)];
                float2 cb = rtab[(size_t)rB * (NN / 2) + (c >> 1)];
                float2 qa, qb;
                qa.x = lo.x * ca.x - lo.y * ca.y;
                qa.y = lo.y * ca.x + lo.x * ca.y;
                qb.x = hi.x * cb.x - hi.y * cb.y;
                qb.y = hi.y * cb.x + hi.x * cb.y;
                *(float2*)(qout + (size_t)rA * ldc + c) = qa;
                *(float2*)(qout + (size_t)rB * ldc + c) = qb;
            } else if (EPI == 2) {
                float2 ea = *(const float2*)(auxr + (size_t)rA * ldc + c);
                float2 eb = *(const float2*)(auxr + (size_t)rB * ldc + c);
                lo.x = fmaxf(lo.x, 0.f) * ea.x; lo.y = fmaxf(lo.y, 0.f) * ea.y;
                hi.x = fmaxf(hi.x, 0.f) * eb.x; hi.y = fmaxf(hi.y, 0.f) * eb.y;
                *(float2*)(C + (size_t)rA * ldc + c) = lo;
                *(float2*)(C + (size_t)rB * ldc + c) = hi;
            } else { // EPI == 3
                float2 oa, ob;
                oa.x = (c     < rA) ? lo.x : 0.f;
                oa.y = (c + 1 < rA) ? lo.y : 0.f;
                ob.x = (c     < rB) ? hi.x : 0.f;
                ob.y = (c + 1 < rB) ? hi.y : 0.f;
                *(float2*)(C + (size_t)rA * ldc + c) = oa;
                *(float2*)(C + (size_t)rB * ldc + c) = ob;
            }
        }
    }
}

// ---------------------------------------------------------------------------
// LayerNorm helpers (192-wide rows, 6 warps)
// ---------------------------------------------------------------------------
__device__ __forceinline__ float2 meanvar192(float v, float* s1, float* s2)
{
    __syncthreads();
    float a = v, b = v * v;
    #pragma unroll
    for (int o = 16; o > 0; o >>= 1) {
        a += __shfl_down_sync(0xffffffffu, a, o);
        b += __shfl_down_sync(0xffffffffu, b, o);
    }
    int lane = threadIdx.x & 31, w = threadIdx.x >> 5;
    if (lane == 0) { s1[w] = a; s2[w] = b; }
    __syncthreads();
    if (threadIdx.x == 0) {
        float sa = 0.f, sb = 0.f;
        #pragma unroll
        for (int i = 0; i < 6; i++) { sa += s1[i]; sb += s2[i]; }
        s1[0] = sa; s2[0] = sb;
    }
    __syncthreads();
    float m   = s1[0] * (1.0f / 192.0f);
    float var = s2[0] * (1.0f / 192.0f) - m * m;
    return make_float2(m, fmaxf(var, 0.f));
}

__global__ void embed_ln_k(const int* __restrict__ idx,
                           const float* __restrict__ emb,
                           const float* __restrict__ pos)
{
    int t = blockIdx.x, d = threadIdx.x;
    __shared__ float s1[8], s2[8];
    float v = emb[(size_t)idx[t] * DD + d] + pos[(size_t)t * DD + d];
    float2 mv = meanvar192(v, s1, s2);
    g_x[(size_t)t * DD + d] = (v - mv.x) * rsqrtf(mv.y + 1e-5f);
}

__global__ void sincos_k()
{
    int i = blockIdx.x * blockDim.x + threadIdx.x;
    if (i >= TT * (NN / 2)) return;
    int t = i / (NN / 2);
    int p = i - t * (NN / 2);
    float f = exp2f(-(float)p * (1.0f / 96.0f)) * 0.15915494309189535f;
    float ph = fmodf((float)t * f, 1.0f) * 6.283185307179586f;
    float s, c;
    sincosf(ph, &s, &c);
    g_rt[i] = make_float2(c, s);
}

__global__ void ln_ykv_k()
{
    int r = blockIdx.x, d = threadIdx.x;
    __shared__ float s1[8], s2[8];
    float v = g_ykv[(size_t)r * DD + d];
    float2 mv = meanvar192(v, s1, s2);
    g_ykv[(size_t)r * DD + d] = (v - mv.x) * rsqrtf(mv.y + 1e-5f);
}

__global__ void finalize_k()
{
    int t = blockIdx.x, d = threadIdx.x;
    __shared__ float s1[8], s2[8];
    float ym = 0.f;
    #pragma unroll
    for (int c = 0; c < KSPLIT; c++)
        ym += g_part[(size_t)c * TT * DD + (size_t)t * DD + d];
    float2 mv = meanvar192(ym, s1, s2);
    float l1 = (ym - mv.x) * rsqrtf(mv.y + 1e-5f);
    float xv = g_x[(size_t)t * DD + d] + l1;
    float2 mv2 = meanvar192(xv, s1, s2);
    g_x[(size_t)t * DD + d] = (xv - mv2.x) * rsqrtf(mv2.y + 1e-5f);
}

// ---------------------------------------------------------------------------
extern "C" void kernel_launch(void* const* d_in, const int* in_sizes, int n_in,
                              void* d_out, int out_size)
{
    const int*   idx  = (const int*)  d_in[0];
    const float* decx = (const float*)d_in[1];   // (NH, D, N)
    const float* decy = (const float*)d_in[2];   // (NH, D, N)
    const float* enc  = (const float*)d_in[3];   // (NH*N, D)
    const float* emb  = (const float*)d_in[4];   // (VOCAB, D)
    const float* pos  = (const float*)d_in[5];   // (BLOCK, D)
    const float* lmh  = (const float*)d_in[6];   // (D, VOCAB)
    float* out = (float*)d_out;

    float *px, *pxs, *pqr, *psc, *pykv, *ppart;
    float2* prt;
    cudaGetSymbolAddress((void**)&px,    g_x);
    cudaGetSymbolAddress((void**)&pxs,   g_xs);
    cudaGetSymbolAddress((void**)&pqr,   g_qr);
    cudaGetSymbolAddress((void**)&psc,   g_sc);
    cudaGetSymbolAddress((void**)&pykv,  g_ykv);
    cudaGetSymbolAddress((void**)&ppart, g_part);
    cudaGetSymbolAddress((void**)&prt,   g_rt);

    const int SM_BT  = NSTAGE * (A_STG + BT_STG) * 4;   // 81920 B
    const int SM_NBT = NSTAGE * (A_STG + BN_STG) * 4;   // 75776 B
    cudaFuncSetAttribute(gemm_mma<1,0,0>, cudaFuncAttributeMaxDynamicSharedMemorySize, SM_NBT);
    cudaFuncSetAttribute(gemm_mma<3,1,0>, cudaFuncAttributeMaxDynamicSharedMemorySize, SM_BT);
    cudaFuncSetAttribute(gemm_mma<0,0,0>, cudaFuncAttributeMaxDynamicSharedMemorySize, SM_NBT);
    cudaFuncSetAttribute(gemm_mma<2,0,0>, cudaFuncAttributeMaxDynamicSharedMemorySize, SM_NBT);
    cudaFuncSetAttribute(gemm_mma<0,0,1>, cudaFuncAttributeMaxDynamicSharedMemorySize, SM_NBT);

    sincos_k<<<(TT * (NN / 2) + 255) / 256, 256>>>();
    embed_ln_k<<<TT, 192>>>(idx, emb, pos);

    for (int l = 0; l < NLAYER; l++) {
        // x_sparse = relu(x @ decx[h]);  qr = rope(x_sparse)  [fused epilogue]
        gemm_mma<1, 0, 0><<<dim3(NN / 128, TT / 128, NHH), 256, SM_NBT>>>(
            px, decx, pxs, pqr, prt, NN, DD, DD, NN, NN,
            0LL, (long long)DD * NN, (long long)TT * NN, (long long)TT * NN);

        // scores = (qr @ qr^T) * tril(-1)
        gemm_mma<3, 1, 0><<<dim3(TT / 128, TT / 128, NHH), 256, SM_BT>>>(
            pqr, pqr, psc, nullptr, nullptr, TT, NN, NN, NN, TT,
            (long long)TT * NN, (long long)TT * NN, (long long)TT * TT, 0LL);

        // ykv_raw = scores @ x
        gemm_mma<0, 0, 0><<<dim3((DD + 127) / 128, TT / 128, NHH), 256, SM_NBT>>>(
            psc, px, pykv, nullptr, nullptr, DD, TT, TT, DD, DD,
            (long long)TT * TT, 0LL, (long long)TT * DD, 0LL);

        // ykv = ln(ykv_raw)
        ln_ykv_k<<<NHH * TT, 192>>>();

        // xy = relu(ykv @ decy[h]) * x_sparse   -> g_qr (reuse)
        gemm_mma<2, 0, 0><<<dim3(NN / 128, TT / 128, NHH), 256, SM_NBT>>>(
            pykv, decy, pqr, pxs, nullptr, NN, DD, DD, NN, NN,
            (long long)TT * DD, (long long)DD * NN, (long long)TT * NN,
            (long long)TT * NN);

        // ymlp partials: xy[1024,12288] @ enc[12288,192], split-K = 16
        gemm_mma<0, 0, 1><<<dim3((DD + 127) / 128, TT / 128, KSPLIT), 256, SM_NBT>>>(
            pqr, enc, ppart, nullptr, nullptr, DD, KCH, NN, DD, DD,
            0LL, (long long)KCH * DD, (long long)TT * DD, 0LL);

        // x = ln(x + ln(sum partials))
        finalize_k<<<TT, 192>>>();
    }

    // logits = x @ lm_head
    gemm_mma<0, 0, 0><<<dim3(VV / 128, TT / 128, 1), 256, SM_NBT>>>(
        px, lmh, out, nullptr, nullptr, VV, DD, DD, VV, VV,
        0LL, 0LL, 0LL, 0LL);
}

// round 6
// speedup vs baseline: 2.9631x; 1.0204x over previous
#include <cuda_runtime.h>
#include <math.h>
#include <stdint.h>

// Problem constants
#define TT 1024
#define DD 192
#define NHH 4
#define NN 3072
#define VV 256
#define NLAYER 4
#define KSPLIT 16
#define KCH ((NHH*NN)/KSPLIT)   // 768
#define NSTAGE 4

// ---------------------------------------------------------------------------
// Static device scratch (no allocation allowed) -- 16B aligned for cp.async
// ---------------------------------------------------------------------------
__device__ __align__(16) float  g_x[TT*DD];        // fp32 residual chain
__device__ __align__(16) float  g_xr[TT*DD];       // tf32-rounded copy for GEMMs
__device__ __align__(16) float  g_xs[NHH*TT*NN];   // fp32 (elementwise use only)
__device__ __align__(16) float  g_qr[NHH*TT*NN];   // tf32; later reused as xy (tf32)
__device__ __align__(16) float  g_sc[NHH*TT*TT];   // tf32
__device__ __align__(16) float  g_ykv[NHH*TT*DD];  // fp32 raw -> tf32 after ln
__device__ __align__(16) float  g_part[KSPLIT*TT*DD];
__device__ __align__(16) float2 g_rt[TT*(NN/2)];   // rope (cos,sin)
// tf32-prerounded weight copies
__device__ __align__(16) float  g_wdx[NHH*DD*NN];
__device__ __align__(16) float  g_wdy[NHH*DD*NN];
__device__ __align__(16) float  g_wenc[NHH*NN*DD];
__device__ __align__(16) float  g_wlmh[DD*VV];

__device__ __forceinline__ uint32_t tf32r(float x) {
    uint32_t y;
    asm("cvt.rna.tf32.f32 %0, %1;" : "=r"(y) : "f"(x));
    return y;
}
__device__ __forceinline__ float tf32f(float x) { return __uint_as_float(tf32r(x)); }
__device__ __forceinline__ uint32_t su32(const void* p) {
    uint32_t a;
    asm("{ .reg .u64 t; cvta.to.shared.u64 t, %1; cvt.u32.u64 %0, t; }"
        : "=r"(a) : "l"(p));
    return a;
}
__device__ __forceinline__ void cp16(uint32_t dst, const void* src, bool full) {
    int sz = full ? 16 : 0;
    asm volatile("cp.async.cg.shared.global [%0], [%1], 16, %2;"
                 :: "r"(dst), "l"(src), "r"(sz) : "memory");
}
__device__ __forceinline__ void mma8(float c[4], const uint32_t a[4], const uint32_t b[2]) {
    asm volatile(
        "mma.sync.aligned.m16n8k8.row.col.f32.tf32.tf32.f32 "
        "{%0,%1,%2,%3}, {%4,%5,%6,%7}, {%8,%9}, {%0,%1,%2,%3};"
        : "+f"(c[0]), "+f"(c[1]), "+f"(c[2]), "+f"(c[3])
        : "r"(a[0]), "r"(a[1]), "r"(a[2]), "r"(a[3]), "r"(b[0]), "r"(b[1]));
}

// ---------------------------------------------------------------------------
// tf32 warp-MMA GEMM, cp.async 4-stage pipeline, warp tile 64x64.
// CTA tile 128x128, BK=16, 128 threads (4 warps, 2x2).
// All A/B inputs must be tf32-prerounded (no cvt in mainloop).
// EPI: 0 plain fp32 | 1 relu->fp32 to C (+fused rope, single-round -> aux tf32) |
//      2 relu*aux (fp32 math, single-round -> tf32) | 3 strict tril (single-round tf32)
// BT : B given as [Nc,K] row-major (A @ B^T); else B is [K,Nc]
// AZM: 1 -> A is xy [h][t][n], split-K chunk KCH selected by blockIdx.z
// ---------------------------------------------------------------------------
#define A_ROW 20
#define A_STG (128*A_ROW)
#define BT_STG (128*A_ROW)
#define BN_ROW 136
#define BN_STG (16*BN_ROW)

template<int EPI, int BT, int AZM>
__global__ __launch_bounds__(128, 2)
void gemm_mma(const float* __restrict__ A, const float* __restrict__ B,
              float* __restrict__ C, const float* __restrict__ aux,
              const float2* __restrict__ rtab,
              int Nc, int K, int lda, int ldb, int ldc,
              long long sA, long long sB, long long sC, long long sAux)
{
    extern __shared__ float smf[];
    float* sA_f = smf;
    float* sB_f = smf + NSTAGE * A_STG;

    const int bx = blockIdx.x, by = blockIdx.y, bz = blockIdx.z;
    const int tid = threadIdx.x;
    const int wid = tid >> 5, lane = tid & 31;
    const int grp = lane >> 2, qid = lane & 3;
    const int wm0 = (wid & 1) * 64, wn0 = (wid >> 1) * 64;
    const int row0 = by * 128, col0 = bx * 128;

    int koff = 0;
    if (AZM == 1) koff = bz * KCH;
    else          A += (long long)bz * sA;
    B += (long long)bz * sB;
    C += (long long)bz * sC;
    const float* auxr = aux ? aux + (long long)bz * sAux : aux;
    float*       qout = (float*)auxr;

    // fully-masked tile above diagonal: zero-fill, exit
    if (EPI == 3 && bx > by) {
        #pragma unroll 4
        for (int i = tid; i < 128 * 32; i += 128) {
            int r = i >> 5, c4 = (i & 31) << 2;
            *(float4*)(C + (size_t)(row0 + r) * ldc + col0 + c4) = make_float4(0, 0, 0, 0);
        }
        return;
    }

    const uint32_t sA_u = su32(sA_f);
    const uint32_t sB_u = su32(sB_f);

    float acc[4][8][4];
    #pragma unroll
    for (int mi = 0; mi < 4; mi++)
        #pragma unroll
        for (int ni = 0; ni < 8; ni++)
            #pragma unroll
            for (int j = 0; j < 4; j++) acc[mi][ni][j] = 0.f;

    const int nch = K / 16;

    auto issue = [&](int s) {
        const int k0 = s * 16;
        const int buf = s & (NSTAGE - 1);
        #pragma unroll
        for (int it = 0; it < 4; it++) {
            int idx4 = tid + it * 128;
            int r = idx4 >> 2, kc = (idx4 & 3) << 2;
            const float* src;
            if (AZM == 1) {
                int gk = koff + k0 + kc;
                int hh = gk / NN, nn = gk - hh * NN;
                src = A + (size_t)hh * TT * NN + (size_t)(row0 + r) * lda + nn;
            } else {
                src = A + (size_t)(row0 + r) * lda + k0 + kc;
            }
            cp16(sA_u + (buf * A_STG + r * A_ROW + kc) * 4, src, true);
        }
        #pragma unroll
        for (int it = 0; it < 4; it++) {
            int idx4 = tid + it * 128;
            if (BT) {
                int nr = idx4 >> 2, kc = (idx4 & 3) << 2;
                const float* src = B + (size_t)(col0 + nr) * ldb + k0 + kc;
                cp16(sB_u + (buf * BT_STG + nr * A_ROW + kc) * 4, src, true);
            } else {
                int kr = idx4 >> 5, nc = (idx4 & 31) << 2;
                int gn = col0 + nc;
                const float* src = B + (size_t)(k0 + kr) * ldb + gn;
                cp16(sB_u + (buf * BN_STG + kr * BN_ROW + nc) * 4, src, gn < Nc);
            }
        }
        asm volatile("cp.async.commit_group;" ::: "memory");
    };

    #pragma unroll
    for (int s = 0; s < NSTAGE - 1; s++) issue(s);

    for (int c = 0; c < nch; c++) {
        asm volatile("cp.async.wait_group %0;" :: "n"(NSTAGE - 2) : "memory");
        __syncthreads();
        if (c + NSTAGE - 1 < nch) issue(c + NSTAGE - 1);

        const int buf = c & (NSTAGE - 1);
        const float* Ab = sA_f + buf * A_STG;
        const float* Bb = sB_f + buf * (BT ? BT_STG : BN_STG);
        #pragma unroll
        for (int ks = 0; ks < 16; ks += 8) {
            uint32_t af[4][4], bf8[8][2];
            #pragma unroll
            for (int mi = 0; mi < 4; mi++) {
                int r0 = wm0 + mi * 16;
                af[mi][0] = __float_as_uint(Ab[(r0 + grp    ) * A_ROW + ks + qid    ]);
                af[mi][1] = __float_as_uint(Ab[(r0 + grp + 8) * A_ROW + ks + qid    ]);
                af[mi][2] = __float_as_uint(Ab[(r0 + grp    ) * A_ROW + ks + qid + 4]);
                af[mi][3] = __float_as_uint(Ab[(r0 + grp + 8) * A_ROW + ks + qid + 4]);
            }
            #pragma unroll
            for (int ni = 0; ni < 8; ni++) {
                int n0 = wn0 + ni * 8;
                if (BT) {
                    bf8[ni][0] = __float_as_uint(Bb[(n0 + grp) * A_ROW + ks + qid    ]);
                    bf8[ni][1] = __float_as_uint(Bb[(n0 + grp) * A_ROW + ks + qid + 4]);
                } else {
                    bf8[ni][0] = __float_as_uint(Bb[(ks + qid    ) * BN_ROW + n0 + grp]);
                    bf8[ni][1] = __float_as_uint(Bb[(ks + qid + 4) * BN_ROW + n0 + grp]);
                }
            }
            #pragma unroll
            for (int mi = 0; mi < 4; mi++)
                #pragma unroll
                for (int ni = 0; ni < 8; ni++)
                    mma8(acc[mi][ni], af[mi], bf8[ni]);
        }
    }

    // ---- epilogue ----
    #pragma unroll
    for (int mi = 0; mi < 4; mi++) {
        const int rA = row0 + wm0 + mi * 16 + grp;
        const int rB = rA + 8;
        #pragma unroll
        for (int ni = 0; ni < 8; ni++) {
            const int c = col0 + wn0 + ni * 8 + (qid << 1);
            if (c >= Nc) continue;
            float2 lo = make_float2(acc[mi][ni][0], acc[mi][ni][1]);
            float2 hi = make_float2(acc[mi][ni][2], acc[mi][ni][3]);
            if (EPI == 0) {
                *(float2*)(C + (size_t)rA * ldc + c) = lo;
                *(float2*)(C + (size_t)rB * ldc + c) = hi;
            } else if (EPI == 1) {
                // x_sparse: fp32 relu (elementwise consumer needs full precision)
                lo.x = fmaxf(lo.x, 0.f); lo.y = fmaxf(lo.y, 0.f);
                hi.x = fmaxf(hi.x, 0.f); hi.y = fmaxf(hi.y, 0.f);
                *(float2*)(C + (size_t)rA * ldc + c) = lo;
                *(float2*)(C + (size_t)rB * ldc + c) = hi;
                // rope computed in fp32, rounded ONCE at store (GEMM operand)
                float2 ca = rtab[(size_t)rA * (NN / 2) + (c >> 1)];
                float2 cb = rtab[(size_t)rB * (NN / 2) + (c >> 1)];
                float2 qa, qb;
                qa.x = tf32f(lo.x * ca.x - lo.y * ca.y);
                qa.y = tf32f(lo.y * ca.x + lo.x * ca.y);
                qb.x = tf32f(hi.x * cb.x - hi.y * cb.y);
                qb.y = tf32f(hi.y * cb.x + hi.x * cb.y);
                *(float2*)(qout + (size_t)rA * ldc + c) = qa;
                *(float2*)(qout + (size_t)rB * ldc + c) = qb;
            } else if (EPI == 2) {
                // xy: fp32 relu * fp32 xs, rounded ONCE at store (GEMM operand)
                float2 ea = *(const float2*)(auxr + (size_t)rA * ldc + c);
                float2 eb = *(const float2*)(auxr + (size_t)rB * ldc + c);
                lo.x = tf32f(fmaxf(lo.x, 0.f) * ea.x); lo.y = tf32f(fmaxf(lo.y, 0.f) * ea.y);
                hi.x = tf32f(fmaxf(hi.x, 0.f) * eb.x); hi.y = tf32f(fmaxf(hi.y, 0.f) * eb.y);
                *(float2*)(C + (size_t)rA * ldc + c) = lo;
                *(float2*)(C + (size_t)rB * ldc + c) = hi;
            } else { // EPI == 3: scores, rounded ONCE at store (GEMM operand)
                float2 oa, ob;
                oa.x = (c     < rA) ? tf32f(lo.x) : 0.f;
                oa.y = (c + 1 < rA) ? tf32f(lo.y) : 0.f;
                ob.x = (c     < rB) ? tf32f(hi.x) : 0.f;
                ob.y = (c + 1 < rB) ? tf32f(hi.y) : 0.f;
                *(float2*)(C + (size_t)rA * ldc + c) = oa;
                *(float2*)(C + (size_t)rB * ldc + c) = ob;
            }
        }
    }
}

// ---------------------------------------------------------------------------
// elementwise tf32 rounding pass (weights, once per launch)
// ---------------------------------------------------------------------------
__global__ void round_k(const float* __restrict__ in, float* __restrict__ out, int n)
{
    int i = blockIdx.x * blockDim.x + threadIdx.x;
    if (i < n) out[i] = tf32f(in[i]);
}

// ---------------------------------------------------------------------------
// LayerNorm helpers (192-wide rows, 6 warps)
// ---------------------------------------------------------------------------
__device__ __forceinline__ float2 meanvar192(float v, float* s1, float* s2)
{
    __syncthreads();
    float a = v, b = v * v;
    #pragma unroll
    for (int o = 16; o > 0; o >>= 1) {
        a += __shfl_down_sync(0xffffffffu, a, o);
        b += __shfl_down_sync(0xffffffffu, b, o);
    }
    int lane = threadIdx.x & 31, w = threadIdx.x >> 5;
    if (lane == 0) { s1[w] = a; s2[w] = b; }
    __syncthreads();
    if (threadIdx.x == 0) {
        float sa = 0.f, sb = 0.f;
        #pragma unroll
        for (int i = 0; i < 6; i++) { sa += s1[i]; sb += s2[i]; }
        s1[0] = sa; s2[0] = sb;
    }
    __syncthreads();
    float m   = s1[0] * (1.0f / 192.0f);
    float var = s2[0] * (1.0f / 192.0f) - m * m;
    return make_float2(m, fmaxf(var, 0.f));
}

__global__ void embed_ln_k(const int* __restrict__ idx,
                           const float* __restrict__ emb,
                           const float* __restrict__ pos)
{
    int t = blockIdx.x, d = threadIdx.x;
    __shared__ float s1[8], s2[8];
    float v = emb[(size_t)idx[t] * DD + d] + pos[(size_t)t * DD + d];
    float2 mv = meanvar192(v, s1, s2);
    float r = (v - mv.x) * rsqrtf(mv.y + 1e-5f);
    g_x [(size_t)t * DD + d] = r;          // fp32 chain
    g_xr[(size_t)t * DD + d] = tf32f(r);   // GEMM copy (single rounding)
}

__global__ void sincos_k()
{
    int i = blockIdx.x * blockDim.x + threadIdx.x;
    if (i >= TT * (NN / 2)) return;
    int t = i / (NN / 2);
    int p = i - t * (NN / 2);
    float f = exp2f(-(float)p * (1.0f / 96.0f)) * 0.15915494309189535f;
    float ph = fmodf((float)t * f, 1.0f) * 6.283185307179586f;
    float s, c;
    sincosf(ph, &s, &c);
    g_rt[i] = make_float2(c, s);
}

__global__ void ln_ykv_k()
{
    int r = blockIdx.x, d = threadIdx.x;
    __shared__ float s1[8], s2[8];
    float v = g_ykv[(size_t)r * DD + d];
    float2 mv = meanvar192(v, s1, s2);
    // ykv only feeds a GEMM -> single rounding at store
    g_ykv[(size_t)r * DD + d] = tf32f((v - mv.x) * rsqrtf(mv.y + 1e-5f));
}

__global__ void finalize_k()
{
    int t = blockIdx.x, d = threadIdx.x;
    __shared__ float s1[8], s2[8];
    float ym = 0.f;
    #pragma unroll
    for (int c = 0; c < KSPLIT; c++)
        ym += g_part[(size_t)c * TT * DD + (size_t)t * DD + d];
    float2 mv = meanvar192(ym, s1, s2);
    float l1 = (ym - mv.x) * rsqrtf(mv.y + 1e-5f);
    float xv = g_x[(size_t)t * DD + d] + l1;   // fp32 residual
    float2 mv2 = meanvar192(xv, s1, s2);
    float r = (xv - mv2.x) * rsqrtf(mv2.y + 1e-5f);
    g_x [(size_t)t * DD + d] = r;
    g_xr[(size_t)t * DD + d] = tf32f(r);
}

// ---------------------------------------------------------------------------
extern "C" void kernel_launch(void* const* d_in, const int* in_sizes, int n_in,
                              void* d_out, int out_size)
{
    const int*   idx  = (const int*)  d_in[0];
    const float* decx = (const float*)d_in[1];   // (NH, D, N)
    const float* decy = (const float*)d_in[2];   // (NH, D, N)
    const float* enc  = (const float*)d_in[3];   // (NH*N, D)
    const float* emb  = (const float*)d_in[4];   // (VOCAB, D)
    const float* pos  = (const float*)d_in[5];   // (BLOCK, D)
    const float* lmh  = (const float*)d_in[6];   // (D, VOCAB)
    float* out = (float*)d_out;

    float *pxr, *pxs, *pqr, *psc, *pykv, *ppart, *pwdx, *pwdy, *pwenc, *pwlmh;
    float2* prt;
    cudaGetSymbolAddress((void**)&pxr,   g_xr);
    cudaGetSymbolAddress((void**)&pxs,   g_xs);
    cudaGetSymbolAddress((void**)&pqr,   g_qr);
    cudaGetSymbolAddress((void**)&psc,   g_sc);
    cudaGetSymbolAddress((void**)&pykv,  g_ykv);
    cudaGetSymbolAddress((void**)&ppart, g_part);
    cudaGetSymbolAddress((void**)&prt,   g_rt);
    cudaGetSymbolAddress((void**)&pwdx,  g_wdx);
    cudaGetSymbolAddress((void**)&pwdy,  g_wdy);
    cudaGetSymbolAddress((void**)&pwenc, g_wenc);
    cudaGetSymbolAddress((void**)&pwlmh, g_wlmh);

    const int SM_BT  = NSTAGE * (A_STG + BT_STG) * 4;   // 81920 B
    const int SM_NBT = NSTAGE * (A_STG + BN_STG) * 4;   // 75776 B
    cudaFuncSetAttribute(gemm_mma<1,0,0>, cudaFuncAttributeMaxDynamicSharedMemorySize, SM_NBT);
    cudaFuncSetAttribute(gemm_mma<3,1,0>, cudaFuncAttributeMaxDynamicSharedMemorySize, SM_BT);
    cudaFuncSetAttribute(gemm_mma<0,0,0>, cudaFuncAttributeMaxDynamicSharedMemorySize, SM_NBT);
    cudaFuncSetAttribute(gemm_mma<2,0,0>, cudaFuncAttributeMaxDynamicSharedMemorySize, SM_NBT);
    cudaFuncSetAttribute(gemm_mma<0,0,1>, cudaFuncAttributeMaxDynamicSharedMemorySize, SM_NBT);

    // weight pre-rounding (once per launch; single rounding == round-at-load)
    round_k<<<(NHH*DD*NN + 255) / 256, 256>>>(decx, pwdx, NHH*DD*NN);
    round_k<<<(NHH*DD*NN + 255) / 256, 256>>>(decy, pwdy, NHH*DD*NN);
    round_k<<<(NHH*NN*DD + 255) / 256, 256>>>(enc,  pwenc, NHH*NN*DD);
    round_k<<<(DD*VV + 255) / 256, 256>>>(lmh, pwlmh, DD*VV);

    sincos_k<<<(TT * (NN / 2) + 255) / 256, 256>>>();
    embed_ln_k<<<TT, 192>>>(idx, emb, pos);

    for (int l = 0; l < NLAYER; l++) {
        // x_sparse(fp32) = relu(x @ decx[h]);  qr(tf32) = rope(x_sparse)
        gemm_mma<1, 0, 0><<<dim3(NN / 128, TT / 128, NHH), 128, SM_NBT>>>(
            pxr, pwdx, pxs, pqr, prt, NN, DD, DD, NN, NN,
            0LL, (long long)DD * NN, (long long)TT * NN, (long long)TT * NN);

        // scores(tf32) = (qr @ qr^T) * tril(-1)
        gemm_mma<3, 1, 0><<<dim3(TT / 128, TT / 128, NHH), 128, SM_BT>>>(
            pqr, pqr, psc, nullptr, nullptr, TT, NN, NN, NN, TT,
            (long long)TT * NN, (long long)TT * NN, (long long)TT * TT, 0LL);

        // ykv_raw(fp32) = scores @ x
        gemm_mma<0, 0, 0><<<dim3((DD + 127) / 128, TT / 128, NHH), 128, SM_NBT>>>(
            psc, pxr, pykv, nullptr, nullptr, DD, TT, TT, DD, DD,
            (long long)TT * TT, 0LL, (long long)TT * DD, 0LL);

        // ykv = ln(ykv_raw) -> tf32
        ln_ykv_k<<<NHH * TT, 192>>>();

        // xy(tf32) = relu(ykv @ decy[h]) * x_sparse(fp32)   -> g_qr (reuse)
        gemm_mma<2, 0, 0><<<dim3(NN / 128, TT / 128, NHH), 128, SM_NBT>>>(
            pykv, pwdy, pqr, pxs, nullptr, NN, DD, DD, NN, NN,
            (long long)TT * DD, (long long)DD * NN, (long long)TT * NN,
            (long long)TT * NN);

        // ymlp partials(fp32): xy[1024,12288] @ enc[12288,192], split-K = 16
        gemm_mma<0, 0, 1><<<dim3((DD + 127) / 128, TT / 128, KSPLIT), 128, SM_NBT>>>(
            pqr, pwenc, ppart, nullptr, nullptr, DD, KCH, NN, DD, DD,
            0LL, (long long)KCH * DD, (long long)TT * DD, 0LL);

        // x = ln(x + ln(sum partials))  (fp32 chain + tf32 GEMM copy)
        finalize_k<<<TT, 192>>>();
    }

    // logits(fp32) = x @ lm_head
    gemm_mma<0, 0, 0><<<dim3(VV / 128, TT / 128, 1), 128, SM_NBT>>>(
        pxr, pwlmh, out, nullptr, nullptr, VV, DD, DD, VV, VV,
        0LL, 0LL, 0LL, 0LL);
}

// round 7
// speedup vs baseline: 3.2932x; 1.1114x over previous
#include <cuda_runtime.h>
#include <math.h>
#include <stdint.h>

// Problem constants
#define TT 1024
#define DD 192
#define NHH 4
#define NN 3072
#define VV 256
#define NLAYER 4
#define KSPLIT 16
#define KCH ((NHH*NN)/KSPLIT)   // 768
#define NSTAGE 4

// ---------------------------------------------------------------------------
// Static device scratch (no allocation allowed) -- 16B aligned for cp.async
// ---------------------------------------------------------------------------
__device__ __align__(16) float  g_x[TT*DD];        // fp32 residual chain
__device__ __align__(16) float  g_xr[TT*DD];       // tf32-rounded copy (GEMM A)
__device__ __align__(16) float  g_xT[DD*TT];       // xr^T (GEMM B for ykv)
__device__ __align__(16) float  g_xs[NHH*TT*NN];   // fp32 (elementwise use only)
__device__ __align__(16) float  g_qr[NHH*TT*NN];   // tf32; later reused as xy (tf32)
__device__ __align__(16) float  g_sc[NHH*TT*TT];   // tf32
__device__ __align__(16) float  g_ykv[NHH*TT*DD];  // fp32 raw -> tf32 after ln
__device__ __align__(16) float  g_part[KSPLIT*TT*DD];
__device__ __align__(16) float2 g_rt[TT*(NN/2)];   // rope (cos,sin)
// tf32-prerounded, transposed weights ([N][K] row-major, K contiguous)
__device__ __align__(16) float  g_wdxT[NHH*NN*DD]; // decx^T per head [n][d]
__device__ __align__(16) float  g_wdyT[NHH*NN*DD];
__device__ __align__(16) float  g_encT[DD*NHH*NN]; // enc^T [d][h*n]
__device__ __align__(16) float  g_lmhT[VV*DD];     // lm_head^T [v][d]

__device__ __forceinline__ uint32_t tf32r(float x) {
    uint32_t y;
    asm("cvt.rna.tf32.f32 %0, %1;" : "=r"(y) : "f"(x));
    return y;
}
__device__ __forceinline__ float tf32f(float x) { return __uint_as_float(tf32r(x)); }
__device__ __forceinline__ uint32_t su32(const void* p) {
    uint32_t a;
    asm("{ .reg .u64 t; cvta.to.shared.u64 t, %1; cvt.u32.u64 %0, t; }"
        : "=r"(a) : "l"(p));
    return a;
}
__device__ __forceinline__ void cp16(uint32_t dst, const void* src, bool full) {
    int sz = full ? 16 : 0;
    asm volatile("cp.async.cg.shared.global [%0], [%1], 16, %2;"
                 :: "r"(dst), "l"(src), "r"(sz) : "memory");
}
__device__ __forceinline__ void mma8(float c[4], const uint32_t a[4], const uint32_t b[2]) {
    asm volatile(
        "mma.sync.aligned.m16n8k8.row.col.f32.tf32.tf32.f32 "
        "{%0,%1,%2,%3}, {%4,%5,%6,%7}, {%8,%9}, {%0,%1,%2,%3};"
        : "+f"(c[0]), "+f"(c[1]), "+f"(c[2]), "+f"(c[3])
        : "r"(a[0]), "r"(a[1]), "r"(a[2]), "r"(a[3]), "r"(b[0]), "r"(b[1]));
}
__device__ __forceinline__ void ldsm4(uint32_t d[4], uint32_t addr) {
    asm volatile("ldmatrix.sync.aligned.m8n8.x4.shared.b16 {%0,%1,%2,%3}, [%4];"
                 : "=r"(d[0]), "=r"(d[1]), "=r"(d[2]), "=r"(d[3]) : "r"(addr));
}

// ---------------------------------------------------------------------------
// tf32 warp-MMA GEMM, cp.async 4-stage pipeline, ldmatrix fragment loads.
// C[M,Nc] = epi(A[M,K] @ B[Nc,K]^T)  -- both operands [rows][K] row-major.
// CTA tile 128x128, BK=16, 256 threads (8 warps, 4m x 2n), warp tile 32x64.
// All A/B inputs must be tf32-prerounded (no cvt in mainloop).
// EPI: 0 plain fp32 | 1 relu->fp32 C (+fused rope, single-round -> aux tf32) |
//      2 relu*aux (fp32 math, single-round tf32) | 3 strict tril (single-round tf32)
// AZM: 1 -> A is xy [h][t][n], split-K chunk KCH selected by blockIdx.z
// smem rows: 20 floats (80B) stride -> conflict-free ldmatrix phases
// ---------------------------------------------------------------------------
#define A_ROW 20
#define A_STG (128*A_ROW)
#define B_STG (128*A_ROW)

template<int EPI, int AZM>
__global__ __launch_bounds__(256, 2)
void gemm_mma(const float* __restrict__ A, const float* __restrict__ B,
              float* __restrict__ C, const float* __restrict__ aux,
              const float2* __restrict__ rtab,
              int Nc, int K, int lda, int ldb, int ldc,
              long long sA, long long sB, long long sC, long long sAux)
{
    extern __shared__ float smf[];
    float* sA_f = smf;
    float* sB_f = smf + NSTAGE * A_STG;

    const int bx = blockIdx.x, by = blockIdx.y, bz = blockIdx.z;
    const int tid = threadIdx.x;
    const int wid = tid >> 5, lane = tid & 31;
    const int grp = lane >> 2, qid = lane & 3;
    const int wm0 = (wid & 3) * 32, wn0 = (wid >> 2) * 64;
    const int row0 = by * 128, col0 = bx * 128;

    int koff = 0;
    if (AZM == 1) koff = bz * KCH;
    else          A += (long long)bz * sA;
    B += (long long)bz * sB;
    C += (long long)bz * sC;
    const float* auxr = aux ? aux + (long long)bz * sAux : aux;
    float*       qout = (float*)auxr;

    // fully-masked tile above diagonal: zero-fill, exit
    if (EPI == 3 && bx > by) {
        #pragma unroll 4
        for (int i = tid; i < 128 * 32; i += 256) {
            int r = i >> 5, c4 = (i & 31) << 2;
            *(float4*)(C + (size_t)(row0 + r) * ldc + col0 + c4) = make_float4(0, 0, 0, 0);
        }
        return;
    }

    const uint32_t sA_u = su32(sA_f);
    const uint32_t sB_u = su32(sB_f);

    // ldmatrix per-lane base addresses (A: a0..a3 tile map; B: b0/b1 pair map)
    const int rowA = (lane & 7) + ((lane >> 3) & 1) * 8;
    const int kA   = ((lane >> 4) & 1) * 4;
    const int rowB = (lane & 7) + ((lane >> 4) & 1) * 8;
    const int kB   = ((lane >> 3) & 1) * 4;
    const uint32_t aBase = sA_u + 4u * ((wm0 + rowA) * A_ROW + kA);
    const uint32_t bBase = sB_u + 4u * ((wn0 + rowB) * A_ROW + kB);

    float acc[2][8][4];
    #pragma unroll
    for (int mi = 0; mi < 2; mi++)
        #pragma unroll
        for (int ni = 0; ni < 8; ni++)
            #pragma unroll
            for (int j = 0; j < 4; j++) acc[mi][ni][j] = 0.f;

    const int nch = K / 16;

    auto issue = [&](int s) {
        const int k0 = s * 16;
        const int buf = s & (NSTAGE - 1);
        #pragma unroll
        for (int it = 0; it < 2; it++) {
            int idx4 = tid + it * 256;
            int r = idx4 >> 2, kc = (idx4 & 3) << 2;
            const float* src;
            if (AZM == 1) {
                int gk = koff + k0 + kc;
                int hh = gk / NN, nn = gk - hh * NN;
                src = A + (size_t)hh * TT * NN + (size_t)(row0 + r) * lda + nn;
            } else {
                src = A + (size_t)(row0 + r) * lda + k0 + kc;
            }
            cp16(sA_u + (buf * A_STG + r * A_ROW + kc) * 4, src, true);
        }
        #pragma unroll
        for (int it = 0; it < 2; it++) {
            int idx4 = tid + it * 256;
            int nr = idx4 >> 2, kc = (idx4 & 3) << 2;
            const float* src = B + (size_t)(col0 + nr) * ldb + k0 + kc;
            cp16(sB_u + (buf * B_STG + nr * A_ROW + kc) * 4, src, col0 + nr < Nc);
        }
        asm volatile("cp.async.commit_group;" ::: "memory");
    };

    #pragma unroll
    for (int s = 0; s < NSTAGE - 1; s++) issue(s);

    for (int c = 0; c < nch; c++) {
        asm volatile("cp.async.wait_group %0;" :: "n"(NSTAGE - 2) : "memory");
        __syncthreads();
        if (c + NSTAGE - 1 < nch) issue(c + NSTAGE - 1);

        const int buf = c & (NSTAGE - 1);
        const uint32_t aOff = aBase + 4u * buf * A_STG;
        const uint32_t bOff = bBase + 4u * buf * B_STG;
        #pragma unroll
        for (int ks = 0; ks < 16; ks += 8) {
            uint32_t af[2][4], bf8[8][2];
            #pragma unroll
            for (int mi = 0; mi < 2; mi++)
                ldsm4(af[mi], aOff + 4u * (mi * 16 * A_ROW + ks));
            #pragma unroll
            for (int p = 0; p < 4; p++) {
                uint32_t t4[4];
                ldsm4(t4, bOff + 4u * (p * 16 * A_ROW + ks));
                bf8[2 * p    ][0] = t4[0]; bf8[2 * p    ][1] = t4[1];
                bf8[2 * p + 1][0] = t4[2]; bf8[2 * p + 1][1] = t4[3];
            }
            #pragma unroll
            for (int mi = 0; mi < 2; mi++)
                #pragma unroll
                for (int ni = 0; ni < 8; ni++)
                    mma8(acc[mi][ni], af[mi], bf8[ni]);
        }
    }

    // ---- epilogue ----
    #pragma unroll
    for (int mi = 0; mi < 2; mi++) {
        const int rA = row0 + wm0 + mi * 16 + grp;
        const int rB = rA + 8;
        #pragma unroll
        for (int ni = 0; ni < 8; ni++) {
            const int c = col0 + wn0 + ni * 8 + (qid << 1);
            if (c >= Nc) continue;
            float2 lo = make_float2(acc[mi][ni][0], acc[mi][ni][1]);
            float2 hi = make_float2(acc[mi][ni][2], acc[mi][ni][3]);
            if (EPI == 0) {
                *(float2*)(C + (size_t)rA * ldc + c) = lo;
                *(float2*)(C + (size_t)rB * ldc + c) = hi;
            } else if (EPI == 1) {
                lo.x = fmaxf(lo.x, 0.f); lo.y = fmaxf(lo.y, 0.f);
                hi.x = fmaxf(hi.x, 0.f); hi.y = fmaxf(hi.y, 0.f);
                *(float2*)(C + (size_t)rA * ldc + c) = lo;
                *(float2*)(C + (size_t)rB * ldc + c) = hi;
                float2 ca = rtab[(size_t)rA * (NN / 2) + (c >> 1)];
                float2 cb = rtab[(size_t)rB * (NN / 2) + (c >> 1)];
                float2 qa, qb;
                qa.x = tf32f(lo.x * ca.x - lo.y * ca.y);
                qa.y = tf32f(lo.y * ca.x + lo.x * ca.y);
                qb.x = tf32f(hi.x * cb.x - hi.y * cb.y);
                qb.y = tf32f(hi.y * cb.x + hi.x * cb.y);
                *(float2*)(qout + (size_t)rA * ldc + c) = qa;
                *(float2*)(qout + (size_t)rB * ldc + c) = qb;
            } else if (EPI == 2) {
                float2 ea = *(const float2*)(auxr + (size_t)rA * ldc + c);
                float2 eb = *(const float2*)(auxr + (size_t)rB * ldc + c);
                lo.x = tf32f(fmaxf(lo.x, 0.f) * ea.x); lo.y = tf32f(fmaxf(lo.y, 0.f) * ea.y);
                hi.x = tf32f(fmaxf(hi.x, 0.f) * eb.x); hi.y = tf32f(fmaxf(hi.y, 0.f) * eb.y);
                *(float2*)(C + (size_t)rA * ldc + c) = lo;
                *(float2*)(C + (size_t)rB * ldc + c) = hi;
            } else { // EPI == 3
                float2 oa, ob;
                oa.x = (c     < rA) ? tf32f(lo.x) : 0.f;
                oa.y = (c + 1 < rA) ? tf32f(lo.y) : 0.f;
                ob.x = (c     < rB) ? tf32f(hi.x) : 0.f;
                ob.y = (c + 1 < rB) ? tf32f(hi.y) : 0.f;
                *(float2*)(C + (size_t)rA * ldc + c) = oa;
                *(float2*)(C + (size_t)rB * ldc + c) = ob;
            }
        }
    }
}

// ---------------------------------------------------------------------------
// Transpose + tf32-round: out[Nn][M] = tf32(in[M][Nn]^T); batched via z
// ---------------------------------------------------------------------------
__global__ void transpose_round_k(const float* __restrict__ in, float* __restrict__ out,
                                  int M, int Nn, long long inS, long long outS)
{
    __shared__ float t[32][33];
    in  += (long long)blockIdx.z * inS;
    out += (long long)blockIdx.z * outS;
    int x = blockIdx.x * 32 + threadIdx.x;
    int y = blockIdx.y * 32 + threadIdx.y;
    #pragma unroll
    for (int i = 0; i < 32; i += 8)
        t[threadIdx.y + i][threadIdx.x] = in[(size_t)(y + i) * Nn + x];
    __syncthreads();
    int x2 = blockIdx.y * 32 + threadIdx.x;
    int y2 = blockIdx.x * 32 + threadIdx.y;
    #pragma unroll
    for (int i = 0; i < 32; i += 8)
        out[(size_t)(y2 + i) * M + x2] = tf32f(t[threadIdx.x][threadIdx.y + i]);
}

// ---------------------------------------------------------------------------
// LayerNorm helpers (192-wide rows, 6 warps)
// ---------------------------------------------------------------------------
__device__ __forceinline__ float2 meanvar192(float v, float* s1, float* s2)
{
    __syncthreads();
    float a = v, b = v * v;
    #pragma unroll
    for (int o = 16; o > 0; o >>= 1) {
        a += __shfl_down_sync(0xffffffffu, a, o);
        b += __shfl_down_sync(0xffffffffu, b, o);
    }
    int lane = threadIdx.x & 31, w = threadIdx.x >> 5;
    if (lane == 0) { s1[w] = a; s2[w] = b; }
    __syncthreads();
    if (threadIdx.x == 0) {
        float sa = 0.f, sb = 0.f;
        #pragma unroll
        for (int i = 0; i < 6; i++) { sa += s1[i]; sb += s2[i]; }
        s1[0] = sa; s2[0] = sb;
    }
    __syncthreads();
    float m   = s1[0] * (1.0f / 192.0f);
    float var = s2[0] * (1.0f / 192.0f) - m * m;
    return make_float2(m, fmaxf(var, 0.f));
}

__global__ void embed_ln_k(const int* __restrict__ idx,
                           const float* __restrict__ emb,
                           const float* __restrict__ pos)
{
    int t = blockIdx.x, d = threadIdx.x;
    __shared__ float s1[8], s2[8];
    float v = emb[(size_t)idx[t] * DD + d] + pos[(size_t)t * DD + d];
    float2 mv = meanvar192(v, s1, s2);
    float r = (v - mv.x) * rsqrtf(mv.y + 1e-5f);
    g_x [(size_t)t * DD + d] = r;
    g_xr[(size_t)t * DD + d] = tf32f(r);
}

__global__ void sincos_k()
{
    int i = blockIdx.x * blockDim.x + threadIdx.x;
    if (i >= TT * (NN / 2)) return;
    int t = i / (NN / 2);
    int p = i - t * (NN / 2);
    float f = exp2f(-(float)p * (1.0f / 96.0f)) * 0.15915494309189535f;
    float ph = fmodf((float)t * f, 1.0f) * 6.283185307179586f;
    float s, c;
    sincosf(ph, &s, &c);
    g_rt[i] = make_float2(c, s);
}

__global__ void ln_ykv_k()
{
    int r = blockIdx.x, d = threadIdx.x;
    __shared__ float s1[8], s2[8];
    float v = g_ykv[(size_t)r * DD + d];
    float2 mv = meanvar192(v, s1, s2);
    g_ykv[(size_t)r * DD + d] = tf32f((v - mv.x) * rsqrtf(mv.y + 1e-5f));
}

__global__ void finalize_k()
{
    int t = blockIdx.x, d = threadIdx.x;
    __shared__ float s1[8], s2[8];
    float ym = 0.f;
    #pragma unroll
    for (int c = 0; c < KSPLIT; c++)
        ym += g_part[(size_t)c * TT * DD + (size_t)t * DD + d];
    float2 mv = meanvar192(ym, s1, s2);
    float l1 = (ym - mv.x) * rsqrtf(mv.y + 1e-5f);
    float xv = g_x[(size_t)t * DD + d] + l1;
    float2 mv2 = meanvar192(xv, s1, s2);
    float r = (xv - mv2.x) * rsqrtf(mv2.y + 1e-5f);
    g_x [(size_t)t * DD + d] = r;
    g_xr[(size_t)t * DD + d] = tf32f(r);
}

// ---------------------------------------------------------------------------
extern "C" void kernel_launch(void* const* d_in, const int* in_sizes, int n_in,
                              void* d_out, int out_size)
{
    const int*   idx  = (const int*)  d_in[0];
    const float* decx = (const float*)d_in[1];   // (NH, D, N)
    const float* decy = (const float*)d_in[2];   // (NH, D, N)
    const float* enc  = (const float*)d_in[3];   // (NH*N, D)
    const float* emb  = (const float*)d_in[4];   // (VOCAB, D)
    const float* pos  = (const float*)d_in[5];   // (BLOCK, D)
    const float* lmh  = (const float*)d_in[6];   // (D, VOCAB)
    float* out = (float*)d_out;

    float *pxr, *pxT, *pxs, *pqr, *psc, *pykv, *ppart, *pwdxT, *pwdyT, *pencT, *plmhT;
    float2* prt;
    cudaGetSymbolAddress((void**)&pxr,   g_xr);
    cudaGetSymbolAddress((void**)&pxT,   g_xT);
    cudaGetSymbolAddress((void**)&pxs,   g_xs);
    cudaGetSymbolAddress((void**)&pqr,   g_qr);
    cudaGetSymbolAddress((void**)&psc,   g_sc);
    cudaGetSymbolAddress((void**)&pykv,  g_ykv);
    cudaGetSymbolAddress((void**)&ppart, g_part);
    cudaGetSymbolAddress((void**)&prt,   g_rt);
    cudaGetSymbolAddress((void**)&pwdxT, g_wdxT);
    cudaGetSymbolAddress((void**)&pwdyT, g_wdyT);
    cudaGetSymbolAddress((void**)&pencT, g_encT);
    cudaGetSymbolAddress((void**)&plmhT, g_lmhT);

    const int SMEMB = NSTAGE * (A_STG + B_STG) * 4;   // 81920 B
    cudaFuncSetAttribute(gemm_mma<1,0>, cudaFuncAttributeMaxDynamicSharedMemorySize, SMEMB);
    cudaFuncSetAttribute(gemm_mma<3,0>, cudaFuncAttributeMaxDynamicSharedMemorySize, SMEMB);
    cudaFuncSetAttribute(gemm_mma<0,0>, cudaFuncAttributeMaxDynamicSharedMemorySize, SMEMB);
    cudaFuncSetAttribute(gemm_mma<2,0>, cudaFuncAttributeMaxDynamicSharedMemorySize, SMEMB);
    cudaFuncSetAttribute(gemm_mma<0,1>, cudaFuncAttributeMaxDynamicSharedMemorySize, SMEMB);

    dim3 tb(32, 8);
    // one-time prep: transposed + tf32-rounded weights
    transpose_round_k<<<dim3(NN/32, DD/32, NHH), tb>>>(decx, pwdxT, DD, NN,
                                                       (long long)DD*NN, (long long)NN*DD);
    transpose_round_k<<<dim3(NN/32, DD/32, NHH), tb>>>(decy, pwdyT, DD, NN,
                                                       (long long)DD*NN, (long long)NN*DD);
    transpose_round_k<<<dim3(DD/32, (NHH*NN)/32, 1), tb>>>(enc, pencT, NHH*NN, DD, 0, 0);
    transpose_round_k<<<dim3(VV/32, DD/32, 1), tb>>>(lmh, plmhT, DD, VV, 0, 0);

    sincos_k<<<(TT * (NN / 2) + 255) / 256, 256>>>();
    embed_ln_k<<<TT, 192>>>(idx, emb, pos);

    for (int l = 0; l < NLAYER; l++) {
        // x^T (tf32 values, exact copy) for ykv GEMM B operand
        transpose_round_k<<<dim3(DD/32, TT/32, 1), tb>>>(pxr, pxT, TT, DD, 0, 0);

        // x_sparse(fp32) = relu(x @ decx[h]);  qr(tf32) = rope(x_sparse)
        gemm_mma<1, 0><<<dim3(NN / 128, TT / 128, NHH), 256, SMEMB>>>(
            pxr, pwdxT, pxs, pqr, prt, NN, DD, DD, DD, NN,
            0LL, (long long)NN * DD, (long long)TT * NN, (long long)TT * NN);

        // scores(tf32) = (qr @ qr^T) * tril(-1)
        gemm_mma<3, 0><<<dim3(TT / 128, TT / 128, NHH), 256, SMEMB>>>(
            pqr, pqr, psc, nullptr, nullptr, TT, NN, NN, NN, TT,
            (long long)TT * NN, (long long)TT * NN, (long long)TT * TT, 0LL);

        // ykv_raw(fp32) = scores @ x   (B = x^T [d][t])
        gemm_mma<0, 0><<<dim3((DD + 127) / 128, TT / 128, NHH), 256, SMEMB>>>(
            psc, pxT, pykv, nullptr, nullptr, DD, TT, TT, TT, DD,
            (long long)TT * TT, 0LL, (long long)TT * DD, 0LL);

        // ykv = ln(ykv_raw) -> tf32
        ln_ykv_k<<<NHH * TT, 192>>>();

        // xy(tf32) = relu(ykv @ decy[h]) * x_sparse(fp32)   -> g_qr (reuse)
        gemm_mma<2, 0><<<dim3(NN / 128, TT / 128, NHH), 256, SMEMB>>>(
            pykv, pwdyT, pqr, pxs, nullptr, NN, DD, DD, DD, NN,
            (long long)TT * DD, (long long)NN * DD, (long long)TT * NN,
            (long long)TT * NN);

        // ymlp partials(fp32): xy[1024,12288] @ enc[12288,192], split-K = 16
        // B = enc^T [d][h*n], per-z K offset = bz*KCH (row-internal shift)
        gemm_mma<0, 1><<<dim3((DD + 127) / 128, TT / 128, KSPLIT), 256, SMEMB>>>(
            pqr, pencT, ppart, nullptr, nullptr, DD, KCH, NN, NHH * NN, DD,
            0LL, (long long)KCH, (long long)TT * DD, 0LL);

        // x = ln(x + ln(sum partials))
        finalize_k<<<TT, 192>>>();
    }

    // logits(fp32) = x @ lm_head  (B = lmh^T [v][d])
    gemm_mma<0, 0><<<dim3((VV + 127) / 128, TT / 128, 1), 256, SMEMB>>>(
        pxr, plmhT, out, nullptr, nullptr, VV, DD, DD, DD, VV,
        0LL, 0LL, 0LL, 0LL);
}

// round 8
// speedup vs baseline: 3.8261x; 1.1618x over previous
#include <cuda_runtime.h>
#include <math.h>
#include <stdint.h>

// Problem constants
#define TT 1024
#define DD 192
#define NHH 4
#define NN 3072
#define VV 256
#define NLAYER 4
#define KSPLIT 16
#define KCH ((NHH*NN)/KSPLIT)   // 768
#define NSTAGE 3
#define BK 32
#define SROW 36                  // floats per smem row (32 + 4 pad)
#define STG_F (128*SROW)         // floats per stage per operand

// ---------------------------------------------------------------------------
// Static device scratch (no allocation allowed) -- 16B aligned for cp.async
// ---------------------------------------------------------------------------
__device__ __align__(16) float  g_x[TT*DD];        // fp32 residual chain
__device__ __align__(16) float  g_xr[TT*DD];       // tf32-rounded copy (GEMM A)
__device__ __align__(16) float  g_xT[DD*TT];       // xr^T (GEMM B for ykv)
__device__ __align__(16) float  g_xs[NHH*TT*NN];   // fp32 (elementwise use only)
__device__ __align__(16) float  g_qr[NHH*TT*NN];   // tf32; later reused as xy (tf32)
__device__ __align__(16) float  g_sc[NHH*TT*TT];   // tf32
__device__ __align__(16) float  g_ykv[NHH*TT*DD];  // tf32 after ln
__device__ __align__(16) float  g_part[KSPLIT*TT*DD];
__device__ __align__(16) float2 g_rt[TT*(NN/2)];   // rope (cos,sin)
// tf32-prerounded, transposed weights ([N][K] row-major, K contiguous)
__device__ __align__(16) float  g_wdxT[NHH*NN*DD];
__device__ __align__(16) float  g_wdyT[NHH*NN*DD];
__device__ __align__(16) float  g_encT[DD*NHH*NN];
__device__ __align__(16) float  g_lmhT[VV*DD];

__device__ __forceinline__ uint32_t tf32r(float x) {
    uint32_t y;
    asm("cvt.rna.tf32.f32 %0, %1;" : "=r"(y) : "f"(x));
    return y;
}
__device__ __forceinline__ float tf32f(float x) { return __uint_as_float(tf32r(x)); }
__device__ __forceinline__ uint32_t su32(const void* p) {
    uint32_t a;
    asm("{ .reg .u64 t; cvta.to.shared.u64 t, %1; cvt.u32.u64 %0, t; }"
        : "=r"(a) : "l"(p));
    return a;
}
__device__ __forceinline__ void cp16(uint32_t dst, const void* src, bool full) {
    int sz = full ? 16 : 0;
    asm volatile("cp.async.cg.shared.global [%0], [%1], 16, %2;"
                 :: "r"(dst), "l"(src), "r"(sz) : "memory");
}
__device__ __forceinline__ void mma8(float c[4], const uint32_t a[4], const uint32_t b[2]) {
    asm volatile(
        "mma.sync.aligned.m16n8k8.row.col.f32.tf32.tf32.f32 "
        "{%0,%1,%2,%3}, {%4,%5,%6,%7}, {%8,%9}, {%0,%1,%2,%3};"
        : "+f"(c[0]), "+f"(c[1]), "+f"(c[2]), "+f"(c[3])
        : "r"(a[0]), "r"(a[1]), "r"(a[2]), "r"(a[3]), "r"(b[0]), "r"(b[1]));
}
__device__ __forceinline__ void ldsm4(uint32_t d[4], uint32_t addr) {
    asm volatile("ldmatrix.sync.aligned.m8n8.x4.shared.b16 {%0,%1,%2,%3}, [%4];"
                 : "=r"(d[0]), "=r"(d[1]), "=r"(d[2]), "=r"(d[3]) : "r"(addr));
}

// ---------------------------------------------------------------------------
// tf32 warp-MMA GEMM, cp.async 3-stage pipeline (BK=32), ldmatrix fragments.
// C[M,Nc] = epi(A[M,K] @ B[Nc,K]^T)  -- both operands [rows][K] row-major.
// CTA tile 128x128, 256 threads (8 warps, 4m x 2n), warp tile 32x64.
// All A/B inputs tf32-prerounded (no cvt in mainloop).
// EPI: 0 plain fp32 | 1 relu->fp32 C (+fused rope -> aux tf32) |
//      2 relu*aux -> tf32 | 3 strict tril -> tf32
// AZM: 0 normal | 1 ymlp split-K (A=xy [h][t][n]) | 2 ykv split-K4
// ---------------------------------------------------------------------------
template<int EPI, int AZM>
__global__ __launch_bounds__(256, 2)
void gemm_mma(const float* __restrict__ A, const float* __restrict__ B,
              float* __restrict__ C, const float* __restrict__ aux,
              const float2* __restrict__ rtab,
              int Nc, int K, int lda, int ldb, int ldc,
              long long sA, long long sB, long long sC, long long sAux)
{
    extern __shared__ float smf[];
    float* sA_f = smf;
    float* sB_f = smf + NSTAGE * STG_F;

    const int bx = blockIdx.x, by = blockIdx.y, bz = blockIdx.z;
    const int tid = threadIdx.x;
    const int wid = tid >> 5, lane = tid & 31;
    const int grp = lane >> 2, qid = lane & 3;
    const int wm0 = (wid & 3) * 32, wn0 = (wid >> 2) * 64;
    const int row0 = by * 128, col0 = bx * 128;

    int koff = 0;
    if (AZM == 2) {          // ykv split-K: bz = h*4 + kz
        A += (long long)(bz >> 2) * sA + (bz & 3) * 256;   // column shift
        B += (bz & 3) * 256;
    } else if (AZM == 1) {   // ymlp split-K
        koff = bz * KCH;
        B += (long long)bz * sB;   // column shift trick (rows contiguous)
    } else {
        A += (long long)bz * sA;
        B += (long long)bz * sB;
    }
    C += (long long)bz * sC;
    const float* auxr = aux ? aux + (long long)bz * sAux : aux;
    float*       qout = (float*)auxr;

    // fully-masked tile above diagonal: zero-fill, exit
    if (EPI == 3 && bx > by) {
        #pragma unroll 4
        for (int i = tid; i < 128 * 32; i += 256) {
            int r = i >> 5, c4 = (i & 31) << 2;
            *(float4*)(C + (size_t)(row0 + r) * ldc + col0 + c4) = make_float4(0, 0, 0, 0);
        }
        return;
    }

    const uint32_t sA_u = su32(sA_f);
    const uint32_t sB_u = su32(sB_f);

    // ldmatrix per-lane base addresses
    const int rowA = (lane & 7) + ((lane >> 3) & 1) * 8;
    const int kA   = ((lane >> 4) & 1) * 4;
    const int rowB = (lane & 7) + ((lane >> 4) & 1) * 8;
    const int kB   = ((lane >> 3) & 1) * 4;
    const uint32_t aBase = sA_u + 4u * ((wm0 + rowA) * SROW + kA);
    const uint32_t bBase = sB_u + 4u * ((wn0 + rowB) * SROW + kB);

    float acc[2][8][4];
    #pragma unroll
    for (int mi = 0; mi < 2; mi++)
        #pragma unroll
        for (int ni = 0; ni < 8; ni++)
            #pragma unroll
            for (int j = 0; j < 4; j++) acc[mi][ni][j] = 0.f;

    const int nch = K / BK;

    auto issue = [&](int s) {
        const int k0 = s * BK;
        const int buf = s % NSTAGE;
        #pragma unroll
        for (int it = 0; it < 4; it++) {
            int idx4 = tid + it * 256;
            int r = idx4 >> 3, kc = (idx4 & 7) << 2;
            const float* src;
            if (AZM == 1) {
                int gk = koff + k0 + kc;
                int hh = gk / NN, nn = gk - hh * NN;
                src = A + (size_t)hh * TT * NN + (size_t)r * lda + nn;
            } else {
                src = A + (size_t)(row0 + 0) * 0 + (size_t)r * lda + k0 + kc;  // r relative
            }
            if (AZM != 1) src = A + (size_t)(row0 + r) * lda + k0 + kc;
            else          src = A + (size_t)((koff + k0 + kc) / NN) * TT * NN
                              + (size_t)(row0 + r) * lda + ((koff + k0 + kc) % NN);
            cp16(sA_u + (buf * STG_F + r * SROW + kc) * 4, src, true);
        }
        #pragma unroll
        for (int it = 0; it < 4; it++) {
            int idx4 = tid + it * 256;
            int nr = idx4 >> 3, kc = (idx4 & 7) << 2;
            const float* src = B + (size_t)(col0 + nr) * ldb + k0 + kc;
            cp16(sB_u + (buf * STG_F + nr * SROW + kc) * 4, src, col0 + nr < Nc);
        }
        asm volatile("cp.async.commit_group;" ::: "memory");
    };

    #pragma unroll
    for (int s = 0; s < NSTAGE - 1; s++) issue(s);

    for (int c = 0; c < nch; c++) {
        asm volatile("cp.async.wait_group %0;" :: "n"(NSTAGE - 2) : "memory");
        __syncthreads();
        if (c + NSTAGE - 1 < nch) issue(c + NSTAGE - 1);

        const int buf = c % NSTAGE;
        const uint32_t aOff = aBase + 4u * buf * STG_F;
        const uint32_t bOff = bBase + 4u * buf * STG_F;
        #pragma unroll
        for (int ks = 0; ks < BK; ks += 8) {
            uint32_t af[2][4], bf8[8][2];
            #pragma unroll
            for (int mi = 0; mi < 2; mi++)
                ldsm4(af[mi], aOff + 4u * (mi * 16 * SROW + ks));
            #pragma unroll
            for (int p = 0; p < 4; p++) {
                uint32_t t4[4];
                ldsm4(t4, bOff + 4u * (p * 16 * SROW + ks));
                bf8[2 * p    ][0] = t4[0]; bf8[2 * p    ][1] = t4[1];
                bf8[2 * p + 1][0] = t4[2]; bf8[2 * p + 1][1] = t4[3];
            }
            #pragma unroll
            for (int mi = 0; mi < 2; mi++)
                #pragma unroll
                for (int ni = 0; ni < 8; ni++)
                    mma8(acc[mi][ni], af[mi], bf8[ni]);
        }
    }

    // ---- epilogue ----
    #pragma unroll
    for (int mi = 0; mi < 2; mi++) {
        const int rA = row0 + wm0 + mi * 16 + grp;
        const int rB = rA + 8;
        #pragma unroll
        for (int ni = 0; ni < 8; ni++) {
            const int c = col0 + wn0 + ni * 8 + (qid << 1);
            if (c >= Nc) continue;
            float2 lo = make_float2(acc[mi][ni][0], acc[mi][ni][1]);
            float2 hi = make_float2(acc[mi][ni][2], acc[mi][ni][3]);
            if (EPI == 0) {
                *(float2*)(C + (size_t)rA * ldc + c) = lo;
                *(float2*)(C + (size_t)rB * ldc + c) = hi;
            } else if (EPI == 1) {
                lo.x = fmaxf(lo.x, 0.f); lo.y = fmaxf(lo.y, 0.f);
                hi.x = fmaxf(hi.x, 0.f); hi.y = fmaxf(hi.y, 0.f);
                *(float2*)(C + (size_t)rA * ldc + c) = lo;
                *(float2*)(C + (size_t)rB * ldc + c) = hi;
                float2 ca = rtab[(size_t)rA * (NN / 2) + (c >> 1)];
                float2 cb = rtab[(size_t)rB * (NN / 2) + (c >> 1)];
                float2 qa, qb;
                qa.x = tf32f(lo.x * ca.x - lo.y * ca.y);
                qa.y = tf32f(lo.y * ca.x + lo.x * ca.y);
                qb.x = tf32f(hi.x * cb.x - hi.y * cb.y);
                qb.y = tf32f(hi.y * cb.x + hi.x * cb.y);
                *(float2*)(qout + (size_t)rA * ldc + c) = qa;
                *(float2*)(qout + (size_t)rB * ldc + c) = qb;
            } else if (EPI == 2) {
                float2 ea = *(const float2*)(auxr + (size_t)rA * ldc + c);
                float2 eb = *(const float2*)(auxr + (size_t)rB * ldc + c);
                lo.x = tf32f(fmaxf(lo.x, 0.f) * ea.x); lo.y = tf32f(fmaxf(lo.y, 0.f) * ea.y);
                hi.x = tf32f(fmaxf(hi.x, 0.f) * eb.x); hi.y = tf32f(fmaxf(hi.y, 0.f) * eb.y);
                *(float2*)(C + (size_t)rA * ldc + c) = lo;
                *(float2*)(C + (size_t)rB * ldc + c) = hi;
            } else { // EPI == 3
                float2 oa, ob;
                oa.x = (c     < rA) ? tf32f(lo.x) : 0.f;
                oa.y = (c + 1 < rA) ? tf32f(lo.y) : 0.f;
                ob.x = (c     < rB) ? tf32f(hi.x) : 0.f;
                ob.y = (c + 1 < rB) ? tf32f(hi.y) : 0.f;
                *(float2*)(C + (size_t)rA * ldc + c) = oa;
                *(float2*)(C + (size_t)rB * ldc + c) = ob;
            }
        }
    }
}

// ---------------------------------------------------------------------------
// Transpose + tf32-round: out[Nn][M] = tf32(in[M][Nn]^T); batched via z
// ---------------------------------------------------------------------------
__global__ void transpose_round_k(const float* __restrict__ in, float* __restrict__ out,
                                  int M, int Nn, long long inS, long long outS)
{
    __shared__ float t[32][33];
    in  += (long long)blockIdx.z * inS;
    out += (long long)blockIdx.z * outS;
    int x = blockIdx.x * 32 + threadIdx.x;
    int y = blockIdx.y * 32 + threadIdx.y;
    #pragma unroll
    for (int i = 0; i < 32; i += 8)
        t[threadIdx.y + i][threadIdx.x] = in[(size_t)(y + i) * Nn + x];
    __syncthreads();
    int x2 = blockIdx.y * 32 + threadIdx.x;
    int y2 = blockIdx.x * 32 + threadIdx.y;
    #pragma unroll
    for (int i = 0; i < 32; i += 8)
        out[(size_t)(y2 + i) * M + x2] = tf32f(t[threadIdx.x][threadIdx.y + i]);
}

// ---------------------------------------------------------------------------
// LayerNorm helpers (192-wide rows, 6 warps)
// ---------------------------------------------------------------------------
__device__ __forceinline__ float2 meanvar192(float v, float* s1, float* s2)
{
    __syncthreads();
    float a = v, b = v * v;
    #pragma unroll
    for (int o = 16; o > 0; o >>= 1) {
        a += __shfl_down_sync(0xffffffffu, a, o);
        b += __shfl_down_sync(0xffffffffu, b, o);
    }
    int lane = threadIdx.x & 31, w = threadIdx.x >> 5;
    if (lane == 0) { s1[w] = a; s2[w] = b; }
    __syncthreads();
    if (threadIdx.x == 0) {
        float sa = 0.f, sb = 0.f;
        #pragma unroll
        for (int i = 0; i < 6; i++) { sa += s1[i]; sb += s2[i]; }
        s1[0] = sa; s2[0] = sb;
    }
    __syncthreads();
    float m   = s1[0] * (1.0f / 192.0f);
    float var = s2[0] * (1.0f / 192.0f) - m * m;
    return make_float2(m, fmaxf(var, 0.f));
}

__global__ void embed_ln_k(const int* __restrict__ idx,
                           const float* __restrict__ emb,
                           const float* __restrict__ pos)
{
    int t = blockIdx.x, d = threadIdx.x;
    __shared__ float s1[8], s2[8];
    float v = emb[(size_t)idx[t] * DD + d] + pos[(size_t)t * DD + d];
    float2 mv = meanvar192(v, s1, s2);
    float r = (v - mv.x) * rsqrtf(mv.y + 1e-5f);
    g_x [(size_t)t * DD + d] = r;
    g_xr[(size_t)t * DD + d] = tf32f(r);
}

__global__ void sincos_k()
{
    int i = blockIdx.x * blockDim.x + threadIdx.x;
    if (i >= TT * (NN / 2)) return;
    int t = i / (NN / 2);
    int p = i - t * (NN / 2);
    float f = exp2f(-(float)p * (1.0f / 96.0f)) * 0.15915494309189535f;
    float ph = fmodf((float)t * f, 1.0f) * 6.283185307179586f;
    float s, c;
    sincosf(ph, &s, &c);
    g_rt[i] = make_float2(c, s);
}

// ykv: reduce 4 split-K partials, then LN -> tf32
__global__ void ln_ykv_k()
{
    int r = blockIdx.x, d = threadIdx.x;     // r = h*TT + t
    __shared__ float s1[8], s2[8];
    int h = r >> 10, t = r & (TT - 1);
    float v = 0.f;
    #pragma unroll
    for (int kz = 0; kz < 4; kz++)
        v += g_part[(size_t)(h * 4 + kz) * TT * DD + (size_t)t * DD + d];
    float2 mv = meanvar192(v, s1, s2);
    g_ykv[(size_t)r * DD + d] = tf32f((v - mv.x) * rsqrtf(mv.y + 1e-5f));
}

__global__ void finalize_k()
{
    int t = blockIdx.x, d = threadIdx.x;
    __shared__ float s1[8], s2[8];
    float ym = 0.f;
    #pragma unroll
    for (int c = 0; c < KSPLIT; c++)
        ym += g_part[(size_t)c * TT * DD + (size_t)t * DD + d];
    float2 mv = meanvar192(ym, s1, s2);
    float l1 = (ym - mv.x) * rsqrtf(mv.y + 1e-5f);
    float xv = g_x[(size_t)t * DD + d] + l1;
    float2 mv2 = meanvar192(xv, s1, s2);
    float r = (xv - mv2.x) * rsqrtf(mv2.y + 1e-5f);
    g_x [(size_t)t * DD + d] = r;
    g_xr[(size_t)t * DD + d] = tf32f(r);
}

// ---------------------------------------------------------------------------
extern "C" void kernel_launch(void* const* d_in, const int* in_sizes, int n_in,
                              void* d_out, int out_size)
{
    const int*   idx  = (const int*)  d_in[0];
    const float* decx = (const float*)d_in[1];   // (NH, D, N)
    const float* decy = (const float*)d_in[2];   // (NH, D, N)
    const float* enc  = (const float*)d_in[3];   // (NH*N, D)
    const float* emb  = (const float*)d_in[4];   // (VOCAB, D)
    const float* pos  = (const float*)d_in[5];   // (BLOCK, D)
    const float* lmh  = (const float*)d_in[6];   // (D, VOCAB)
    float* out = (float*)d_out;

    float *pxr, *pxT, *pxs, *pqr, *psc, *ppart, *pwdxT, *pwdyT, *pencT, *plmhT, *pykv;
    float2* prt;
    cudaGetSymbolAddress((void**)&pxr,   g_xr);
    cudaGetSymbolAddress((void**)&pxT,   g_xT);
    cudaGetSymbolAddress((void**)&pxs,   g_xs);
    cudaGetSymbolAddress((void**)&pqr,   g_qr);
    cudaGetSymbolAddress((void**)&psc,   g_sc);
    cudaGetSymbolAddress((void**)&pykv,  g_ykv);
    cudaGetSymbolAddress((void**)&ppart, g_part);
    cudaGetSymbolAddress((void**)&prt,   g_rt);
    cudaGetSymbolAddress((void**)&pwdxT, g_wdxT);
    cudaGetSymbolAddress((void**)&pwdyT, g_wdyT);
    cudaGetSymbolAddress((void**)&pencT, g_encT);
    cudaGetSymbolAddress((void**)&plmhT, g_lmhT);

    const int SMEMB = NSTAGE * 2 * STG_F * 4;   // 110592 B
    cudaFuncSetAttribute(gemm_mma<1,0>, cudaFuncAttributeMaxDynamicSharedMemorySize, SMEMB);
    cudaFuncSetAttribute(gemm_mma<3,0>, cudaFuncAttributeMaxDynamicSharedMemorySize, SMEMB);
    cudaFuncSetAttribute(gemm_mma<0,0>, cudaFuncAttributeMaxDynamicSharedMemorySize, SMEMB);
    cudaFuncSetAttribute(gemm_mma<0,2>, cudaFuncAttributeMaxDynamicSharedMemorySize, SMEMB);
    cudaFuncSetAttribute(gemm_mma<2,0>, cudaFuncAttributeMaxDynamicSharedMemorySize, SMEMB);
    cudaFuncSetAttribute(gemm_mma<0,1>, cudaFuncAttributeMaxDynamicSharedMemorySize, SMEMB);

    dim3 tb(32, 8);
    transpose_round_k<<<dim3(NN/32, DD/32, NHH), tb>>>(decx, pwdxT, DD, NN,
                                                       (long long)DD*NN, (long long)NN*DD);
    transpose_round_k<<<dim3(NN/32, DD/32, NHH), tb>>>(decy, pwdyT, DD, NN,
                                                       (long long)DD*NN, (long long)NN*DD);
    transpose_round_k<<<dim3(DD/32, (NHH*NN)/32, 1), tb>>>(enc, pencT, NHH*NN, DD, 0, 0);
    transpose_round_k<<<dim3(VV/32, DD/32, 1), tb>>>(lmh, plmhT, DD, VV, 0, 0);

    sincos_k<<<(TT * (NN / 2) + 255) / 256, 256>>>();
    embed_ln_k<<<TT, 192>>>(idx, emb, pos);

    for (int l = 0; l < NLAYER; l++) {
        // x^T for ykv GEMM B operand
        transpose_round_k<<<dim3(DD/32, TT/32, 1), tb>>>(pxr, pxT, TT, DD, 0, 0);

        // x_sparse(fp32) = relu(x @ decx[h]);  qr(tf32) = rope(x_sparse)
        gemm_mma<1, 0><<<dim3(NN / 128, TT / 128, NHH), 256, SMEMB>>>(
            pxr, pwdxT, pxs, pqr, prt, NN, DD, DD, DD, NN,
            0LL, (long long)NN * DD, (long long)TT * NN, (long long)TT * NN);

        // scores(tf32) = (qr @ qr^T) * tril(-1)
        gemm_mma<3, 0><<<dim3(TT / 128, TT / 128, NHH), 256, SMEMB>>>(
            pqr, pqr, psc, nullptr, nullptr, TT, NN, NN, NN, TT,
            (long long)TT * NN, (long long)TT * NN, (long long)TT * TT, 0LL);

        // ykv partials(fp32) = scores @ x   (split-K=4; bz = h*4+kz)
        gemm_mma<0, 2><<<dim3(2, TT / 128, NHH * 4), 256, SMEMB>>>(
            psc, pxT, ppart, nullptr, nullptr, DD, TT / 4, TT, TT, DD,
            (long long)TT * TT, 0LL, (long long)TT * DD, 0LL);

        // ykv = ln(sum partials) -> tf32
        ln_ykv_k<<<NHH * TT, 192>>>();

        // xy(tf32) = relu(ykv @ decy[h]) * x_sparse(fp32)   -> g_qr (reuse)
        gemm_mma<2, 0><<<dim3(NN / 128, TT / 128, NHH), 256, SMEMB>>>(
            pykv, pwdyT, pqr, pxs, nullptr, NN, DD, DD, DD, NN,
            (long long)TT * DD, (long long)NN * DD, (long long)TT * NN,
            (long long)TT * NN);

        // ymlp partials(fp32): xy @ enc^T, split-K = 16 (column-shift trick on B)
        gemm_mma<0, 1><<<dim3(2, TT / 128, KSPLIT), 256, SMEMB>>>(
            pqr, pencT, ppart, nullptr, nullptr, DD, KCH, NN, NHH * NN, DD,
            0LL, (long long)KCH, (long long)TT * DD, 0LL);

        // x = ln(x + ln(sum partials))
        finalize_k<<<TT, 192>>>();
    }

    // logits(fp32) = x @ lm_head  (B = lmh^T [v][d])
    gemm_mma<0, 0><<<dim3(2, TT / 128, 1), 256, SMEMB>>>(
        pxr, plmhT, out, nullptr, nullptr, VV, DD, DD, DD, VV,
        0LL, 0LL, 0LL, 0LL);
}

// round 9
// speedup vs baseline: 3.9133x; 1.0228x over previous
#include <cuda_runtime.h>
#include <math.h>
#include <stdint.h>

// Problem constants
#define TT 1024
#define DD 192
#define NHH 4
#define NN 3072
#define VV 256
#define NLAYER 4
#define KSPLIT 16
#define KCH ((NHH*NN)/KSPLIT)   // 768
#define NSTAGE 3
#define BK 32
#define SROW 36                  // floats per smem row (32 + 4 pad)
#define A_ST1 (128*SROW)         // stage floats (128-row operand)
#define A_ST2 (128*SROW)
#define B_ST2 (256*SROW)

// ---------------------------------------------------------------------------
// Static device scratch (no allocation allowed) -- 16B aligned for cp.async
// ---------------------------------------------------------------------------
__device__ __align__(16) float  g_x[TT*DD];        // fp32 residual chain
__device__ __align__(16) float  g_xr[TT*DD];       // tf32-rounded copy (GEMM A)
__device__ __align__(16) float  g_xT[DD*TT];       // xr^T (GEMM B for ykv)
__device__ __align__(16) float  g_xs[NHH*TT*NN];   // fp32 (elementwise use only)
__device__ __align__(16) float  g_qr[NHH*TT*NN];   // tf32; later reused as xy (tf32)
__device__ __align__(16) float  g_sc[NHH*TT*TT];   // tf32
__device__ __align__(16) float  g_ykv[NHH*TT*DD];  // tf32 after ln
__device__ __align__(16) float  g_part[KSPLIT*TT*DD];
__device__ __align__(16) float2 g_rt[TT*(NN/2)];   // rope (cos,sin)
__device__ __align__(16) float  g_wdxT[NHH*NN*DD];
__device__ __align__(16) float  g_wdyT[NHH*NN*DD];
__device__ __align__(16) float  g_encT[DD*NHH*NN];
__device__ __align__(16) float  g_lmhT[VV*DD];

__device__ __forceinline__ uint32_t tf32r(float x) {
    uint32_t y;
    asm("cvt.rna.tf32.f32 %0, %1;" : "=r"(y) : "f"(x));
    return y;
}
__device__ __forceinline__ float tf32f(float x) { return __uint_as_float(tf32r(x)); }
__device__ __forceinline__ uint32_t su32(const void* p) {
    uint32_t a;
    asm("{ .reg .u64 t; cvta.to.shared.u64 t, %1; cvt.u32.u64 %0, t; }"
        : "=r"(a) : "l"(p));
    return a;
}
__device__ __forceinline__ void cp16(uint32_t dst, const void* src, bool full) {
    int sz = full ? 16 : 0;
    asm volatile("cp.async.cg.shared.global [%0], [%1], 16, %2;"
                 :: "r"(dst), "l"(src), "r"(sz) : "memory");
}
__device__ __forceinline__ void mma8(float c[4], const uint32_t a[4], const uint32_t b[2]) {
    asm volatile(
        "mma.sync.aligned.m16n8k8.row.col.f32.tf32.tf32.f32 "
        "{%0,%1,%2,%3}, {%4,%5,%6,%7}, {%8,%9}, {%0,%1,%2,%3};"
        : "+f"(c[0]), "+f"(c[1]), "+f"(c[2]), "+f"(c[3])
        : "r"(a[0]), "r"(a[1]), "r"(a[2]), "r"(a[3]), "r"(b[0]), "r"(b[1]));
}
__device__ __forceinline__ void ldsm4(uint32_t d[4], uint32_t addr) {
    asm volatile("ldmatrix.sync.aligned.m8n8.x4.shared.b16 {%0,%1,%2,%3}, [%4];"
                 : "=r"(d[0]), "=r"(d[1]), "=r"(d[2]), "=r"(d[3]) : "r"(addr));
}

// ---------------------------------------------------------------------------
// Kernel 1: tile 128x128, 256 thr (8 warps 4m x 2n), EPI=0 only.
// C[M,Nc] = A[M,K] @ B[Nc,K]^T, fp32 out.
// AZM: 0 normal | 1 ymlp split-K (A=xy [h][t][n]) | 2 ykv split-K4
// ---------------------------------------------------------------------------
template<int AZM>
__global__ __launch_bounds__(256, 2)
void gemm_mma(const float* __restrict__ A, const float* __restrict__ B,
              float* __restrict__ C,
              int Nc, int K, int lda, int ldb, int ldc,
              long long sA, long long sB, long long sC)
{
    extern __shared__ float smf[];
    float* sA_f = smf;
    float* sB_f = smf + NSTAGE * A_ST1;

    const int bx = blockIdx.x, by = blockIdx.y, bz = blockIdx.z;
    const int tid = threadIdx.x;
    const int wid = tid >> 5, lane = tid & 31;
    const int grp = lane >> 2, qid = lane & 3;
    const int wm0 = (wid & 3) * 32, wn0 = (wid >> 2) * 64;
    const int row0 = by * 128, col0 = bx * 128;

    int koff = 0;
    if (AZM == 2) {
        A += (long long)(bz >> 2) * sA + (bz & 3) * 256;
        B += (bz & 3) * 256;
    } else if (AZM == 1) {
        koff = bz * KCH;
        B += (long long)bz * sB;
    } else {
        A += (long long)bz * sA;
        B += (long long)bz * sB;
    }
    C += (long long)bz * sC;

    const uint32_t sA_u = su32(sA_f);
    const uint32_t sB_u = su32(sB_f);

    const int rowA = (lane & 7) + ((lane >> 3) & 1) * 8;
    const int kA   = ((lane >> 4) & 1) * 4;
    const int rowB = (lane & 7) + ((lane >> 4) & 1) * 8;
    const int kB   = ((lane >> 3) & 1) * 4;
    const uint32_t aBase = sA_u + 4u * ((wm0 + rowA) * SROW + kA);
    const uint32_t bBase = sB_u + 4u * ((wn0 + rowB) * SROW + kB);

    float acc[2][8][4];
    #pragma unroll
    for (int mi = 0; mi < 2; mi++)
        #pragma unroll
        for (int ni = 0; ni < 8; ni++)
            #pragma unroll
            for (int j = 0; j < 4; j++) acc[mi][ni][j] = 0.f;

    const int nch = K / BK;

    auto issue = [&](int s) {
        const int k0 = s * BK;
        const int buf = s % NSTAGE;
        #pragma unroll
        for (int it = 0; it < 4; it++) {
            int idx4 = tid + it * 256;
            int r = idx4 >> 3, kc = (idx4 & 7) << 2;
            const float* src;
            if (AZM == 1) {
                int gk = koff + k0 + kc;
                int hh = gk / NN, nn = gk - hh * NN;
                src = A + (size_t)hh * TT * NN + (size_t)(row0 + r) * lda + nn;
            } else {
                src = A + (size_t)(row0 + r) * lda + k0 + kc;
            }
            cp16(sA_u + (buf * A_ST1 + r * SROW + kc) * 4, src, true);
        }
        #pragma unroll
        for (int it = 0; it < 4; it++) {
            int idx4 = tid + it * 256;
            int nr = idx4 >> 3, kc = (idx4 & 7) << 2;
            const float* src = B + (size_t)(col0 + nr) * ldb + k0 + kc;
            cp16(sB_u + (buf * A_ST1 + nr * SROW + kc) * 4, src, col0 + nr < Nc);
        }
        asm volatile("cp.async.commit_group;" ::: "memory");
    };

    #pragma unroll
    for (int s = 0; s < NSTAGE - 1; s++) issue(s);

    for (int c = 0; c < nch; c++) {
        asm volatile("cp.async.wait_group %0;" :: "n"(NSTAGE - 2) : "memory");
        __syncthreads();
        if (c + NSTAGE - 1 < nch) issue(c + NSTAGE - 1);

        const int buf = c % NSTAGE;
        const uint32_t aOff = aBase + 4u * buf * A_ST1;
        const uint32_t bOff = bBase + 4u * buf * A_ST1;
        #pragma unroll
        for (int ks = 0; ks < BK; ks += 8) {
            uint32_t af[2][4], bf8[8][2];
            #pragma unroll
            for (int mi = 0; mi < 2; mi++)
                ldsm4(af[mi], aOff + 4u * (mi * 16 * SROW + ks));
            #pragma unroll
            for (int p = 0; p < 4; p++) {
                uint32_t t4[4];
                ldsm4(t4, bOff + 4u * (p * 16 * SROW + ks));
                bf8[2 * p    ][0] = t4[0]; bf8[2 * p    ][1] = t4[1];
                bf8[2 * p + 1][0] = t4[2]; bf8[2 * p + 1][1] = t4[3];
            }
            #pragma unroll
            for (int mi = 0; mi < 2; mi++)
                #pragma unroll
                for (int ni = 0; ni < 8; ni++)
                    mma8(acc[mi][ni], af[mi], bf8[ni]);
        }
    }

    #pragma unroll
    for (int mi = 0; mi < 2; mi++) {
        const int rA = row0 + wm0 + mi * 16 + grp;
        const int rB = rA + 8;
        #pragma unroll
        for (int ni = 0; ni < 8; ni++) {
            const int c = col0 + wn0 + ni * 8 + (qid << 1);
            if (c >= Nc) continue;
            *(float2*)(C + (size_t)rA * ldc + c) = make_float2(acc[mi][ni][0], acc[mi][ni][1]);
            *(float2*)(C + (size_t)rB * ldc + c) = make_float2(acc[mi][ni][2], acc[mi][ni][3]);
        }
    }
}

// ---------------------------------------------------------------------------
// Kernel 2: tile 128x256, 512 thr (16 warps 4m x 4n), warp tile 32x64.
// EPI: 1 relu->fp32 C (+fused rope -> aux tf32) | 2 relu*aux -> tf32 |
//      3 strict tril -> tf32
// ---------------------------------------------------------------------------
template<int EPI>
__global__ __launch_bounds__(512, 1)
void gemm_wide(const float* __restrict__ A, const float* __restrict__ B,
               float* __restrict__ C, const float* __restrict__ aux,
               const float2* __restrict__ rtab,
               int Nc, int K, int lda, int ldb, int ldc,
               long long sA, long long sB, long long sC, long long sAux)
{
    extern __shared__ float smf[];
    float* sA_f = smf;
    float* sB_f = smf + NSTAGE * A_ST2;

    const int bx = blockIdx.x, by = blockIdx.y, bz = blockIdx.z;
    const int tid = threadIdx.x;
    const int wid = tid >> 5, lane = tid & 31;
    const int grp = lane >> 2, qid = lane & 3;
    const int wm0 = (wid & 3) * 32, wn0 = (wid >> 2) * 64;
    const int row0 = by * 128, col0 = bx * 256;

    A += (long long)bz * sA;
    B += (long long)bz * sB;
    C += (long long)bz * sC;
    const float* auxr = aux ? aux + (long long)bz * sAux : aux;
    float*       qout = (float*)auxr;

    // fully-masked tile (strict tril): zero-fill, exit
    if (EPI == 3 && col0 >= row0 + 127) {
        #pragma unroll 4
        for (int i = tid; i < 128 * 64; i += 512) {
            int r = i >> 6, c4 = (i & 63) << 2;
            *(float4*)(C + (size_t)(row0 + r) * ldc + col0 + c4) = make_float4(0, 0, 0, 0);
        }
        return;
    }

    const uint32_t sA_u = su32(sA_f);
    const uint32_t sB_u = su32(sB_f);

    const int rowA = (lane & 7) + ((lane >> 3) & 1) * 8;
    const int kA   = ((lane >> 4) & 1) * 4;
    const int rowB = (lane & 7) + ((lane >> 4) & 1) * 8;
    const int kB   = ((lane >> 3) & 1) * 4;
    const uint32_t aBase = sA_u + 4u * ((wm0 + rowA) * SROW + kA);
    const uint32_t bBase = sB_u + 4u * ((wn0 + rowB) * SROW + kB);

    float acc[2][8][4];
    #pragma unroll
    for (int mi = 0; mi < 2; mi++)
        #pragma unroll
        for (int ni = 0; ni < 8; ni++)
            #pragma unroll
            for (int j = 0; j < 4; j++) acc[mi][ni][j] = 0.f;

    const int nch = K / BK;

    auto issue = [&](int s) {
        const int k0 = s * BK;
        const int buf = s % NSTAGE;
        #pragma unroll
        for (int it = 0; it < 2; it++) {
            int idx4 = tid + it * 512;
            int r = idx4 >> 3, kc = (idx4 & 7) << 2;
            const float* src = A + (size_t)(row0 + r) * lda + k0 + kc;
            cp16(sA_u + (buf * A_ST2 + r * SROW + kc) * 4, src, true);
        }
        #pragma unroll
        for (int it = 0; it < 4; it++) {
            int idx4 = tid + it * 512;
            int nr = idx4 >> 3, kc = (idx4 & 7) << 2;
            const float* src = B + (size_t)(col0 + nr) * ldb + k0 + kc;
            cp16(sB_u + (buf * B_ST2 + nr * SROW + kc) * 4, src, col0 + nr < Nc);
        }
        asm volatile("cp.async.commit_group;" ::: "memory");
    };

    #pragma unroll
    for (int s = 0; s < NSTAGE - 1; s++) issue(s);

    for (int c = 0; c < nch; c++) {
        asm volatile("cp.async.wait_group %0;" :: "n"(NSTAGE - 2) : "memory");
        __syncthreads();
        if (c + NSTAGE - 1 < nch) issue(c + NSTAGE - 1);

        const int buf = c % NSTAGE;
        const uint32_t aOff = aBase + 4u * buf * A_ST2;
        const uint32_t bOff = bBase + 4u * buf * B_ST2;
        #pragma unroll
        for (int ks = 0; ks < BK; ks += 8) {
            uint32_t af[2][4], bf8[8][2];
            #pragma unroll
            for (int mi = 0; mi < 2; mi++)
                ldsm4(af[mi], aOff + 4u * (mi * 16 * SROW + ks));
            #pragma unroll
            for (int p = 0; p < 4; p++) {
                uint32_t t4[4];
                ldsm4(t4, bOff + 4u * (p * 16 * SROW + ks));
                bf8[2 * p    ][0] = t4[0]; bf8[2 * p    ][1] = t4[1];
                bf8[2 * p + 1][0] = t4[2]; bf8[2 * p + 1][1] = t4[3];
            }
            #pragma unroll
            for (int mi = 0; mi < 2; mi++)
                #pragma unroll
                for (int ni = 0; ni < 8; ni++)
                    mma8(acc[mi][ni], af[mi], bf8[ni]);
        }
    }

    // ---- epilogue ----
    #pragma unroll
    for (int mi = 0; mi < 2; mi++) {
        const int rA = row0 + wm0 + mi * 16 + grp;
        const int rB = rA + 8;
        #pragma unroll
        for (int ni = 0; ni < 8; ni++) {
            const int c = col0 + wn0 + ni * 8 + (qid << 1);
            float2 lo = make_float2(acc[mi][ni][0], acc[mi][ni][1]);
            float2 hi = make_float2(acc[mi][ni][2], acc[mi][ni][3]);
            if (EPI == 1) {
                lo.x = fmaxf(lo.x, 0.f); lo.y = fmaxf(lo.y, 0.f);
                hi.x = fmaxf(hi.x, 0.f); hi.y = fmaxf(hi.y, 0.f);
                *(float2*)(C + (size_t)rA * ldc + c) = lo;
                *(float2*)(C + (size_t)rB * ldc + c) = hi;
                float2 ca = rtab[(size_t)rA * (NN / 2) + (c >> 1)];
                float2 cb = rtab[(size_t)rB * (NN / 2) + (c >> 1)];
                float2 qa, qb;
                qa.x = tf32f(lo.x * ca.x - lo.y * ca.y);
                qa.y = tf32f(lo.y * ca.x + lo.x * ca.y);
                qb.x = tf32f(hi.x * cb.x - hi.y * cb.y);
                qb.y = tf32f(hi.y * cb.x + hi.x * cb.y);
                *(float2*)(qout + (size_t)rA * ldc + c) = qa;
                *(float2*)(qout + (size_t)rB * ldc + c) = qb;
            } else if (EPI == 2) {
                float2 ea = *(const float2*)(auxr + (size_t)rA * ldc + c);
                float2 eb = *(const float2*)(auxr + (size_t)rB * ldc + c);
                lo.x = tf32f(fmaxf(lo.x, 0.f) * ea.x); lo.y = tf32f(fmaxf(lo.y, 0.f) * ea.y);
                hi.x = tf32f(fmaxf(hi.x, 0.f) * eb.x); hi.y = tf32f(fmaxf(hi.y, 0.f) * eb.y);
                *(float2*)(C + (size_t)rA * ldc + c) = lo;
                *(float2*)(C + (size_t)rB * ldc + c) = hi;
            } else { // EPI == 3
                float2 oa, ob;
                oa.x = (c     < rA) ? tf32f(lo.x) : 0.f;
                oa.y = (c + 1 < rA) ? tf32f(lo.y) : 0.f;
                ob.x = (c     < rB) ? tf32f(hi.x) : 0.f;
                ob.y = (c + 1 < rB) ? tf32f(hi.y) : 0.f;
                *(float2*)(C + (size_t)rA * ldc + c) = oa;
                *(float2*)(C + (size_t)rB * ldc + c) = ob;
            }
        }
    }
}

// ---------------------------------------------------------------------------
__global__ void transpose_round_k(const float* __restrict__ in, float* __restrict__ out,
                                  int M, int Nn, long long inS, long long outS)
{
    __shared__ float t[32][33];
    in  += (long long)blockIdx.z * inS;
    out += (long long)blockIdx.z * outS;
    int x = blockIdx.x * 32 + threadIdx.x;
    int y = blockIdx.y * 32 + threadIdx.y;
    #pragma unroll
    for (int i = 0; i < 32; i += 8)
        t[threadIdx.y + i][threadIdx.x] = in[(size_t)(y + i) * Nn + x];
    __syncthreads();
    int x2 = blockIdx.y * 32 + threadIdx.x;
    int y2 = blockIdx.x * 32 + threadIdx.y;
    #pragma unroll
    for (int i = 0; i < 32; i += 8)
        out[(size_t)(y2 + i) * M + x2] = tf32f(t[threadIdx.x][threadIdx.y + i]);
}

// ---------------------------------------------------------------------------
__device__ __forceinline__ float2 meanvar192(float v, float* s1, float* s2)
{
    __syncthreads();
    float a = v, b = v * v;
    #pragma unroll
    for (int o = 16; o > 0; o >>= 1) {
        a += __shfl_down_sync(0xffffffffu, a, o);
        b += __shfl_down_sync(0xffffffffu, b, o);
    }
    int lane = threadIdx.x & 31, w = threadIdx.x >> 5;
    if (lane == 0) { s1[w] = a; s2[w] = b; }
    __syncthreads();
    if (threadIdx.x == 0) {
        float sa = 0.f, sb = 0.f;
        #pragma unroll
        for (int i = 0; i < 6; i++) { sa += s1[i]; sb += s2[i]; }
        s1[0] = sa; s2[0] = sb;
    }
    __syncthreads();
    float m   = s1[0] * (1.0f / 192.0f);
    float var = s2[0] * (1.0f / 192.0f) - m * m;
    return make_float2(m, fmaxf(var, 0.f));
}

__global__ void embed_ln_k(const int* __restrict__ idx,
                           const float* __restrict__ emb,
                           const float* __restrict__ pos)
{
    int t = blockIdx.x, d = threadIdx.x;
    __shared__ float s1[8], s2[8];
    float v = emb[(size_t)idx[t] * DD + d] + pos[(size_t)t * DD + d];
    float2 mv = meanvar192(v, s1, s2);
    float r = (v - mv.x) * rsqrtf(mv.y + 1e-5f);
    g_x [(size_t)t * DD + d] = r;
    g_xr[(size_t)t * DD + d] = tf32f(r);
}

__global__ void sincos_k()
{
    int i = blockIdx.x * blockDim.x + threadIdx.x;
    if (i >= TT * (NN / 2)) return;
    int t = i / (NN / 2);
    int p = i - t * (NN / 2);
    float f = exp2f(-(float)p * (1.0f / 96.0f)) * 0.15915494309189535f;
    float ph = fmodf((float)t * f, 1.0f) * 6.283185307179586f;
    float s, c;
    sincosf(ph, &s, &c);
    g_rt[i] = make_float2(c, s);
}

__global__ void ln_ykv_k()
{
    int r = blockIdx.x, d = threadIdx.x;     // r = h*TT + t
    __shared__ float s1[8], s2[8];
    int h = r >> 10, t = r & (TT - 1);
    float v = 0.f;
    #pragma unroll
    for (int kz = 0; kz < 4; kz++)
        v += g_part[(size_t)(h * 4 + kz) * TT * DD + (size_t)t * DD + d];
    float2 mv = meanvar192(v, s1, s2);
    g_ykv[(size_t)r * DD + d] = tf32f((v - mv.x) * rsqrtf(mv.y + 1e-5f));
}

__global__ void finalize_k()
{
    int t = blockIdx.x, d = threadIdx.x;
    __shared__ float s1[8], s2[8];
    float ym = 0.f;
    #pragma unroll
    for (int c = 0; c < KSPLIT; c++)
        ym += g_part[(size_t)c * TT * DD + (size_t)t * DD + d];
    float2 mv = meanvar192(ym, s1, s2);
    float l1 = (ym - mv.x) * rsqrtf(mv.y + 1e-5f);
    float xv = g_x[(size_t)t * DD + d] + l1;
    float2 mv2 = meanvar192(xv, s1, s2);
    float r = (xv - mv2.x) * rsqrtf(mv2.y + 1e-5f);
    g_x [(size_t)t * DD + d] = r;
    g_xr[(size_t)t * DD + d] = tf32f(r);
}

// ---------------------------------------------------------------------------
extern "C" void kernel_launch(void* const* d_in, const int* in_sizes, int n_in,
                              void* d_out, int out_size)
{
    const int*   idx  = (const int*)  d_in[0];
    const float* decx = (const float*)d_in[1];
    const float* decy = (const float*)d_in[2];
    const float* enc  = (const float*)d_in[3];
    const float* emb  = (const float*)d_in[4];
    const float* pos  = (const float*)d_in[5];
    const float* lmh  = (const float*)d_in[6];
    float* out = (float*)d_out;

    float *pxr, *pxT, *pxs, *pqr, *psc, *ppart, *pwdxT, *pwdyT, *pencT, *plmhT, *pykv;
    float2* prt;
    cudaGetSymbolAddress((void**)&pxr,   g_xr);
    cudaGetSymbolAddress((void**)&pxT,   g_xT);
    cudaGetSymbolAddress((void**)&pxs,   g_xs);
    cudaGetSymbolAddress((void**)&pqr,   g_qr);
    cudaGetSymbolAddress((void**)&psc,   g_sc);
    cudaGetSymbolAddress((void**)&pykv,  g_ykv);
    cudaGetSymbolAddress((void**)&ppart, g_part);
    cudaGetSymbolAddress((void**)&prt,   g_rt);
    cudaGetSymbolAddress((void**)&pwdxT, g_wdxT);
    cudaGetSymbolAddress((void**)&pwdyT, g_wdyT);
    cudaGetSymbolAddress((void**)&pencT, g_encT);
    cudaGetSymbolAddress((void**)&plmhT, g_lmhT);

    const int SMEM1 = NSTAGE * 2 * A_ST1 * 4;            // 110592 B
    const int SMEM2 = NSTAGE * (A_ST2 + B_ST2) * 4;      // 165888 B
    cudaFuncSetAttribute(gemm_mma<0>,  cudaFuncAttributeMaxDynamicSharedMemorySize, SMEM1);
    cudaFuncSetAttribute(gemm_mma<1>,  cudaFuncAttributeMaxDynamicSharedMemorySize, SMEM1);
    cudaFuncSetAttribute(gemm_mma<2>,  cudaFuncAttributeMaxDynamicSharedMemorySize, SMEM1);
    cudaFuncSetAttribute(gemm_wide<1>, cudaFuncAttributeMaxDynamicSharedMemorySize, SMEM2);
    cudaFuncSetAttribute(gemm_wide<2>, cudaFuncAttributeMaxDynamicSharedMemorySize, SMEM2);
    cudaFuncSetAttribute(gemm_wide<3>, cudaFuncAttributeMaxDynamicSharedMemorySize, SMEM2);

    dim3 tb(32, 8);
    transpose_round_k<<<dim3(NN/32, DD/32, NHH), tb>>>(decx, pwdxT, DD, NN,
                                                       (long long)DD*NN, (long long)NN*DD);
    transpose_round_k<<<dim3(NN/32, DD/32, NHH), tb>>>(decy, pwdyT, DD, NN,
                                                       (long long)DD*NN, (long long)NN*DD);
    transpose_round_k<<<dim3(DD/32, (NHH*NN)/32, 1), tb>>>(enc, pencT, NHH*NN, DD, 0, 0);
    transpose_round_k<<<dim3(VV/32, DD/32, 1), tb>>>(lmh, plmhT, DD, VV, 0, 0);

    sincos_k<<<(TT * (NN / 2) + 255) / 256, 256>>>();
    embed_ln_k<<<TT, 192>>>(idx, emb, pos);

    for (int l = 0; l < NLAYER; l++) {
        transpose_round_k<<<dim3(DD/32, TT/32, 1), tb>>>(pxr, pxT, TT, DD, 0, 0);

        // x_sparse(fp32) = relu(x @ decx[h]);  qr(tf32) = rope(x_sparse)
        gemm_wide<1><<<dim3(NN / 256, TT / 128, NHH), 512, SMEM2>>>(
            pxr, pwdxT, pxs, pqr, prt, NN, DD, DD, DD, NN,
            0LL, (long long)NN * DD, (long long)TT * NN, (long long)TT * NN);

        // scores(tf32) = (qr @ qr^T) * tril(-1)
        gemm_wide<3><<<dim3(TT / 256, TT / 128, NHH), 512, SMEM2>>>(
            pqr, pqr, psc, nullptr, nullptr, TT, NN, NN, NN, TT,
            (long long)TT * NN, (long long)TT * NN, (long long)TT * TT, 0LL);

        // ykv partials(fp32) = scores @ x   (split-K=4; bz = h*4+kz)
        gemm_mma<2><<<dim3(2, TT / 128, NHH * 4), 256, SMEM1>>>(
            psc, pxT, ppart, DD, TT / 4, TT, TT, DD,
            (long long)TT * TT, 0LL, (long long)TT * DD);

        // ykv = ln(sum partials) -> tf32
        ln_ykv_k<<<NHH * TT, 192>>>();

        // xy(tf32) = relu(ykv @ decy[h]) * x_sparse(fp32)
        gemm_wide<2><<<dim3(NN / 256, TT / 128, NHH), 512, SMEM2>>>(
            pykv, pwdyT, pqr, pxs, nullptr, NN, DD, DD, DD, NN,
            (long long)TT * DD, (long long)NN * DD, (long long)TT * NN,
            (long long)TT * NN);

        // ymlp partials(fp32): xy @ enc^T, split-K = 16
        gemm_mma<1><<<dim3(2, TT / 128, KSPLIT), 256, SMEM1>>>(
            pqr, pencT, ppart, DD, KCH, NN, NHH * NN, DD,
            0LL, (long long)KCH, (long long)TT * DD);

        finalize_k<<<TT, 192>>>();
    }

    // logits(fp32) = x @ lm_head
    gemm_mma<0><<<dim3(2, TT / 128, 1), 256, SMEM1>>>(
        pxr, plmhT, out, VV, DD, DD, DD, VV,
        0LL, 0LL, 0LL);
}

// round 10
// speedup vs baseline: 4.8507x; 1.2395x over previous
#include <cuda_runtime.h>
#include <math.h>
#include <stdint.h>

// Problem constants
#define TT 1024
#define DD 192
#define NHH 4
#define NN 3072
#define VV 256
#define NLAYER 4
#define KSPLIT 16
#define KCH ((NHH*NN)/KSPLIT)   // 768
#define NSTAGE 3
#define BK 32
#define SROW 36                  // floats per smem row (32 + 4 pad)
#define A_ST1 (128*SROW)
#define A_ST2 (128*SROW)
#define B_ST2 (256*SROW)

// ---------------------------------------------------------------------------
// Static device scratch (no allocation allowed) -- 16B aligned for cp.async
// ---------------------------------------------------------------------------
__device__ __align__(16) float  g_x[TT*DD];        // fp32 residual chain
__device__ __align__(16) float  g_xr[TT*DD];       // tf32-rounded copy (GEMM A)
__device__ __align__(16) float  g_xT[DD*TT];       // xr^T (GEMM B for ykv)
__device__ __align__(16) float  g_xs[NHH*TT*NN];   // fp32 (elementwise use only)
__device__ __align__(16) float  g_qr[NHH*TT*NN];   // tf32; later reused as xy (tf32)
__device__ __align__(16) float  g_sc[NHH*TT*TT];   // tf32 masked scores
__device__ __align__(16) float  g_scp[2*NHH*TT*TT];// scores split-K partials (fp32)
__device__ __align__(16) float  g_ykv[NHH*TT*DD];  // tf32 after ln
__device__ __align__(16) float  g_part[KSPLIT*TT*DD];
__device__ __align__(16) float2 g_rt[TT*(NN/2)];   // rope (cos,sin)
__device__ __align__(16) float  g_wdxT[NHH*NN*DD];
__device__ __align__(16) float  g_wdyT[NHH*NN*DD];
__device__ __align__(16) float  g_encT[DD*NHH*NN];
__device__ __align__(16) float  g_lmhT[VV*DD];

__device__ __forceinline__ uint32_t tf32r(float x) {
    uint32_t y;
    asm("cvt.rna.tf32.f32 %0, %1;" : "=r"(y) : "f"(x));
    return y;
}
__device__ __forceinline__ float tf32f(float x) { return __uint_as_float(tf32r(x)); }
__device__ __forceinline__ uint32_t su32(const void* p) {
    uint32_t a;
    asm("{ .reg .u64 t; cvta.to.shared.u64 t, %1; cvt.u32.u64 %0, t; }"
        : "=r"(a) : "l"(p));
    return a;
}
__device__ __forceinline__ void cp16(uint32_t dst, const void* src, bool full) {
    int sz = full ? 16 : 0;
    asm volatile("cp.async.cg.shared.global [%0], [%1], 16, %2;"
                 :: "r"(dst), "l"(src), "r"(sz) : "memory");
}
__device__ __forceinline__ void mma8(float c[4], const uint32_t a[4], const uint32_t b[2]) {
    asm volatile(
        "mma.sync.aligned.m16n8k8.row.col.f32.tf32.tf32.f32 "
        "{%0,%1,%2,%3}, {%4,%5,%6,%7}, {%8,%9}, {%0,%1,%2,%3};"
        : "+f"(c[0]), "+f"(c[1]), "+f"(c[2]), "+f"(c[3])
        : "r"(a[0]), "r"(a[1]), "r"(a[2]), "r"(a[3]), "r"(b[0]), "r"(b[1]));
}
__device__ __forceinline__ void ldsm4(uint32_t d[4], uint32_t addr) {
    asm volatile("ldmatrix.sync.aligned.m8n8.x4.shared.b16 {%0,%1,%2,%3}, [%4];"
                 : "=r"(d[0]), "=r"(d[1]), "=r"(d[2]), "=r"(d[3]) : "r"(addr));
}

// ---------------------------------------------------------------------------
// Kernel 1: tile 128x128, 256 thr (8 warps 4m x 2n), plain fp32 out.
// C[M,Nc] = A[M,K] @ B[Nc,K]^T
// AZM: 0 normal | 1 ymlp split-K | 2 ykv split-K4 |
//      3 scores: triangular tile map (bx<=by) + K-split2 partials
// ---------------------------------------------------------------------------
template<int AZM>
__global__ __launch_bounds__(256, 2)
void gemm_mma(const float* __restrict__ A, const float* __restrict__ B,
              float* __restrict__ C,
              int Nc, int K, int lda, int ldb, int ldc,
              long long sA, long long sB, long long sC)
{
    extern __shared__ float smf[];
    float* sA_f = smf;
    float* sB_f = smf + NSTAGE * A_ST1;

    const int bx = blockIdx.x, by = blockIdx.y, bz = blockIdx.z;
    const int tid = threadIdx.x;
    const int wid = tid >> 5, lane = tid & 31;
    const int grp = lane >> 2, qid = lane & 3;
    const int wm0 = (wid & 3) * 32, wn0 = (wid >> 2) * 64;

    int row0, col0;
    if (AZM == 3) {
        int bid = bx;                      // 0..35 triangular
        int by3 = (int)((sqrtf(8.f * bid + 1.f) - 1.f) * 0.5f);
        while ((by3 + 1) * (by3 + 2) / 2 <= bid) by3++;
        while (by3 * (by3 + 1) / 2 > bid)       by3--;
        row0 = by3 * 128;
        col0 = (bid - by3 * (by3 + 1) / 2) * 128;
    } else {
        row0 = by * 128; col0 = bx * 128;
    }

    int koff = 0;
    if (AZM == 3) {                        // bz = h*2 + ks
        long long hoff = (long long)(bz >> 1) * sA + (long long)(bz & 1) * K;
        A += hoff; B += hoff;
    } else if (AZM == 2) {
        A += (long long)(bz >> 2) * sA + (bz & 3) * 256;
        B += (bz & 3) * 256;
    } else if (AZM == 1) {
        koff = bz * KCH;
        B += (long long)bz * sB;
    } else {
        A += (long long)bz * sA;
        B += (long long)bz * sB;
    }
    C += (long long)bz * sC;

    const uint32_t sA_u = su32(sA_f);
    const uint32_t sB_u = su32(sB_f);

    const int rowA = (lane & 7) + ((lane >> 3) & 1) * 8;
    const int kA   = ((lane >> 4) & 1) * 4;
    const int rowB = (lane & 7) + ((lane >> 4) & 1) * 8;
    const int kB   = ((lane >> 3) & 1) * 4;
    const uint32_t aBase = sA_u + 4u * ((wm0 + rowA) * SROW + kA);
    const uint32_t bBase = sB_u + 4u * ((wn0 + rowB) * SROW + kB);

    float acc[2][8][4];
    #pragma unroll
    for (int mi = 0; mi < 2; mi++)
        #pragma unroll
        for (int ni = 0; ni < 8; ni++)
            #pragma unroll
            for (int j = 0; j < 4; j++) acc[mi][ni][j] = 0.f;

    const int nch = K / BK;

    auto issue = [&](int s) {
        const int k0 = s * BK;
        const int buf = s % NSTAGE;
        #pragma unroll
        for (int it = 0; it < 4; it++) {
            int idx4 = tid + it * 256;
            int r = idx4 >> 3, kc = (idx4 & 7) << 2;
            const float* src;
            if (AZM == 1) {
                int gk = koff + k0 + kc;
                int hh = gk / NN, nn = gk - hh * NN;
                src = A + (size_t)hh * TT * NN + (size_t)(row0 + r) * lda + nn;
            } else {
                src = A + (size_t)(row0 + r) * lda + k0 + kc;
            }
            cp16(sA_u + (buf * A_ST1 + r * SROW + kc) * 4, src, true);
        }
        #pragma unroll
        for (int it = 0; it < 4; it++) {
            int idx4 = tid + it * 256;
            int nr = idx4 >> 3, kc = (idx4 & 7) << 2;
            const float* src = B + (size_t)(col0 + nr) * ldb + k0 + kc;
            cp16(sB_u + (buf * A_ST1 + nr * SROW + kc) * 4, src, col0 + nr < Nc);
        }
        asm volatile("cp.async.commit_group;" ::: "memory");
    };

    #pragma unroll
    for (int s = 0; s < NSTAGE - 1; s++) issue(s);

    for (int c = 0; c < nch; c++) {
        asm volatile("cp.async.wait_group %0;" :: "n"(NSTAGE - 2) : "memory");
        __syncthreads();
        if (c + NSTAGE - 1 < nch) issue(c + NSTAGE - 1);

        const int buf = c % NSTAGE;
        const uint32_t aOff = aBase + 4u * buf * A_ST1;
        const uint32_t bOff = bBase + 4u * buf * A_ST1;
        #pragma unroll
        for (int ks = 0; ks < BK; ks += 8) {
            uint32_t af[2][4], bf8[8][2];
            #pragma unroll
            for (int mi = 0; mi < 2; mi++)
                ldsm4(af[mi], aOff + 4u * (mi * 16 * SROW + ks));
            #pragma unroll
            for (int p = 0; p < 4; p++) {
                uint32_t t4[4];
                ldsm4(t4, bOff + 4u * (p * 16 * SROW + ks));
                bf8[2 * p    ][0] = t4[0]; bf8[2 * p    ][1] = t4[1];
                bf8[2 * p + 1][0] = t4[2]; bf8[2 * p + 1][1] = t4[3];
            }
            #pragma unroll
            for (int mi = 0; mi < 2; mi++)
                #pragma unroll
                for (int ni = 0; ni < 8; ni++)
                    mma8(acc[mi][ni], af[mi], bf8[ni]);
        }
    }

    #pragma unroll
    for (int mi = 0; mi < 2; mi++) {
        const int rA = row0 + wm0 + mi * 16 + grp;
        const int rB = rA + 8;
        #pragma unroll
        for (int ni = 0; ni < 8; ni++) {
            const int c = col0 + wn0 + ni * 8 + (qid << 1);
            if (c >= Nc) continue;
            *(float2*)(C + (size_t)rA * ldc + c) = make_float2(acc[mi][ni][0], acc[mi][ni][1]);
            *(float2*)(C + (size_t)rB * ldc + c) = make_float2(acc[mi][ni][2], acc[mi][ni][3]);
        }
    }
}

// ---------------------------------------------------------------------------
// Kernel 2: tile 128x256, 512 thr (16 warps 4m x 4n), warp tile 32x64.
// EPI: 1 relu->fp32 C (+fused rope -> aux tf32) | 2 relu*aux -> tf32
// ---------------------------------------------------------------------------
template<int EPI>
__global__ __launch_bounds__(512, 1)
void gemm_wide(const float* __restrict__ A, const float* __restrict__ B,
               float* __restrict__ C, const float* __restrict__ aux,
               const float2* __restrict__ rtab,
               int Nc, int K, int lda, int ldb, int ldc,
               long long sA, long long sB, long long sC, long long sAux)
{
    extern __shared__ float smf[];
    float* sA_f = smf;
    float* sB_f = smf + NSTAGE * A_ST2;

    const int bx = blockIdx.x, by = blockIdx.y, bz = blockIdx.z;
    const int tid = threadIdx.x;
    const int wid = tid >> 5, lane = tid & 31;
    const int grp = lane >> 2, qid = lane & 3;
    const int wm0 = (wid & 3) * 32, wn0 = (wid >> 2) * 64;
    const int row0 = by * 128, col0 = bx * 256;

    A += (long long)bz * sA;
    B += (long long)bz * sB;
    C += (long long)bz * sC;
    const float* auxr = aux ? aux + (long long)bz * sAux : aux;
    float*       qout = (float*)auxr;

    const uint32_t sA_u = su32(sA_f);
    const uint32_t sB_u = su32(sB_f);

    const int rowA = (lane & 7) + ((lane >> 3) & 1) * 8;
    const int kA   = ((lane >> 4) & 1) * 4;
    const int rowB = (lane & 7) + ((lane >> 4) & 1) * 8;
    const int kB   = ((lane >> 3) & 1) * 4;
    const uint32_t aBase = sA_u + 4u * ((wm0 + rowA) * SROW + kA);
    const uint32_t bBase = sB_u + 4u * ((wn0 + rowB) * SROW + kB);

    float acc[2][8][4];
    #pragma unroll
    for (int mi = 0; mi < 2; mi++)
        #pragma unroll
        for (int ni = 0; ni < 8; ni++)
            #pragma unroll
            for (int j = 0; j < 4; j++) acc[mi][ni][j] = 0.f;

    const int nch = K / BK;

    auto issue = [&](int s) {
        const int k0 = s * BK;
        const int buf = s % NSTAGE;
        #pragma unroll
        for (int it = 0; it < 2; it++) {
            int idx4 = tid + it * 512;
            int r = idx4 >> 3, kc = (idx4 & 7) << 2;
            const float* src = A + (size_t)(row0 + r) * lda + k0 + kc;
            cp16(sA_u + (buf * A_ST2 + r * SROW + kc) * 4, src, true);
        }
        #pragma unroll
        for (int it = 0; it < 4; it++) {
            int idx4 = tid + it * 512;
            int nr = idx4 >> 3, kc = (idx4 & 7) << 2;
            const float* src = B + (size_t)(col0 + nr) * ldb + k0 + kc;
            cp16(sB_u + (buf * B_ST2 + nr * SROW + kc) * 4, src, col0 + nr < Nc);
        }
        asm volatile("cp.async.commit_group;" ::: "memory");
    };

    #pragma unroll
    for (int s = 0; s < NSTAGE - 1; s++) issue(s);

    for (int c = 0; c < nch; c++) {
        asm volatile("cp.async.wait_group %0;" :: "n"(NSTAGE - 2) : "memory");
        __syncthreads();
        if (c + NSTAGE - 1 < nch) issue(c + NSTAGE - 1);

        const int buf = c % NSTAGE;
        const uint32_t aOff = aBase + 4u * buf * A_ST2;
        const uint32_t bOff = bBase + 4u * buf * B_ST2;
        #pragma unroll
        for (int ks = 0; ks < BK; ks += 8) {
            uint32_t af[2][4], bf8[8][2];
            #pragma unroll
            for (int mi = 0; mi < 2; mi++)
                ldsm4(af[mi], aOff + 4u * (mi * 16 * SROW + ks));
            #pragma unroll
            for (int p = 0; p < 4; p++) {
                uint32_t t4[4];
                ldsm4(t4, bOff + 4u * (p * 16 * SROW + ks));
                bf8[2 * p    ][0] = t4[0]; bf8[2 * p    ][1] = t4[1];
                bf8[2 * p + 1][0] = t4[2]; bf8[2 * p + 1][1] = t4[3];
            }
            #pragma unroll
            for (int mi = 0; mi < 2; mi++)
                #pragma unroll
                for (int ni = 0; ni < 8; ni++)
                    mma8(acc[mi][ni], af[mi], bf8[ni]);
        }
    }

    // ---- epilogue ----
    #pragma unroll
    for (int mi = 0; mi < 2; mi++) {
        const int rA = row0 + wm0 + mi * 16 + grp;
        const int rB = rA + 8;
        #pragma unroll
        for (int ni = 0; ni < 8; ni++) {
            const int c = col0 + wn0 + ni * 8 + (qid << 1);
            float2 lo = make_float2(acc[mi][ni][0], acc[mi][ni][1]);
            float2 hi = make_float2(acc[mi][ni][2], acc[mi][ni][3]);
            if (EPI == 1) {
                lo.x = fmaxf(lo.x, 0.f); lo.y = fmaxf(lo.y, 0.f);
                hi.x = fmaxf(hi.x, 0.f); hi.y = fmaxf(hi.y, 0.f);
                *(float2*)(C + (size_t)rA * ldc + c) = lo;
                *(float2*)(C + (size_t)rB * ldc + c) = hi;
                float2 ca = rtab[(size_t)rA * (NN / 2) + (c >> 1)];
                float2 cb = rtab[(size_t)rB * (NN / 2) + (c >> 1)];
                float2 qa, qb;
                qa.x = tf32f(lo.x * ca.x - lo.y * ca.y);
                qa.y = tf32f(lo.y * ca.x + lo.x * ca.y);
                qb.x = tf32f(hi.x * cb.x - hi.y * cb.y);
                qb.y = tf32f(hi.y * cb.x + hi.x * cb.y);
                *(float2*)(qout + (size_t)rA * ldc + c) = qa;
                *(float2*)(qout + (size_t)rB * ldc + c) = qb;
            } else { // EPI == 2
                float2 ea = *(const float2*)(auxr + (size_t)rA * ldc + c);
                float2 eb = *(const float2*)(auxr + (size_t)rB * ldc + c);
                lo.x = tf32f(fmaxf(lo.x, 0.f) * ea.x); lo.y = tf32f(fmaxf(lo.y, 0.f) * ea.y);
                hi.x = tf32f(fmaxf(hi.x, 0.f) * eb.x); hi.y = tf32f(fmaxf(hi.y, 0.f) * eb.y);
                *(float2*)(C + (size_t)rA * ldc + c) = lo;
                *(float2*)(C + (size_t)rB * ldc + c) = hi;
            }
        }
    }
}

// ---------------------------------------------------------------------------
// scores reduce: g_sc = tril_mask(tf32(p0 + p1)); zero above diagonal
// ---------------------------------------------------------------------------
__global__ void reduce_sc_k()
{
    long long i = (long long)blockIdx.x * 256 + threadIdx.x;  // float4 units
    int c  = (int)(i & (TT / 4 - 1)) << 2;
    int r  = (int)(i >> 8) & (TT - 1);
    int h  = (int)(i >> 18);
    float4 o;
    if (c >= r) {
        o = make_float4(0.f, 0.f, 0.f, 0.f);
    } else {
        size_t off = (size_t)r * TT + c;
        float4 p0 = *(const float4*)(g_scp + (size_t)(h * 2    ) * TT * TT + off);
        float4 p1 = *(const float4*)(g_scp + (size_t)(h * 2 + 1) * TT * TT + off);
        o.x = (c     < r) ? tf32f(p0.x + p1.x) : 0.f;
        o.y = (c + 1 < r) ? tf32f(p0.y + p1.y) : 0.f;
        o.z = (c + 2 < r) ? tf32f(p0.z + p1.z) : 0.f;
        o.w = (c + 3 < r) ? tf32f(p0.w + p1.w) : 0.f;
    }
    *(float4*)(g_sc + (size_t)h * TT * TT + (size_t)r * TT + c) = o;
}

// ---------------------------------------------------------------------------
__global__ void transpose_round_k(const float* __restrict__ in, float* __restrict__ out,
                                  int M, int Nn, long long inS, long long outS)
{
    __shared__ float t[32][33];
    in  += (long long)blockIdx.z * inS;
    out += (long long)blockIdx.z * outS;
    int x = blockIdx.x * 32 + threadIdx.x;
    int y = blockIdx.y * 32 + threadIdx.y;
    #pragma unroll
    for (int i = 0; i < 32; i += 8)
        t[threadIdx.y + i][threadIdx.x] = in[(size_t)(y + i) * Nn + x];
    __syncthreads();
    int x2 = blockIdx.y * 32 + threadIdx.x;
    int y2 = blockIdx.x * 32 + threadIdx.y;
    #pragma unroll
    for (int i = 0; i < 32; i += 8)
        out[(size_t)(y2 + i) * M + x2] = tf32f(t[threadIdx.x][threadIdx.y + i]);
}

// ---------------------------------------------------------------------------
__device__ __forceinline__ float2 meanvar192(float v, float* s1, float* s2)
{
    __syncthreads();
    float a = v, b = v * v;
    #pragma unroll
    for (int o = 16; o > 0; o >>= 1) {
        a += __shfl_down_sync(0xffffffffu, a, o);
        b += __shfl_down_sync(0xffffffffu, b, o);
    }
    int lane = threadIdx.x & 31, w = threadIdx.x >> 5;
    if (lane == 0) { s1[w] = a; s2[w] = b; }
    __syncthreads();
    if (threadIdx.x == 0) {
        float sa = 0.f, sb = 0.f;
        #pragma unroll
        for (int i = 0; i < 6; i++) { sa += s1[i]; sb += s2[i]; }
        s1[0] = sa; s2[0] = sb;
    }
    __syncthreads();
    float m   = s1[0] * (1.0f / 192.0f);
    float var = s2[0] * (1.0f / 192.0f) - m * m;
    return make_float2(m, fmaxf(var, 0.f));
}

__global__ void embed_ln_k(const int* __restrict__ idx,
                           const float* __restrict__ emb,
                           const float* __restrict__ pos)
{
    int t = blockIdx.x, d = threadIdx.x;
    __shared__ float s1[8], s2[8];
    float v = emb[(size_t)idx[t] * DD + d] + pos[(size_t)t * DD + d];
    float2 mv = meanvar192(v, s1, s2);
    float r = (v - mv.x) * rsqrtf(mv.y + 1e-5f);
    g_x [(size_t)t * DD + d] = r;
    g_xr[(size_t)t * DD + d] = tf32f(r);
}

__global__ void sincos_k()
{
    int i = blockIdx.x * blockDim.x + threadIdx.x;
    if (i >= TT * (NN / 2)) return;
    int t = i / (NN / 2);
    int p = i - t * (NN / 2);
    float f = exp2f(-(float)p * (1.0f / 96.0f)) * 0.15915494309189535f;
    float ph = fmodf((float)t * f, 1.0f) * 6.283185307179586f;
    float s, c;
    sincosf(ph, &s, &c);
    g_rt[i] = make_float2(c, s);
}

__global__ void ln_ykv_k()
{
    int r = blockIdx.x, d = threadIdx.x;     // r = h*TT + t
    __shared__ float s1[8], s2[8];
    int h = r >> 10, t = r & (TT - 1);
    float v = 0.f;
    #pragma unroll
    for (int kz = 0; kz < 4; kz++)
        v += g_part[(size_t)(h * 4 + kz) * TT * DD + (size_t)t * DD + d];
    float2 mv = meanvar192(v, s1, s2);
    g_ykv[(size_t)r * DD + d] = tf32f((v - mv.x) * rsqrtf(mv.y + 1e-5f));
}

__global__ void finalize_k()
{
    int t = blockIdx.x, d = threadIdx.x;
    __shared__ float s1[8], s2[8];
    float ym = 0.f;
    #pragma unroll
    for (int c = 0; c < KSPLIT; c++)
        ym += g_part[(size_t)c * TT * DD + (size_t)t * DD + d];
    float2 mv = meanvar192(ym, s1, s2);
    float l1 = (ym - mv.x) * rsqrtf(mv.y + 1e-5f);
    float xv = g_x[(size_t)t * DD + d] + l1;
    float2 mv2 = meanvar192(xv, s1, s2);
    float r = (xv - mv2.x) * rsqrtf(mv2.y + 1e-5f);
    g_x [(size_t)t * DD + d] = r;
    g_xr[(size_t)t * DD + d] = tf32f(r);
}

// ---------------------------------------------------------------------------
extern "C" void kernel_launch(void* const* d_in, const int* in_sizes, int n_in,
                              void* d_out, int out_size)
{
    const int*   idx  = (const int*)  d_in[0];
    const float* decx = (const float*)d_in[1];
    const float* decy = (const float*)d_in[2];
    const float* enc  = (const float*)d_in[3];
    const float* emb  = (const float*)d_in[4];
    const float* pos  = (const float*)d_in[5];
    const float* lmh  = (const float*)d_in[6];
    float* out = (float*)d_out;

    float *pxr, *pxT, *pxs, *pqr, *psc, *pscp, *ppart, *pwdxT, *pwdyT, *pencT, *plmhT, *pykv;
    float2* prt;
    cudaGetSymbolAddress((void**)&pxr,   g_xr);
    cudaGetSymbolAddress((void**)&pxT,   g_xT);
    cudaGetSymbolAddress((void**)&pxs,   g_xs);
    cudaGetSymbolAddress((void**)&pqr,   g_qr);
    cudaGetSymbolAddress((void**)&psc,   g_sc);
    cudaGetSymbolAddress((void**)&pscp,  g_scp);
    cudaGetSymbolAddress((void**)&pykv,  g_ykv);
    cudaGetSymbolAddress((void**)&ppart, g_part);
    cudaGetSymbolAddress((void**)&prt,   g_rt);
    cudaGetSymbolAddress((void**)&pwdxT, g_wdxT);
    cudaGetSymbolAddress((void**)&pwdyT, g_wdyT);
    cudaGetSymbolAddress((void**)&pencT, g_encT);
    cudaGetSymbolAddress((void**)&plmhT, g_lmhT);

    const int SMEM1 = NSTAGE * 2 * A_ST1 * 4;            // 110592 B
    const int SMEM2 = NSTAGE * (A_ST2 + B_ST2) * 4;      // 165888 B
    cudaFuncSetAttribute(gemm_mma<0>,  cudaFuncAttributeMaxDynamicSharedMemorySize, SMEM1);
    cudaFuncSetAttribute(gemm_mma<1>,  cudaFuncAttributeMaxDynamicSharedMemorySize, SMEM1);
    cudaFuncSetAttribute(gemm_mma<2>,  cudaFuncAttributeMaxDynamicSharedMemorySize, SMEM1);
    cudaFuncSetAttribute(gemm_mma<3>,  cudaFuncAttributeMaxDynamicSharedMemorySize, SMEM1);
    cudaFuncSetAttribute(gemm_wide<1>, cudaFuncAttributeMaxDynamicSharedMemorySize, SMEM2);
    cudaFuncSetAttribute(gemm_wide<2>, cudaFuncAttributeMaxDynamicSharedMemorySize, SMEM2);

    dim3 tb(32, 8);
    transpose_round_k<<<dim3(NN/32, DD/32, NHH), tb>>>(decx, pwdxT, DD, NN,
                                                       (long long)DD*NN, (long long)NN*DD);
    transpose_round_k<<<dim3(NN/32, DD/32, NHH), tb>>>(decy, pwdyT, DD, NN,
                                                       (long long)DD*NN, (long long)NN*DD);
    transpose_round_k<<<dim3(DD/32, (NHH*NN)/32, 1), tb>>>(enc, pencT, NHH*NN, DD, 0, 0);
    transpose_round_k<<<dim3(VV/32, DD/32, 1), tb>>>(lmh, plmhT, DD, VV, 0, 0);

    sincos_k<<<(TT * (NN / 2) + 255) / 256, 256>>>();
    embed_ln_k<<<TT, 192>>>(idx, emb, pos);

    for (int l = 0; l < NLAYER; l++) {
        transpose_round_k<<<dim3(DD/32, TT/32, 1), tb>>>(pxr, pxT, TT, DD, 0, 0);

        // x_sparse(fp32) = relu(x @ decx[h]);  qr(tf32) = rope(x_sparse)
        gemm_wide<1><<<dim3(NN / 256, TT / 128, NHH), 512, SMEM2>>>(
            pxr, pwdxT, pxs, pqr, prt, NN, DD, DD, DD, NN,
            0LL, (long long)NN * DD, (long long)TT * NN, (long long)TT * NN);

        // scores partials: lower-triangle tiles only, K split in 2 (bz = h*2+ks)
        gemm_mma<3><<<dim3(36, 1, NHH * 2), 256, SMEM1>>>(
            pqr, pqr, pscp, TT, NN / 2, NN, NN, TT,
            (long long)TT * NN, 0LL, (long long)TT * TT);

        // g_sc = tril_mask(tf32(p0+p1)), zero above
        reduce_sc_k<<<NHH * TT * TT / 4 / 256, 256>>>();

        // ykv partials(fp32) = scores @ x   (split-K=4; bz = h*4+kz)
        gemm_mma<2><<<dim3(2, TT / 128, NHH * 4), 256, SMEM1>>>(
            psc, pxT, ppart, DD, TT / 4, TT, TT, DD,
            (long long)TT * TT, 0LL, (long long)TT * DD);

        // ykv = ln(sum partials) -> tf32
        ln_ykv_k<<<NHH * TT, 192>>>();

        // xy(tf32) = relu(ykv @ decy[h]) * x_sparse(fp32)
        gemm_wide<2><<<dim3(NN / 256, TT / 128, NHH), 512, SMEM2>>>(
            pykv, pwdyT, pqr, pxs, nullptr, NN, DD, DD, DD, NN,
            (long long)TT * DD, (long long)NN * DD, (long long)TT * NN,
            (long long)TT * NN);

        // ymlp partials(fp32): xy @ enc^T, split-K = 16
        gemm_mma<1><<<dim3(2, TT / 128, KSPLIT), 256, SMEM1>>>(
            pqr, pencT, ppart, DD, KCH, NN, NHH * NN, DD,
            0LL, (long long)KCH, (long long)TT * DD);

        finalize_k<<<TT, 192>>>();
    }

    // logits(fp32) = x @ lm_head
    gemm_mma<0><<<dim3(2, TT / 128, 1), 256, SMEM1>>>(
        pxr, plmhT, out, VV, DD, DD, DD, VV,
        0LL, 0LL, 0LL);
}

// round 11
// speedup vs baseline: 7.4293x; 1.5316x over previous
#include <cuda_runtime.h>
#include <cuda_fp16.h>
#include <math.h>
#include <stdint.h>

// Problem constants
#define TT 1024
#define DD 192
#define NHH 4
#define NN 3072
#define VV 256
#define NLAYER 4
#define KSPLIT 16
#define KCH ((NHH*NN)/KSPLIT)   // 768
#define NSTAGE 3
#define BK 64
#define SROWH 72                 // halves per smem row (64 + 8 pad)
#define ST1_H (128*SROWH)        // halves per stage (128-row operand)
#define STA_H (128*SROWH)
#define STB_H (256*SROWH)

// ---------------------------------------------------------------------------
// Static device scratch -- 16B aligned for cp.async
// ---------------------------------------------------------------------------
__device__ __align__(16) float   g_x[TT*DD];        // fp32 residual chain
__device__ __align__(16) __half  g_xr[TT*DD];       // fp16 copy (GEMM A)
__device__ __align__(16) __half  g_xT[DD*TT];       // fp16 x^T (GEMM B for ykv)
__device__ __align__(16) float   g_xs[NHH*TT*NN];   // fp32 (elementwise use only)
__device__ __align__(16) __half  g_qr[NHH*TT*NN];   // fp16 qr; reused as xy
__device__ __align__(16) __half  g_sc[NHH*TT*TT];   // fp16 masked scores
__device__ __align__(16) float   g_scp[2*NHH*TT*TT];// scores split-K partials
__device__ __align__(16) __half  g_ykv[NHH*TT*DD];  // fp16 after ln
__device__ __align__(16) float   g_part[KSPLIT*TT*DD];
__device__ __align__(16) float2  g_rt[TT*(NN/2)];
__device__ __align__(16) __half  g_wdxT[NHH*NN*DD];
__device__ __align__(16) __half  g_wdyT[NHH*NN*DD];
__device__ __align__(16) __half  g_encT[DD*NHH*NN];
__device__ __align__(16) __half  g_lmhT[VV*DD];

__device__ __forceinline__ uint32_t su32(const void* p) {
    uint32_t a;
    asm("{ .reg .u64 t; cvta.to.shared.u64 t, %1; cvt.u32.u64 %0, t; }"
        : "=r"(a) : "l"(p));
    return a;
}
__device__ __forceinline__ void cp16(uint32_t dst, const void* src, bool full) {
    int sz = full ? 16 : 0;
    asm volatile("cp.async.cg.shared.global [%0], [%1], 16, %2;"
                 :: "r"(dst), "l"(src), "r"(sz) : "memory");
}
__device__ __forceinline__ void mma16(float c[4], const uint32_t a[4], const uint32_t b[2]) {
    asm volatile(
        "mma.sync.aligned.m16n8k16.row.col.f32.f16.f16.f32 "
        "{%0,%1,%2,%3}, {%4,%5,%6,%7}, {%8,%9}, {%0,%1,%2,%3};"
        : "+f"(c[0]), "+f"(c[1]), "+f"(c[2]), "+f"(c[3])
        : "r"(a[0]), "r"(a[1]), "r"(a[2]), "r"(a[3]), "r"(b[0]), "r"(b[1]));
}
__device__ __forceinline__ void ldsm4(uint32_t d[4], uint32_t addr) {
    asm volatile("ldmatrix.sync.aligned.m8n8.x4.shared.b16 {%0,%1,%2,%3}, [%4];"
                 : "=r"(d[0]), "=r"(d[1]), "=r"(d[2]), "=r"(d[3]) : "r"(addr));
}
__device__ __forceinline__ uint32_t packh2(float a, float b) {
    __half2 h = __floats2half2_rn(a, b);
    return *(uint32_t*)&h;
}
__device__ __forceinline__ __half h1(float a) { return __float2half_rn(a); }

// ---------------------------------------------------------------------------
// Kernel 1: tile 128x128, 256 thr (8 warps 4m x 2n), fp16 in, fp32 out.
// C[M,Nc] = A[M,K] @ B[Nc,K]^T
// AZM: 0 normal | 1 ymlp split-K | 2 ykv split-K4 | 3 scores tri + K-split2
// ---------------------------------------------------------------------------
template<int AZM>
__global__ __launch_bounds__(256, 2)
void gemm_mma(const __half* __restrict__ A, const __half* __restrict__ B,
              float* __restrict__ C,
              int Nc, int K, int lda, int ldb, int ldc,
              long long sA, long long sB, long long sC)
{
    extern __shared__ __half smh[];
    const uint32_t sA_u = su32(smh);
    const uint32_t sB_u = su32(smh + NSTAGE * ST1_H);

    const int bx = blockIdx.x, by = blockIdx.y, bz = blockIdx.z;
    const int tid = threadIdx.x;
    const int wid = tid >> 5, lane = tid & 31;
    const int grp = lane >> 2, qid = lane & 3;
    const int wm0 = (wid & 3) * 32, wn0 = (wid >> 2) * 64;

    int row0, col0;
    if (AZM == 3) {
        int bid = bx;
        int by3 = (int)((sqrtf(8.f * bid + 1.f) - 1.f) * 0.5f);
        while ((by3 + 1) * (by3 + 2) / 2 <= bid) by3++;
        while (by3 * (by3 + 1) / 2 > bid)       by3--;
        row0 = by3 * 128;
        col0 = (bid - by3 * (by3 + 1) / 2) * 128;
    } else {
        row0 = by * 128; col0 = bx * 128;
    }

    int koff = 0;
    if (AZM == 3) {
        long long hoff = (long long)(bz >> 1) * sA + (long long)(bz & 1) * K;
        A += hoff; B += hoff;
    } else if (AZM == 2) {
        A += (long long)(bz >> 2) * sA + (bz & 3) * 256;
        B += (bz & 3) * 256;
    } else if (AZM == 1) {
        koff = bz * KCH;
        B += (long long)bz * sB;
    } else {
        A += (long long)bz * sA;
        B += (long long)bz * sB;
    }
    C += (long long)bz * sC;

    // ldmatrix per-lane bases (halves)
    const int rowA = (lane & 7) + ((lane >> 3) & 1) * 8;
    const int kA   = ((lane >> 4) & 1) * 8;
    const int rowB = (lane & 7) + ((lane >> 4) & 1) * 8;
    const int kB   = ((lane >> 3) & 1) * 8;
    const uint32_t aBase = sA_u + 2u * ((wm0 + rowA) * SROWH + kA);
    const uint32_t bBase = sB_u + 2u * ((wn0 + rowB) * SROWH + kB);

    float acc[2][8][4];
    #pragma unroll
    for (int mi = 0; mi < 2; mi++)
        #pragma unroll
        for (int ni = 0; ni < 8; ni++)
            #pragma unroll
            for (int j = 0; j < 4; j++) acc[mi][ni][j] = 0.f;

    const int nch = K / BK;

    auto issue = [&](int s) {
        const int k0 = s * BK;
        const int buf = s % NSTAGE;
        #pragma unroll
        for (int it = 0; it < 4; it++) {
            int idx = tid + it * 256;          // 0..1023
            int r = idx >> 3, kc = (idx & 7) << 3;   // kc in halves
            const __half* src;
            if (AZM == 1) {
                int gk = koff + k0 + kc;
                int hh = gk / NN, nn = gk - hh * NN;
                src = A + (size_t)hh * TT * NN + (size_t)(row0 + r) * lda + nn;
            } else {
                src = A + (size_t)(row0 + r) * lda + k0 + kc;
            }
            cp16(sA_u + (buf * ST1_H + r * SROWH + kc) * 2, src, true);
        }
        #pragma unroll
        for (int it = 0; it < 4; it++) {
            int idx = tid + it * 256;
            int nr = idx >> 3, kc = (idx & 7) << 3;
            const __half* src = B + (size_t)(col0 + nr) * ldb + k0 + kc;
            cp16(sB_u + (buf * ST1_H + nr * SROWH + kc) * 2, src, col0 + nr < Nc);
        }
        asm volatile("cp.async.commit_group;" ::: "memory");
    };

    #pragma unroll
    for (int s = 0; s < NSTAGE - 1; s++) issue(s);

    for (int c = 0; c < nch; c++) {
        asm volatile("cp.async.wait_group %0;" :: "n"(NSTAGE - 2) : "memory");
        __syncthreads();
        if (c + NSTAGE - 1 < nch) issue(c + NSTAGE - 1);

        const int buf = c % NSTAGE;
        const uint32_t aOff = aBase + 2u * buf * ST1_H;
        const uint32_t bOff = bBase + 2u * buf * ST1_H;
        #pragma unroll
        for (int ks = 0; ks < BK; ks += 16) {
            uint32_t af[2][4], bf8[8][2];
            #pragma unroll
            for (int mi = 0; mi < 2; mi++)
                ldsm4(af[mi], aOff + 2u * (mi * 16 * SROWH + ks));
            #pragma unroll
            for (int p = 0; p < 4; p++) {
                uint32_t t4[4];
                ldsm4(t4, bOff + 2u * (p * 16 * SROWH + ks));
                bf8[2 * p    ][0] = t4[0]; bf8[2 * p    ][1] = t4[1];
                bf8[2 * p + 1][0] = t4[2]; bf8[2 * p + 1][1] = t4[3];
            }
            #pragma unroll
            for (int mi = 0; mi < 2; mi++)
                #pragma unroll
                for (int ni = 0; ni < 8; ni++)
                    mma16(acc[mi][ni], af[mi], bf8[ni]);
        }
    }

    #pragma unroll
    for (int mi = 0; mi < 2; mi++) {
        const int rA = row0 + wm0 + mi * 16 + grp;
        const int rB = rA + 8;
        #pragma unroll
        for (int ni = 0; ni < 8; ni++) {
            const int c = col0 + wn0 + ni * 8 + (qid << 1);
            if (c >= Nc) continue;
            *(float2*)(C + (size_t)rA * ldc + c) = make_float2(acc[mi][ni][0], acc[mi][ni][1]);
            *(float2*)(C + (size_t)rB * ldc + c) = make_float2(acc[mi][ni][2], acc[mi][ni][3]);
        }
    }
}

// ---------------------------------------------------------------------------
// Kernel 2: tile 128x256, 512 thr (16 warps 4m x 4n).
// EPI 1: C=xs fp32 = relu(acc); qr fp16 = rope(relu) -> auxp
// EPI 2: C=xy fp16 = relu(acc)*xs(fp32 auxp)
// ---------------------------------------------------------------------------
template<int EPI>
__global__ __launch_bounds__(512, 1)
void gemm_wide(const __half* __restrict__ A, const __half* __restrict__ B,
               void* __restrict__ Cv, void* __restrict__ auxp,
               const float2* __restrict__ rtab,
               int Nc, int K, int lda, int ldb, int ldc,
               long long sA, long long sB, long long sC, long long sAux)
{
    extern __shared__ __half smh[];
    const uint32_t sA_u = su32(smh);
    const uint32_t sB_u = su32(smh + NSTAGE * STA_H);

    const int bx = blockIdx.x, by = blockIdx.y, bz = blockIdx.z;
    const int tid = threadIdx.x;
    const int wid = tid >> 5, lane = tid & 31;
    const int grp = lane >> 2, qid = lane & 3;
    const int wm0 = (wid & 3) * 32, wn0 = (wid >> 2) * 64;
    const int row0 = by * 128, col0 = bx * 256;

    A += (long long)bz * sA;
    B += (long long)bz * sB;

    const int rowA = (lane & 7) + ((lane >> 3) & 1) * 8;
    const int kA   = ((lane >> 4) & 1) * 8;
    const int rowB = (lane & 7) + ((lane >> 4) & 1) * 8;
    const int kB   = ((lane >> 3) & 1) * 8;
    const uint32_t aBase = sA_u + 2u * ((wm0 + rowA) * SROWH + kA);
    const uint32_t bBase = sB_u + 2u * ((wn0 + rowB) * SROWH + kB);

    float acc[2][8][4];
    #pragma unroll
    for (int mi = 0; mi < 2; mi++)
        #pragma unroll
        for (int ni = 0; ni < 8; ni++)
            #pragma unroll
            for (int j = 0; j < 4; j++) acc[mi][ni][j] = 0.f;

    const int nch = K / BK;

    auto issue = [&](int s) {
        const int k0 = s * BK;
        const int buf = s % NSTAGE;
        #pragma unroll
        for (int it = 0; it < 2; it++) {
            int idx = tid + it * 512;          // 0..1023
            int r = idx >> 3, kc = (idx & 7) << 3;
            const __half* src = A + (size_t)(row0 + r) * lda + k0 + kc;
            cp16(sA_u + (buf * STA_H + r * SROWH + kc) * 2, src, true);
        }
        #pragma unroll
        for (int it = 0; it < 4; it++) {
            int idx = tid + it * 512;          // 0..2047
            int nr = idx >> 3, kc = (idx & 7) << 3;
            const __half* src = B + (size_t)(col0 + nr) * ldb + k0 + kc;
            cp16(sB_u + (buf * STB_H + nr * SROWH + kc) * 2, src, col0 + nr < Nc);
        }
        asm volatile("cp.async.commit_group;" ::: "memory");
    };

    #pragma unroll
    for (int s = 0; s < NSTAGE - 1; s++) issue(s);

    for (int c = 0; c < nch; c++) {
        asm volatile("cp.async.wait_group %0;" :: "n"(NSTAGE - 2) : "memory");
        __syncthreads();
        if (c + NSTAGE - 1 < nch) issue(c + NSTAGE - 1);

        const int buf = c % NSTAGE;
        const uint32_t aOff = aBase + 2u * buf * STA_H;
        const uint32_t bOff = bBase + 2u * buf * STB_H;
        #pragma unroll
        for (int ks = 0; ks < BK; ks += 16) {
            uint32_t af[2][4], bf8[8][2];
            #pragma unroll
            for (int mi = 0; mi < 2; mi++)
                ldsm4(af[mi], aOff + 2u * (mi * 16 * SROWH + ks));
            #pragma unroll
            for (int p = 0; p < 4; p++) {
                uint32_t t4[4];
                ldsm4(t4, bOff + 2u * (p * 16 * SROWH + ks));
                bf8[2 * p    ][0] = t4[0]; bf8[2 * p    ][1] = t4[1];
                bf8[2 * p + 1][0] = t4[2]; bf8[2 * p + 1][1] = t4[3];
            }
            #pragma unroll
            for (int mi = 0; mi < 2; mi++)
                #pragma unroll
                for (int ni = 0; ni < 8; ni++)
                    mma16(acc[mi][ni], af[mi], bf8[ni]);
        }
    }

    // ---- epilogue ----
    #pragma unroll
    for (int mi = 0; mi < 2; mi++) {
        const int rA = row0 + wm0 + mi * 16 + grp;
        const int rB = rA + 8;
        #pragma unroll
        for (int ni = 0; ni < 8; ni++) {
            const int c = col0 + wn0 + ni * 8 + (qid << 1);
            float2 lo = make_float2(acc[mi][ni][0], acc[mi][ni][1]);
            float2 hi = make_float2(acc[mi][ni][2], acc[mi][ni][3]);
            if (EPI == 1) {
                float* Cx = (float*)Cv + (long long)bz * sC;
                __half* Q = (__half*)auxp + (long long)bz * sAux;
                lo.x = fmaxf(lo.x, 0.f); lo.y = fmaxf(lo.y, 0.f);
                hi.x = fmaxf(hi.x, 0.f); hi.y = fmaxf(hi.y, 0.f);
                *(float2*)(Cx + (size_t)rA * ldc + c) = lo;
                *(float2*)(Cx + (size_t)rB * ldc + c) = hi;
                float2 ca = rtab[(size_t)rA * (NN / 2) + (c >> 1)];
                float2 cb = rtab[(size_t)rB * (NN / 2) + (c >> 1)];
                *(uint32_t*)(Q + (size_t)rA * ldc + c) =
                    packh2(lo.x * ca.x - lo.y * ca.y, lo.y * ca.x + lo.x * ca.y);
                *(uint32_t*)(Q + (size_t)rB * ldc + c) =
                    packh2(hi.x * cb.x - hi.y * cb.y, hi.y * cb.x + hi.x * cb.y);
            } else { // EPI == 2
                __half* Cx = (__half*)Cv + (long long)bz * sC;
                const float* E = (const float*)auxp + (long long)bz * sAux;
                float2 ea = *(const float2*)(E + (size_t)rA * ldc + c);
                float2 eb = *(const float2*)(E + (size_t)rB * ldc + c);
                *(uint32_t*)(Cx + (size_t)rA * ldc + c) =
                    packh2(fmaxf(lo.x, 0.f) * ea.x, fmaxf(lo.y, 0.f) * ea.y);
                *(uint32_t*)(Cx + (size_t)rB * ldc + c) =
                    packh2(fmaxf(hi.x, 0.f) * eb.x, fmaxf(hi.y, 0.f) * eb.y);
            }
        }
    }
}

// ---------------------------------------------------------------------------
// scores reduce: g_sc(fp16) = tril_mask(p0 + p1), zero above diagonal
// ---------------------------------------------------------------------------
__global__ void reduce_sc_k()
{
    int idx = blockIdx.x * 256 + threadIdx.x;          // 8-col units
    int c  = (idx & (TT / 8 - 1)) << 3;
    int r  = (idx >> 7) & (TT - 1);
    int h  = idx >> 17;
    uint4 o;
    if (c + 7 < r) {
        size_t off = (size_t)(h * 2) * TT * TT + (size_t)r * TT + c;
        size_t off1 = off + (size_t)TT * TT;
        float4 a0 = *(const float4*)(g_scp + off);
        float4 a1 = *(const float4*)(g_scp + off + 4);
        float4 b0 = *(const float4*)(g_scp + off1);
        float4 b1 = *(const float4*)(g_scp + off1 + 4);
        o.x = packh2(a0.x + b0.x, a0.y + b0.y);
        o.y = packh2(a0.z + b0.z, a0.w + b0.w);
        o.z = packh2(a1.x + b1.x, a1.y + b1.y);
        o.w = packh2(a1.z + b1.z, a1.w + b1.w);
    } else if (c >= r) {
        o = make_uint4(0, 0, 0, 0);
    } else {
        size_t off = (size_t)(h * 2) * TT * TT + (size_t)r * TT + c;
        size_t off1 = off + (size_t)TT * TT;
        float v[8];
        #pragma unroll
        for (int j = 0; j < 8; j++)
            v[j] = (c + j < r) ? (g_scp[off + j] + g_scp[off1 + j]) : 0.f;
        o.x = packh2(v[0], v[1]); o.y = packh2(v[2], v[3]);
        o.z = packh2(v[4], v[5]); o.w = packh2(v[6], v[7]);
    }
    *(uint4*)(g_sc + (size_t)h * TT * TT + (size_t)r * TT + c) = o;
}

// ---------------------------------------------------------------------------
// Transpose + fp16 round: out[Nn][M] = half(in[M][Nn]^T); batched via z
// ---------------------------------------------------------------------------
__global__ void transpose_half_k(const float* __restrict__ in, __half* __restrict__ out,
                                 int M, int Nn, long long inS, long long outS)
{
    __shared__ float t[32][33];
    in  += (long long)blockIdx.z * inS;
    out += (long long)blockIdx.z * outS;
    int x = blockIdx.x * 32 + threadIdx.x;
    int y = blockIdx.y * 32 + threadIdx.y;
    #pragma unroll
    for (int i = 0; i < 32; i += 8)
        t[threadIdx.y + i][threadIdx.x] = in[(size_t)(y + i) * Nn + x];
    __syncthreads();
    int x2 = blockIdx.y * 32 + threadIdx.x;
    int y2 = blockIdx.x * 32 + threadIdx.y;
    #pragma unroll
    for (int i = 0; i < 32; i += 8)
        out[(size_t)(y2 + i) * M + x2] = h1(t[threadIdx.x][threadIdx.y + i]);
}

// ---------------------------------------------------------------------------
__device__ __forceinline__ float2 meanvar192(float v, float* s1, float* s2)
{
    __syncthreads();
    float a = v, b = v * v;
    #pragma unroll
    for (int o = 16; o > 0; o >>= 1) {
        a += __shfl_down_sync(0xffffffffu, a, o);
        b += __shfl_down_sync(0xffffffffu, b, o);
    }
    int lane = threadIdx.x & 31, w = threadIdx.x >> 5;
    if (lane == 0) { s1[w] = a; s2[w] = b; }
    __syncthreads();
    if (threadIdx.x == 0) {
        float sa = 0.f, sb = 0.f;
        #pragma unroll
        for (int i = 0; i < 6; i++) { sa += s1[i]; sb += s2[i]; }
        s1[0] = sa; s2[0] = sb;
    }
    __syncthreads();
    float m   = s1[0] * (1.0f / 192.0f);
    float var = s2[0] * (1.0f / 192.0f) - m * m;
    return make_float2(m, fmaxf(var, 0.f));
}

__global__ void embed_ln_k(const int* __restrict__ idx,
                           const float* __restrict__ emb,
                           const float* __restrict__ pos)
{
    int t = blockIdx.x, d = threadIdx.x;
    __shared__ float s1[8], s2[8];
    float v = emb[(size_t)idx[t] * DD + d] + pos[(size_t)t * DD + d];
    float2 mv = meanvar192(v, s1, s2);
    float r = (v - mv.x) * rsqrtf(mv.y + 1e-5f);
    g_x [(size_t)t * DD + d] = r;
    g_xr[(size_t)t * DD + d] = h1(r);
    g_xT[(size_t)d * TT + t] = h1(r);
}

__global__ void sincos_k()
{
    int i = blockIdx.x * blockDim.x + threadIdx.x;
    if (i >= TT * (NN / 2)) return;
    int t = i / (NN / 2);
    int p = i - t * (NN / 2);
    float f = exp2f(-(float)p * (1.0f / 96.0f)) * 0.15915494309189535f;
    float ph = fmodf((float)t * f, 1.0f) * 6.283185307179586f;
    float s, c;
    sincosf(ph, &s, &c);
    g_rt[i] = make_float2(c, s);
}

__global__ void ln_ykv_k()
{
    int r = blockIdx.x, d = threadIdx.x;     // r = h*TT + t
    __shared__ float s1[8], s2[8];
    int h = r >> 10, t = r & (TT - 1);
    float v = 0.f;
    #pragma unroll
    for (int kz = 0; kz < 4; kz++)
        v += g_part[(size_t)(h * 4 + kz) * TT * DD + (size_t)t * DD + d];
    float2 mv = meanvar192(v, s1, s2);
    g_ykv[(size_t)r * DD + d] = h1((v - mv.x) * rsqrtf(mv.y + 1e-5f));
}

__global__ void finalize_k()
{
    int t = blockIdx.x, d = threadIdx.x;
    __shared__ float s1[8], s2[8];
    float ym = 0.f;
    #pragma unroll
    for (int c = 0; c < KSPLIT; c++)
        ym += g_part[(size_t)c * TT * DD + (size_t)t * DD + d];
    float2 mv = meanvar192(ym, s1, s2);
    float l1 = (ym - mv.x) * rsqrtf(mv.y + 1e-5f);
    float xv = g_x[(size_t)t * DD + d] + l1;
    float2 mv2 = meanvar192(xv, s1, s2);
    float r = (xv - mv2.x) * rsqrtf(mv2.y + 1e-5f);
    g_x [(size_t)t * DD + d] = r;
    g_xr[(size_t)t * DD + d] = h1(r);
    g_xT[(size_t)d * TT + t] = h1(r);
}

// ---------------------------------------------------------------------------
extern "C" void kernel_launch(void* const* d_in, const int* in_sizes, int n_in,
                              void* d_out, int out_size)
{
    const int*   idx  = (const int*)  d_in[0];
    const float* decx = (const float*)d_in[1];
    const float* decy = (const float*)d_in[2];
    const float* enc  = (const float*)d_in[3];
    const float* emb  = (const float*)d_in[4];
    const float* pos  = (const float*)d_in[5];
    const float* lmh  = (const float*)d_in[6];
    float* out = (float*)d_out;

    __half *pxr, *pxT, *pqr, *psc, *pykv, *pwdxT, *pwdyT, *pencT, *plmhT;
    float *pxs, *pscp, *ppart;
    float2* prt;
    cudaGetSymbolAddress((void**)&pxr,   g_xr);
    cudaGetSymbolAddress((void**)&pxT,   g_xT);
    cudaGetSymbolAddress((void**)&pxs,   g_xs);
    cudaGetSymbolAddress((void**)&pqr,   g_qr);
    cudaGetSymbolAddress((void**)&psc,   g_sc);
    cudaGetSymbolAddress((void**)&pscp,  g_scp);
    cudaGetSymbolAddress((void**)&pykv,  g_ykv);
    cudaGetSymbolAddress((void**)&ppart, g_part);
    cudaGetSymbolAddress((void**)&prt,   g_rt);
    cudaGetSymbolAddress((void**)&pwdxT, g_wdxT);
    cudaGetSymbolAddress((void**)&pwdyT, g_wdyT);
    cudaGetSymbolAddress((void**)&pencT, g_encT);
    cudaGetSymbolAddress((void**)&plmhT, g_lmhT);

    const int SMEM1 = NSTAGE * 2 * ST1_H * 2;            // 110592 B
    const int SMEM2 = NSTAGE * (STA_H + STB_H) * 2;      // 165888 B
    cudaFuncSetAttribute(gemm_mma<0>,  cudaFuncAttributeMaxDynamicSharedMemorySize, SMEM1);
    cudaFuncSetAttribute(gemm_mma<1>,  cudaFuncAttributeMaxDynamicSharedMemorySize, SMEM1);
    cudaFuncSetAttribute(gemm_mma<2>,  cudaFuncAttributeMaxDynamicSharedMemorySize, SMEM1);
    cudaFuncSetAttribute(gemm_mma<3>,  cudaFuncAttributeMaxDynamicSharedMemorySize, SMEM1);
    cudaFuncSetAttribute(gemm_wide<1>, cudaFuncAttributeMaxDynamicSharedMemorySize, SMEM2);
    cudaFuncSetAttribute(gemm_wide<2>, cudaFuncAttributeMaxDynamicSharedMemorySize, SMEM2);

    dim3 tb(32, 8);
    transpose_half_k<<<dim3(NN/32, DD/32, NHH), tb>>>(decx, pwdxT, DD, NN,
                                                      (long long)DD*NN, (long long)NN*DD);
    transpose_half_k<<<dim3(NN/32, DD/32, NHH), tb>>>(decy, pwdyT, DD, NN,
                                                      (long long)DD*NN, (long long)NN*DD);
    transpose_half_k<<<dim3(DD/32, (NHH*NN)/32, 1), tb>>>(enc, pencT, NHH*NN, DD, 0, 0);
    transpose_half_k<<<dim3(VV/32, DD/32, 1), tb>>>(lmh, plmhT, DD, VV, 0, 0);

    sincos_k<<<(TT * (NN / 2) + 255) / 256, 256>>>();
    embed_ln_k<<<TT, 192>>>(idx, emb, pos);

    for (int l = 0; l < NLAYER; l++) {
        // x_sparse(fp32) = relu(x @ decx[h]);  qr(fp16) = rope(x_sparse)
        gemm_wide<1><<<dim3(NN / 256, TT / 128, NHH), 512, SMEM2>>>(
            pxr, pwdxT, pxs, pqr, prt, NN, DD, DD, DD, NN,
            0LL, (long long)NN * DD, (long long)TT * NN, (long long)TT * NN);

        // scores partials: lower-triangle tiles, K split in 2 (bz = h*2+ks)
        gemm_mma<3><<<dim3(36, 1, NHH * 2), 256, SMEM1>>>(
            pqr, pqr, pscp, TT, NN / 2, NN, NN, TT,
            (long long)TT * NN, 0LL, (long long)TT * TT);

        // g_sc(fp16) = tril_mask(p0+p1)
        reduce_sc_k<<<NHH * TT * TT / 8 / 256, 256>>>();

        // ykv partials(fp32) = scores @ x   (split-K=4; bz = h*4+kz)
        gemm_mma<2><<<dim3(2, TT / 128, NHH * 4), 256, SMEM1>>>(
            psc, pxT, ppart, DD, TT / 4, TT, TT, DD,
            (long long)TT * TT, 0LL, (long long)TT * DD);

        // ykv(fp16) = ln(sum partials)
        ln_ykv_k<<<NHH * TT, 192>>>();

        // xy(fp16) = relu(ykv @ decy[h]) * x_sparse(fp32)
        gemm_wide<2><<<dim3(NN / 256, TT / 128, NHH), 512, SMEM2>>>(
            pykv, pwdyT, pqr, pxs, nullptr, NN, DD, DD, DD, NN,
            (long long)TT * DD, (long long)NN * DD, (long long)TT * NN,
            (long long)TT * NN);

        // ymlp partials(fp32): xy @ enc^T, split-K = 16
        gemm_mma<1><<<dim3(2, TT / 128, KSPLIT), 256, SMEM1>>>(
            pqr, pencT, ppart, DD, KCH, NN, NHH * NN, DD,
            0LL, (long long)KCH, (long long)TT * DD);

        finalize_k<<<TT, 192>>>();
    }

    // logits(fp32) = x @ lm_head
    gemm_mma<0><<<dim3(2, TT / 128, 1), 256, SMEM1>>>(
        pxr, plmhT, out, VV, DD, DD, DD, VV,
        0LL, 0LL, 0LL);
}

// round 12
// speedup vs baseline: 7.4332x; 1.0005x over previous
#include <cuda_runtime.h>
#include <cuda_fp16.h>
#include <math.h>
#include <stdint.h>

// Problem constants
#define TT 1024
#define DD 192
#define NHH 4
#define NN 3072
#define VV 256
#define NLAYER 4
#define KSPLIT 16
#define KCH ((NHH*NN)/KSPLIT)   // 768
#define NSTAGE 3
#define BK 64
#define SROWH 72                 // halves per smem row (64 + 8 pad), K1
#define ST1_H (128*SROWH)
#define SROW2 200                // halves per smem row (192 + 8 pad), wide
#define WA_H (128*SROW2)
#define WB_H (256*SROW2)

// ---------------------------------------------------------------------------
// Static device scratch -- 16B aligned for cp.async
// ---------------------------------------------------------------------------
__device__ __align__(16) float   g_x[TT*DD];        // fp32 residual chain
__device__ __align__(16) __half  g_xr[TT*DD];       // fp16 copy (GEMM A)
__device__ __align__(16) __half  g_xT[DD*TT];       // fp16 x^T (GEMM B for ykv)
__device__ __align__(16) float   g_xs[NHH*TT*NN];   // fp32 (elementwise use only)
__device__ __align__(16) __half  g_qr[NHH*TT*NN];   // fp16 qr; reused as xy
__device__ __align__(16) __half  g_sc[NHH*TT*TT];   // fp16 masked scores (upper: static 0)
__device__ __align__(16) float   g_scp[2*NHH*TT*TT];// scores split-K partials
__device__ __align__(16) __half  g_ykv[NHH*TT*DD];  // fp16 after ln
__device__ __align__(16) float   g_part[KSPLIT*TT*DD];
__device__ __align__(16) float2  g_rt[TT*(NN/2)];
__device__ __align__(16) __half  g_wdxT[NHH*NN*DD];
__device__ __align__(16) __half  g_wdyT[NHH*NN*DD];
__device__ __align__(16) __half  g_encT[DD*NHH*NN];
__device__ __align__(16) __half  g_lmhT[VV*DD];

__device__ __forceinline__ uint32_t su32(const void* p) {
    uint32_t a;
    asm("{ .reg .u64 t; cvta.to.shared.u64 t, %1; cvt.u32.u64 %0, t; }"
        : "=r"(a) : "l"(p));
    return a;
}
__device__ __forceinline__ void cp16(uint32_t dst, const void* src, bool full) {
    int sz = full ? 16 : 0;
    asm volatile("cp.async.cg.shared.global [%0], [%1], 16, %2;"
                 :: "r"(dst), "l"(src), "r"(sz) : "memory");
}
__device__ __forceinline__ void mma16(float c[4], const uint32_t a[4], const uint32_t b[2]) {
    asm volatile(
        "mma.sync.aligned.m16n8k16.row.col.f32.f16.f16.f32 "
        "{%0,%1,%2,%3}, {%4,%5,%6,%7}, {%8,%9}, {%0,%1,%2,%3};"
        : "+f"(c[0]), "+f"(c[1]), "+f"(c[2]), "+f"(c[3])
        : "r"(a[0]), "r"(a[1]), "r"(a[2]), "r"(a[3]), "r"(b[0]), "r"(b[1]));
}
__device__ __forceinline__ void ldsm4(uint32_t d[4], uint32_t addr) {
    asm volatile("ldmatrix.sync.aligned.m8n8.x4.shared.b16 {%0,%1,%2,%3}, [%4];"
                 : "=r"(d[0]), "=r"(d[1]), "=r"(d[2]), "=r"(d[3]) : "r"(addr));
}
__device__ __forceinline__ uint32_t packh2(float a, float b) {
    __half2 h = __floats2half2_rn(a, b);
    return *(uint32_t*)&h;
}
__device__ __forceinline__ __half h1(float a) { return __float2half_rn(a); }

// ---------------------------------------------------------------------------
// Kernel 1: tile 128x128, 256 thr (8 warps 4m x 2n), fp16 in, fp32 out.
// C[M,Nc] = A[M,K] @ B[Nc,K]^T
// AZM: 0 normal | 1 ymlp split-K | 2 ykv tri-skip split-K | 3 scores tri + K-split2
// ---------------------------------------------------------------------------
template<int AZM>
__global__ __launch_bounds__(256, 2)
void gemm_mma(const __half* __restrict__ A, const __half* __restrict__ B,
              float* __restrict__ C,
              int Nc, int K, int lda, int ldb, int ldc,
              long long sA, long long sB, long long sC)
{
    extern __shared__ __half smh[];
    const uint32_t sA_u = su32(smh);
    const uint32_t sB_u = su32(smh + NSTAGE * ST1_H);

    const int bx = blockIdx.x, by = blockIdx.y, bz = blockIdx.z;
    const int tid = threadIdx.x;
    const int wid = tid >> 5, lane = tid & 31;
    const int grp = lane >> 2, qid = lane & 3;
    const int wm0 = (wid & 3) * 32, wn0 = (wid >> 2) * 64;

    int row0, col0 = bx * 128;
    int koff = 0;
    if (AZM == 3) {
        int bid = bx;
        int by3 = (int)((sqrtf(8.f * bid + 1.f) - 1.f) * 0.5f);
        while ((by3 + 1) * (by3 + 2) / 2 <= bid) by3++;
        while (by3 * (by3 + 1) / 2 > bid)       by3--;
        row0 = by3 * 128;
        col0 = (bid - by3 * (by3 + 1) / 2) * 128;
        long long hoff = (long long)(bz >> 1) * sA + (long long)(bz & 1) * K;
        A += hoff; B += hoff;
        C += (long long)bz * sC;
    } else if (AZM == 2) {
        // bz = h*20 + j; decode j -> (by2, kz) with kz <= by2/2
        int h = bz / 20, j = bz - h * 20;
        int by2 = 0, c0 = 0;
        #pragma unroll 8
        for (int q = 0; q < 8; q++) {
            int cnt = (by2 >> 1) + 1;
            if (j < c0 + cnt) break;
            c0 += cnt; by2++;
        }
        int kz = j - c0;
        row0 = by2 * 128;
        A += (long long)h * sA + kz * 256;
        B += kz * 256;
        C += (long long)(h * 4 + kz) * sC;
    } else if (AZM == 1) {
        row0 = by * 128;
        koff = bz * KCH;
        B += (long long)bz * sB;
        C += (long long)bz * sC;
    } else {
        row0 = by * 128;
        A += (long long)bz * sA;
        B += (long long)bz * sB;
        C += (long long)bz * sC;
    }

    const int rowA = (lane & 7) + ((lane >> 3) & 1) * 8;
    const int kA   = ((lane >> 4) & 1) * 8;
    const int rowB = (lane & 7) + ((lane >> 4) & 1) * 8;
    const int kB   = ((lane >> 3) & 1) * 8;
    const uint32_t aBase = sA_u + 2u * ((wm0 + rowA) * SROWH + kA);
    const uint32_t bBase = sB_u + 2u * ((wn0 + rowB) * SROWH + kB);

    float acc[2][8][4];
    #pragma unroll
    for (int mi = 0; mi < 2; mi++)
        #pragma unroll
        for (int ni = 0; ni < 8; ni++)
            #pragma unroll
            for (int j = 0; j < 4; j++) acc[mi][ni][j] = 0.f;

    const int nch = K / BK;

    auto issue = [&](int s) {
        const int k0 = s * BK;
        const int buf = s % NSTAGE;
        #pragma unroll
        for (int it = 0; it < 4; it++) {
            int idx = tid + it * 256;
            int r = idx >> 3, kc = (idx & 7) << 3;
            const __half* src;
            if (AZM == 1) {
                int gk = koff + k0 + kc;
                int hh = gk / NN, nn = gk - hh * NN;
                src = A + (size_t)hh * TT * NN + (size_t)(row0 + r) * lda + nn;
            } else {
                src = A + (size_t)(row0 + r) * lda + k0 + kc;
            }
            cp16(sA_u + (buf * ST1_H + r * SROWH + kc) * 2, src, true);
        }
        #pragma unroll
        for (int it = 0; it < 4; it++) {
            int idx = tid + it * 256;
            int nr = idx >> 3, kc = (idx & 7) << 3;
            const __half* src = B + (size_t)(col0 + nr) * ldb + k0 + kc;
            cp16(sB_u + (buf * ST1_H + nr * SROWH + kc) * 2, src, col0 + nr < Nc);
        }
        asm volatile("cp.async.commit_group;" ::: "memory");
    };

    #pragma unroll
    for (int s = 0; s < NSTAGE - 1; s++) issue(s);

    for (int c = 0; c < nch; c++) {
        asm volatile("cp.async.wait_group %0;" :: "n"(NSTAGE - 2) : "memory");
        __syncthreads();
        if (c + NSTAGE - 1 < nch) issue(c + NSTAGE - 1);

        const int buf = c % NSTAGE;
        const uint32_t aOff = aBase + 2u * buf * ST1_H;
        const uint32_t bOff = bBase + 2u * buf * ST1_H;
        #pragma unroll
        for (int ks = 0; ks < BK; ks += 16) {
            uint32_t af[2][4], bf8[8][2];
            #pragma unroll
            for (int mi = 0; mi < 2; mi++)
                ldsm4(af[mi], aOff + 2u * (mi * 16 * SROWH + ks));
            #pragma unroll
            for (int p = 0; p < 4; p++) {
                uint32_t t4[4];
                ldsm4(t4, bOff + 2u * (p * 16 * SROWH + ks));
                bf8[2 * p    ][0] = t4[0]; bf8[2 * p    ][1] = t4[1];
                bf8[2 * p + 1][0] = t4[2]; bf8[2 * p + 1][1] = t4[3];
            }
            #pragma unroll
            for (int mi = 0; mi < 2; mi++)
                #pragma unroll
                for (int ni = 0; ni < 8; ni++)
                    mma16(acc[mi][ni], af[mi], bf8[ni]);
        }
    }

    #pragma unroll
    for (int mi = 0; mi < 2; mi++) {
        const int rA = row0 + wm0 + mi * 16 + grp;
        const int rB = rA + 8;
        #pragma unroll
        for (int ni = 0; ni < 8; ni++) {
            const int c = col0 + wn0 + ni * 8 + (qid << 1);
            if (c >= Nc) continue;
            *(float2*)(C + (size_t)rA * ldc + c) = make_float2(acc[mi][ni][0], acc[mi][ni][1]);
            *(float2*)(C + (size_t)rB * ldc + c) = make_float2(acc[mi][ni][2], acc[mi][ni][3]);
        }
    }
}

// ---------------------------------------------------------------------------
// Kernel 2: wide single-shot GEMM. K=192 (fits entirely in smem).
// Tile 128x256, 512 thr (16 warps 4m x 4n). One load, one sync, no pipeline.
// EPI 1: C=xs fp32 = relu(acc); qr fp16 = rope(relu) -> auxp
// EPI 2: C=xy fp16 = relu(acc)*xs(fp32 auxp)
// ---------------------------------------------------------------------------
template<int EPI>
__global__ __launch_bounds__(512, 1)
void gemm_wide(const __half* __restrict__ A, const __half* __restrict__ B,
               void* __restrict__ Cv, void* __restrict__ auxp,
               const float2* __restrict__ rtab,
               long long sA, long long sB, long long sC, long long sAux)
{
    extern __shared__ __half smh[];
    const uint32_t sA_u = su32(smh);
    const uint32_t sB_u = su32(smh + WA_H);

    const int bx = blockIdx.x, by = blockIdx.y, bz = blockIdx.z;
    const int tid = threadIdx.x;
    const int wid = tid >> 5, lane = tid & 31;
    const int grp = lane >> 2, qid = lane & 3;
    const int wm0 = (wid & 3) * 32, wn0 = (wid >> 2) * 64;
    const int row0 = by * 128, col0 = bx * 256;

    A += (long long)bz * sA;
    B += (long long)bz * sB;

    // single-shot load of full-K operands
    #pragma unroll
    for (int it = 0; it < 6; it++) {
        int idx = tid + it * 512;              // 0..3071
        int r = idx / 24, kc = (idx % 24) << 3;
        cp16(sA_u + (r * SROW2 + kc) * 2,
             A + (size_t)(row0 + r) * DD + kc, true);
    }
    #pragma unroll
    for (int it = 0; it < 12; it++) {
        int idx = tid + it * 512;              // 0..6143
        int nr = idx / 24, kc = (idx % 24) << 3;
        cp16(sB_u + (nr * SROW2 + kc) * 2,
             B + (size_t)(col0 + nr) * DD + kc, true);
    }
    asm volatile("cp.async.commit_group;" ::: "memory");
    asm volatile("cp.async.wait_group 0;" ::: "memory");
    __syncthreads();

    const int rowA = (lane & 7) + ((lane >> 3) & 1) * 8;
    const int kA   = ((lane >> 4) & 1) * 8;
    const int rowB = (lane & 7) + ((lane >> 4) & 1) * 8;
    const int kB   = ((lane >> 3) & 1) * 8;
    const uint32_t aBase = sA_u + 2u * ((wm0 + rowA) * SROW2 + kA);
    const uint32_t bBase = sB_u + 2u * ((wn0 + rowB) * SROW2 + kB);

    float acc[2][8][4];
    #pragma unroll
    for (int mi = 0; mi < 2; mi++)
        #pragma unroll
        for (int ni = 0; ni < 8; ni++)
            #pragma unroll
            for (int j = 0; j < 4; j++) acc[mi][ni][j] = 0.f;

    #pragma unroll
    for (int ks = 0; ks < DD; ks += 16) {
        uint32_t af[2][4], bf8[8][2];
        #pragma unroll
        for (int mi = 0; mi < 2; mi++)
            ldsm4(af[mi], aBase + 2u * (mi * 16 * SROW2 + ks));
        #pragma unroll
        for (int p = 0; p < 4; p++) {
            uint32_t t4[4];
            ldsm4(t4, bBase + 2u * (p * 16 * SROW2 + ks));
            bf8[2 * p    ][0] = t4[0]; bf8[2 * p    ][1] = t4[1];
            bf8[2 * p + 1][0] = t4[2]; bf8[2 * p + 1][1] = t4[3];
        }
        #pragma unroll
        for (int mi = 0; mi < 2; mi++)
            #pragma unroll
            for (int ni = 0; ni < 8; ni++)
                mma16(acc[mi][ni], af[mi], bf8[ni]);
    }

    // ---- epilogue ----
    #pragma unroll
    for (int mi = 0; mi < 2; mi++) {
        const int rA = row0 + wm0 + mi * 16 + grp;
        const int rB = rA + 8;
        #pragma unroll
        for (int ni = 0; ni < 8; ni++) {
            const int c = col0 + wn0 + ni * 8 + (qid << 1);
            float2 lo = make_float2(acc[mi][ni][0], acc[mi][ni][1]);
            float2 hi = make_float2(acc[mi][ni][2], acc[mi][ni][3]);
            if (EPI == 1) {
                float* Cx = (float*)Cv + (long long)bz * sC;
                __half* Q = (__half*)auxp + (long long)bz * sAux;
                lo.x = fmaxf(lo.x, 0.f); lo.y = fmaxf(lo.y, 0.f);
                hi.x = fmaxf(hi.x, 0.f); hi.y = fmaxf(hi.y, 0.f);
                *(float2*)(Cx + (size_t)rA * NN + c) = lo;
                *(float2*)(Cx + (size_t)rB * NN + c) = hi;
                float2 ca = rtab[(size_t)rA * (NN / 2) + (c >> 1)];
                float2 cb = rtab[(size_t)rB * (NN / 2) + (c >> 1)];
                *(uint32_t*)(Q + (size_t)rA * NN + c) =
                    packh2(lo.x * ca.x - lo.y * ca.y, lo.y * ca.x + lo.x * ca.y);
                *(uint32_t*)(Q + (size_t)rB * NN + c) =
                    packh2(hi.x * cb.x - hi.y * cb.y, hi.y * cb.x + hi.x * cb.y);
            } else { // EPI == 2
                __half* Cx = (__half*)Cv + (long long)bz * sC;
                const float* E = (const float*)auxp + (long long)bz * sAux;
                float2 ea = *(const float2*)(E + (size_t)rA * NN + c);
                float2 eb = *(const float2*)(E + (size_t)rB * NN + c);
                *(uint32_t*)(Cx + (size_t)rA * NN + c) =
                    packh2(fmaxf(lo.x, 0.f) * ea.x, fmaxf(lo.y, 0.f) * ea.y);
                *(uint32_t*)(Cx + (size_t)rB * NN + c) =
                    packh2(fmaxf(hi.x, 0.f) * eb.x, fmaxf(hi.y, 0.f) * eb.y);
            }
        }
    }
}

// ---------------------------------------------------------------------------
// scores reduce: g_sc(fp16) = tril_mask(p0 + p1); upper triangle is statically
// zero (device globals zero-init, never written) -> early-out, half traffic.
// ---------------------------------------------------------------------------
__global__ void reduce_sc_k()
{
    int idx = blockIdx.x * 256 + threadIdx.x;          // 8-col units
    int c  = (idx & (TT / 8 - 1)) << 3;
    int r  = (idx >> 7) & (TT - 1);
    int h  = idx >> 17;
    if (c >= r) return;                                // upper: static zero
    uint4 o;
    size_t off  = (size_t)(h * 2) * TT * TT + (size_t)r * TT + c;
    size_t off1 = off + (size_t)TT * TT;
    if (c + 7 < r) {
        float4 a0 = *(const float4*)(g_scp + off);
        float4 a1 = *(const float4*)(g_scp + off + 4);
        float4 b0 = *(const float4*)(g_scp + off1);
        float4 b1 = *(const float4*)(g_scp + off1 + 4);
        o.x = packh2(a0.x + b0.x, a0.y + b0.y);
        o.y = packh2(a0.z + b0.z, a0.w + b0.w);
        o.z = packh2(a1.x + b1.x, a1.y + b1.y);
        o.w = packh2(a1.z + b1.z, a1.w + b1.w);
    } else {
        float v[8];
        #pragma unroll
        for (int j = 0; j < 8; j++)
            v[j] = (c + j < r) ? (g_scp[off + j] + g_scp[off1 + j]) : 0.f;
        o.x = packh2(v[0], v[1]); o.y = packh2(v[2], v[3]);
        o.z = packh2(v[4], v[5]); o.w = packh2(v[6], v[7]);
    }
    *(uint4*)(g_sc + (size_t)h * TT * TT + (size_t)r * TT + c) = o;
}

// ---------------------------------------------------------------------------
__global__ void transpose_half_k(const float* __restrict__ in, __half* __restrict__ out,
                                 int M, int Nn, long long inS, long long outS)
{
    __shared__ float t[32][33];
    in  += (long long)blockIdx.z * inS;
    out += (long long)blockIdx.z * outS;
    int x = blockIdx.x * 32 + threadIdx.x;
    int y = blockIdx.y * 32 + threadIdx.y;
    #pragma unroll
    for (int i = 0; i < 32; i += 8)
        t[threadIdx.y + i][threadIdx.x] = in[(size_t)(y + i) * Nn + x];
    __syncthreads();
    int x2 = blockIdx.y * 32 + threadIdx.x;
    int y2 = blockIdx.x * 32 + threadIdx.y;
    #pragma unroll
    for (int i = 0; i < 32; i += 8)
        out[(size_t)(y2 + i) * M + x2] = h1(t[threadIdx.x][threadIdx.y + i]);
}

// ---------------------------------------------------------------------------
__device__ __forceinline__ float2 meanvar192(float v, float* s1, float* s2)
{
    __syncthreads();
    float a = v, b = v * v;
    #pragma unroll
    for (int o = 16; o > 0; o >>= 1) {
        a += __shfl_down_sync(0xffffffffu, a, o);
        b += __shfl_down_sync(0xffffffffu, b, o);
    }
    int lane = threadIdx.x & 31, w = threadIdx.x >> 5;
    if (lane == 0) { s1[w] = a; s2[w] = b; }
    __syncthreads();
    if (threadIdx.x == 0) {
        float sa = 0.f, sb = 0.f;
        #pragma unroll
        for (int i = 0; i < 6; i++) { sa += s1[i]; sb += s2[i]; }
        s1[0] = sa; s2[0] = sb;
    }
    __syncthreads();
    float m   = s1[0] * (1.0f / 192.0f);
    float var = s2[0] * (1.0f / 192.0f) - m * m;
    return make_float2(m, fmaxf(var, 0.f));
}

__global__ void embed_ln_k(const int* __restrict__ idx,
                           const float* __restrict__ emb,
                           const float* __restrict__ pos)
{
    int t = blockIdx.x, d = threadIdx.x;
    __shared__ float s1[8], s2[8];
    float v = emb[(size_t)idx[t] * DD + d] + pos[(size_t)t * DD + d];
    float2 mv = meanvar192(v, s1, s2);
    float r = (v - mv.x) * rsqrtf(mv.y + 1e-5f);
    g_x [(size_t)t * DD + d] = r;
    g_xr[(size_t)t * DD + d] = h1(r);
    g_xT[(size_t)d * TT + t] = h1(r);
}

__global__ void sincos_k()
{
    int i = blockIdx.x * blockDim.x + threadIdx.x;
    if (i >= TT * (NN / 2)) return;
    int t = i / (NN / 2);
    int p = i - t * (NN / 2);
    float f = exp2f(-(float)p * (1.0f / 96.0f)) * 0.15915494309189535f;
    float ph = fmodf((float)t * f, 1.0f) * 6.283185307179586f;
    float s, c;
    sincosf(ph, &s, &c);
    g_rt[i] = make_float2(c, s);
}

// ykv: reduce valid split-K partials only (kz <= t>>8), then LN -> fp16
__global__ void ln_ykv_k()
{
    int r = blockIdx.x, d = threadIdx.x;     // r = h*TT + t
    __shared__ float s1[8], s2[8];
    int h = r >> 10, t = r & (TT - 1);
    int kcnt = (t >> 8) + 1;
    float v = 0.f;
    for (int kz = 0; kz < kcnt; kz++)
        v += g_part[(size_t)(h * 4 + kz) * TT * DD + (size_t)t * DD + d];
    float2 mv = meanvar192(v, s1, s2);
    g_ykv[(size_t)r * DD + d] = h1((v - mv.x) * rsqrtf(mv.y + 1e-5f));
}

__global__ void finalize_k()
{
    int t = blockIdx.x, d = threadIdx.x;
    __shared__ float s1[8], s2[8];
    float ym = 0.f;
    #pragma unroll
    for (int c = 0; c < KSPLIT; c++)
        ym += g_part[(size_t)c * TT * DD + (size_t)t * DD + d];
    float2 mv = meanvar192(ym, s1, s2);
    float l1 = (ym - mv.x) * rsqrtf(mv.y + 1e-5f);
    float xv = g_x[(size_t)t * DD + d] + l1;
    float2 mv2 = meanvar192(xv, s1, s2);
    float r = (xv - mv2.x) * rsqrtf(mv2.y + 1e-5f);
    g_x [(size_t)t * DD + d] = r;
    g_xr[(size_t)t * DD + d] = h1(r);
    g_xT[(size_t)d * TT + t] = h1(r);
}

// ---------------------------------------------------------------------------
extern "C" void kernel_launch(void* const* d_in, const int* in_sizes, int n_in,
                              void* d_out, int out_size)
{
    const int*   idx  = (const int*)  d_in[0];
    const float* decx = (const float*)d_in[1];
    const float* decy = (const float*)d_in[2];
    const float* enc  = (const float*)d_in[3];
    const float* emb  = (const float*)d_in[4];
    const float* pos  = (const float*)d_in[5];
    const float* lmh  = (const float*)d_in[6];
    float* out = (float*)d_out;

    __half *pxr, *pxT, *pqr, *psc, *pykv, *pwdxT, *pwdyT, *pencT, *plmhT;
    float *pxs, *pscp, *ppart;
    float2* prt;
    cudaGetSymbolAddress((void**)&pxr,   g_xr);
    cudaGetSymbolAddress((void**)&pxT,   g_xT);
    cudaGetSymbolAddress((void**)&pxs,   g_xs);
    cudaGetSymbolAddress((void**)&pqr,   g_qr);
    cudaGetSymbolAddress((void**)&psc,   g_sc);
    cudaGetSymbolAddress((void**)&pscp,  g_scp);
    cudaGetSymbolAddress((void**)&pykv,  g_ykv);
    cudaGetSymbolAddress((void**)&ppart, g_part);
    cudaGetSymbolAddress((void**)&prt,   g_rt);
    cudaGetSymbolAddress((void**)&pwdxT, g_wdxT);
    cudaGetSymbolAddress((void**)&pwdyT, g_wdyT);
    cudaGetSymbolAddress((void**)&pencT, g_encT);
    cudaGetSymbolAddress((void**)&plmhT, g_lmhT);

    const int SMEM1 = NSTAGE * 2 * ST1_H * 2;            // 110592 B
    const int SMEMW = (WA_H + WB_H) * 2;                 // 153600 B
    cudaFuncSetAttribute(gemm_mma<0>,  cudaFuncAttributeMaxDynamicSharedMemorySize, SMEM1);
    cudaFuncSetAttribute(gemm_mma<1>,  cudaFuncAttributeMaxDynamicSharedMemorySize, SMEM1);
    cudaFuncSetAttribute(gemm_mma<2>,  cudaFuncAttributeMaxDynamicSharedMemorySize, SMEM1);
    cudaFuncSetAttribute(gemm_mma<3>,  cudaFuncAttributeMaxDynamicSharedMemorySize, SMEM1);
    cudaFuncSetAttribute(gemm_wide<1>, cudaFuncAttributeMaxDynamicSharedMemorySize, SMEMW);
    cudaFuncSetAttribute(gemm_wide<2>, cudaFuncAttributeMaxDynamicSharedMemorySize, SMEMW);

    dim3 tb(32, 8);
    transpose_half_k<<<dim3(NN/32, DD/32, NHH), tb>>>(decx, pwdxT, DD, NN,
                                                      (long long)DD*NN, (long long)NN*DD);
    transpose_half_k<<<dim3(NN/32, DD/32, NHH), tb>>>(decy, pwdyT, DD, NN,
                                                      (long long)DD*NN, (long long)NN*DD);
    transpose_half_k<<<dim3(DD/32, (NHH*NN)/32, 1), tb>>>(enc, pencT, NHH*NN, DD, 0, 0);
    transpose_half_k<<<dim3(VV/32, DD/32, 1), tb>>>(lmh, plmhT, DD, VV, 0, 0);

    sincos_k<<<(TT * (NN / 2) + 255) / 256, 256>>>();
    embed_ln_k<<<TT, 192>>>(idx, emb, pos);

    for (int l = 0; l < NLAYER; l++) {
        // x_sparse(fp32) = relu(x @ decx[h]);  qr(fp16) = rope(x_sparse)
        gemm_wide<1><<<dim3(NN / 256, TT / 128, NHH), 512, SMEMW>>>(
            pxr, pwdxT, pxs, pqr, prt,
            0LL, (long long)NN * DD, (long long)TT * NN, (long long)TT * NN);

        // scores partials: lower-triangle tiles, K split in 2 (bz = h*2+ks)
        gemm_mma<3><<<dim3(36, 1, NHH * 2), 256, SMEM1>>>(
            pqr, pqr, pscp, TT, NN / 2, NN, NN, TT,
            (long long)TT * NN, 0LL, (long long)TT * TT);

        // g_sc(fp16) = tril_mask(p0+p1) [lower triangle only]
        reduce_sc_k<<<NHH * TT * TT / 8 / 256, 256>>>();

        // ykv partials(fp32) = scores @ x   (tri-skip split-K; bz = h*20+j)
        gemm_mma<2><<<dim3(2, 1, NHH * 20), 256, SMEM1>>>(
            psc, pxT, ppart, DD, 256, TT, TT, DD,
            (long long)TT * TT, 0LL, (long long)TT * DD);

        // ykv(fp16) = ln(sum valid partials)
        ln_ykv_k<<<NHH * TT, 192>>>();

        // xy(fp16) = relu(ykv @ decy[h]) * x_sparse(fp32)
        gemm_wide<2><<<dim3(NN / 256, TT / 128, NHH), 512, SMEMW>>>(
            pykv, pwdyT, pqr, pxs, nullptr,
            (long long)TT * DD, (long long)NN * DD, (long long)TT * NN,
            (long long)TT * NN);

        // ymlp partials(fp32): xy @ enc^T, split-K = 16
        gemm_mma<1><<<dim3(2, TT / 128, KSPLIT), 256, SMEM1>>>(
            pqr, pencT, ppart, DD, KCH, NN, NHH * NN, DD,
            0LL, (long long)KCH, (long long)TT * DD);

        finalize_k<<<TT, 192>>>();
    }

    // logits(fp32) = x @ lm_head
    gemm_mma<0><<<dim3(2, TT / 128, 1), 256, SMEM1>>>(
        pxr, plmhT, out, VV, DD, DD, DD, VV,
        0LL, 0LL, 0LL);
}